// round 8
// baseline (speedup 1.0000x reference)
#include <cuda_runtime.h>
#include <cuda_bf16.h>
#include <math.h>
#include <stdint.h>

// Problem constants: B=64, N=1024, C=768, heads=8, d=128
#define B_ 64
#define N_ 1024
#define C_ 768
#define H_ 8
#define D_ 128
#define EPSF 1e-8f
#define ROWS_ ((size_t)B_*C_)   // 49152

// ---------------------------------------------------------------------------
// Scratch (device globals — allocation-free rule)
// ---------------------------------------------------------------------------
__device__ __nv_bfloat16 g_xh[ROWS_*N_];   // xt hi, later gelu hi (in-place)
__device__ __nv_bfloat16 g_xl[ROWS_*N_];   // xt lo, later gelu lo
__device__ __nv_bfloat16 g_kTh[(size_t)B_*N_*C_];  // kT [b][n][c] hi
__device__ __nv_bfloat16 g_kTl[(size_t)B_*N_*C_];
__device__ __nv_bfloat16 g_vTh[(size_t)B_*N_*C_];
__device__ __nv_bfloat16 g_vTl[(size_t)B_*N_*C_];
__device__ __nv_bfloat16 g_kth[(size_t)B_*H_*D_*D_];  // ktT [bh][m][n] hi
__device__ __nv_bfloat16 g_ktl[(size_t)B_*H_*D_*D_];
__device__ __nv_bfloat16 g_wh[3][(size_t)N_*N_];
__device__ __nv_bfloat16 g_wl[3][(size_t)N_*N_];
__device__ float g_part[3072];
__device__ float g_norm2;

// ---------------------------------------------------------------------------
// Helpers
// ---------------------------------------------------------------------------
__device__ __forceinline__ uint32_t smem_u32(const void* p){
  uint32_t a;
  asm("{ .reg .u64 t; cvta.to.shared.u64 t, %1; cvt.u32.u64 %0, t; }" : "=r"(a) : "l"(p));
  return a;
}
// bf16 hi/lo split of two floats -> packed bf16x2 regs (mem order [x,y])
__device__ __forceinline__ void split2(float fx, float fy, uint32_t& hi, uint32_t& lo){
  uint32_t h;
  asm("cvt.rn.bf16x2.f32 %0, %1, %2;" : "=r"(h) : "f"(fy), "f"(fx));
  float hx = __uint_as_float(h << 16);
  float hy = __uint_as_float(h & 0xffff0000u);
  float lx = fx - hx, ly = fy - hy;
  asm("cvt.rn.bf16x2.f32 %0, %1, %2;" : "=r"(lo) : "f"(ly), "f"(lx));
  hi = h;
}
__device__ __forceinline__ float gelu_exact(float x){
  return 0.5f * x * (1.0f + erff(x * 0.7071067811865475f));
}

#define CP_ASYNC16(s, g) \
  asm volatile("cp.async.cg.shared.global [%0], [%1], 16;" :: "r"(s), "l"(g) : "memory")
#define CP_COMMIT() asm volatile("cp.async.commit_group;" ::: "memory")
#define CP_WAIT1()  asm volatile("cp.async.wait_group 1;" ::: "memory")
#define CP_WAIT0()  asm volatile("cp.async.wait_group 0;" ::: "memory")

__device__ __forceinline__ void ldmx4(uint32_t* r, uint32_t addr){
  asm volatile("ldmatrix.sync.aligned.m8n8.x4.shared.b16 {%0,%1,%2,%3}, [%4];"
    : "=r"(r[0]), "=r"(r[1]), "=r"(r[2]), "=r"(r[3]) : "r"(addr));
}
__device__ __forceinline__ void mma16816(float* c, const uint32_t* a, const uint32_t* b){
  asm volatile("mma.sync.aligned.m16n8k16.row.col.f32.bf16.bf16.f32 "
    "{%0,%1,%2,%3},{%4,%5,%6,%7},{%8,%9},{%0,%1,%2,%3};"
    : "+f"(c[0]), "+f"(c[1]), "+f"(c[2]), "+f"(c[3])
    : "r"(a[0]), "r"(a[1]), "r"(a[2]), "r"(a[3]), "r"(b[0]), "r"(b[1]));
}

// ===========================================================================
// k_split: fp32 -> bf16 hi/lo (weights only, 2MB each)
// ===========================================================================
__global__ void k_split(const float4* __restrict__ in, uint2* __restrict__ hi,
                        uint2* __restrict__ lo, int n4){
  int i = blockIdx.x * blockDim.x + threadIdx.x;
  if (i >= n4) return;
  float4 v = in[i];
  uint32_t h0,l0,h1,l1;
  split2(v.x, v.y, h0, l0);
  split2(v.z, v.w, h1, l1);
  hi[i] = make_uint2(h0, h1);
  lo[i] = make_uint2(l0, l1);
}

// ===========================================================================
// Shared HMMA mainloop: C128x128 += A @ B^T over nch*32 K, 3-term bf16 split.
// Term-major MMA issue: 16-instruction reuse distance per accumulator.
// ===========================================================================
#define KC 32
#define RSB 80
#define TILE_SB (128*RSB)           // 10240 B
#define STAGE_B (4*TILE_SB)         // Ah,Al,Bh,Bl
#define GSMEM (3*STAGE_B)           // 122880 B

__device__ __forceinline__ void gemm_main(
    uint32_t sb, int tid,
    const __nv_bfloat16* __restrict__ Ah, const __nv_bfloat16* __restrict__ Al, int lda,
    const __nv_bfloat16* __restrict__ Bh, const __nv_bfloat16* __restrict__ Bl, int ldb,
    int nch, float (*acc)[4]){
  const int t64  = tid & 63;
  const int tile = tid >> 6;                 // 0:Ah 1:Al 2:Bh 3:Bl
  const __nv_bfloat16* gsrc; int ld;
  if      (tile == 0){ gsrc = Ah; ld = lda; }
  else if (tile == 1){ gsrc = Al; ld = lda; }
  else if (tile == 2){ gsrc = Bh; ld = ldb; }
  else               { gsrc = Bl; ld = ldb; }

  auto issue = [&](int ch, int stage){
    const int k0 = ch * KC;
    const uint32_t sbase = sb + stage * STAGE_B + tile * TILE_SB;
#pragma unroll
    for (int j = 0; j < 8; j++){
      const int seg = t64 + 64 * j;
      const int row = seg >> 2, s4 = seg & 3;
      CP_ASYNC16(sbase + row * RSB + s4 * 16,
                 (const char*)(gsrc + (size_t)row * ld + k0) + s4 * 16);
    }
    CP_COMMIT();
  };

  issue(0, 0);
  issue(1, 1);

  const int wid = tid >> 5, lane = tid & 31;
  const int wm = (wid >> 2) * 64, wn = (wid & 3) * 32;
  const int a_row = lane % 16, a_k8 = (lane >> 4) * 8;
  const int b_row = (lane & 7) + ((lane >> 4) * 8);
  const int b_k8  = ((lane >> 3) & 1) * 8;

  for (int ch = 0; ch < nch; ch++){
    CP_WAIT1();
    __syncthreads();
    if (ch + 2 < nch) issue(ch + 2, (ch + 2) % 3);
    else CP_COMMIT();   // keep group count uniform for CP_WAIT1

    const uint32_t st = sb + (ch % 3) * STAGE_B;
    const uint32_t aH = st,             aL = st + TILE_SB;
    const uint32_t bH = st + 2*TILE_SB, bL = st + 3*TILE_SB;

#pragma unroll
    for (int kk = 0; kk < 2; kk++){
      uint32_t ah[4][4], al[4][4], bh[4][2], bl[4][2];
      const int kc = kk * 32 + a_k8 * 2;
#pragma unroll
      for (int mi = 0; mi < 4; mi++){
        const uint32_t ro = (uint32_t)(wm + mi*16 + a_row) * RSB + kc;
        ldmx4(ah[mi], aH + ro);
        ldmx4(al[mi], aL + ro);
      }
#pragma unroll
      for (int nh = 0; nh < 2; nh++){
        const uint32_t ro = (uint32_t)(wn + nh*16 + b_row) * RSB + kk*32 + b_k8*2;
        uint32_t r[4];
        ldmx4(r, bH + ro);
        bh[nh*2+0][0]=r[0]; bh[nh*2+0][1]=r[1]; bh[nh*2+1][0]=r[2]; bh[nh*2+1][1]=r[3];
        ldmx4(r, bL + ro);
        bl[nh*2+0][0]=r[0]; bl[nh*2+0][1]=r[1]; bl[nh*2+1][0]=r[2]; bl[nh*2+1][1]=r[3];
      }
      // Term-major: accumulator reuse distance = 16 MMAs (no RAW stalls)
#pragma unroll
      for (int mi = 0; mi < 4; mi++)
#pragma unroll
        for (int ni = 0; ni < 4; ni++)
          mma16816(acc[4*mi+ni], ah[mi], bh[ni]);
#pragma unroll
      for (int mi = 0; mi < 4; mi++)
#pragma unroll
        for (int ni = 0; ni < 4; ni++)
          mma16816(acc[4*mi+ni], ah[mi], bl[ni]);
#pragma unroll
      for (int mi = 0; mi < 4; mi++)
#pragma unroll
        for (int ni = 0; ni < 4; ni++)
          mma16816(acc[4*mi+ni], al[mi], bh[ni]);
    }
  }
  CP_WAIT0();
  __syncthreads();   // stages free for epilogue reuse
}

// Transposed bf16 hi/lo epilogue via fp32 smem bounce.
#define TS 130
__device__ __forceinline__ void epi_T_bf16(
    float (*acc)[4], char* smem, int tid, float f,
    __nv_bfloat16* dsth, __nv_bfloat16* dstl, int ldd){
  float* T = (float*)smem;
  const int wid = tid >> 5, lane = tid & 31;
  const int wm = (wid >> 2) * 64, wn = (wid & 3) * 32;
  const int tr = lane >> 2, tc = (lane & 3) * 2;
#pragma unroll
  for (int mi = 0; mi < 4; mi++)
#pragma unroll
    for (int ni = 0; ni < 4; ni++){
      float* a = acc[4*mi+ni];
      const int r = wm + mi*16 + tr, c = wn + ni*8 + tc;
      T[r*TS + c]     = a[0]*f; T[r*TS + c + 1]     = a[1]*f;
      T[(r+8)*TS + c] = a[2]*f; T[(r+8)*TS + c + 1] = a[3]*f;
    }
  __syncthreads();
#pragma unroll
  for (int it = 0; it < 4; it++){
    const int j = it*32 + (tid >> 3);
    const int mbase = (tid & 7) * 2;
#pragma unroll
    for (int p = 0; p < 8; p++){
      const int m = mbase + p*16;
      float f0 = T[m*TS + j], f1 = T[(m+1)*TS + j];
      uint32_t h, l; split2(f0, f1, h, l);
      *(uint32_t*)(dsth + (size_t)j*ldd + m) = h;
      *(uint32_t*)(dstl + (size_t)j*ldd + m) = l;
    }
  }
  __syncthreads();
}

// ===========================================================================
// kv GEMM: C = xt @ W^T -> write transposed bf16 hi/lo (+ norm partials)
// ===========================================================================
__global__ void __launch_bounds__(256,1)
k_gemm_kv(const __nv_bfloat16* __restrict__ Wh, const __nv_bfloat16* __restrict__ Wl,
          __nv_bfloat16* __restrict__ dsth, __nv_bfloat16* __restrict__ dstl,
          int with_norm){
  extern __shared__ __align__(128) char smem[];
  __shared__ float red[8];
  const uint32_t sb = smem_u32(smem);
  const int tid = threadIdx.x;
  const int n0 = blockIdx.x * 128, m0 = blockIdx.y * 128;
  float acc[16][4] = {};
  gemm_main(sb, tid, g_xh + (size_t)m0*N_, g_xl + (size_t)m0*N_, N_,
            Wh + (size_t)n0*N_, Wl + (size_t)n0*N_, N_, 32, acc);
  if (with_norm){
    float s2 = 0.f;
#pragma unroll
    for (int q = 0; q < 16; q++)
#pragma unroll
      for (int e = 0; e < 4; e++) s2 += acc[q][e]*acc[q][e];
#pragma unroll
    for (int o = 16; o; o >>= 1) s2 += __shfl_down_sync(0xffffffffu, s2, o);
    if ((tid & 31) == 0) red[tid >> 5] = s2;
    __syncthreads();
    if (tid == 0){
      float t = 0.f;
#pragma unroll
      for (int w = 0; w < 8; w++) t += red[w];
      g_part[blockIdx.y * 8 + blockIdx.x] = t;
    }
  }
  const int b = m0 / C_, c0 = m0 % C_;
  const size_t off = ((size_t)b*N_ + n0) * C_ + c0;
  epi_T_bf16(acc, smem, tid, 1.f, dsth + off, dstl + off, C_);
}

__global__ void k_reduce(){
  __shared__ float sh[1024];
  const int t = threadIdx.x;
  sh[t] = g_part[t] + g_part[t+1024] + g_part[t+2048];
  __syncthreads();
  for (int o = 512; o; o >>= 1){
    if (t < o) sh[t] += sh[t+o];
    __syncthreads();
  }
  if (t == 0) g_norm2 = sh[0];
}

// ===========================================================================
// kt GEMM: kt[n][m] = sum_c kT[n][c] * vT[m][c]; scaled; store ktT[m][n].
// ===========================================================================
__global__ void __launch_bounds__(256,1)
k_gemm_kt(const float* __restrict__ scale){
  extern __shared__ __align__(128) char smem[];
  const uint32_t sb = smem_u32(smem);
  const int tid = threadIdx.x;
  const int bh = blockIdx.x, b = bh >> 3, h = bh & 7;
  const size_t base = ((size_t)b*N_ + h*D_) * C_;
  float acc[16][4] = {};
  gemm_main(sb, tid, g_kTh + base, g_kTl + base, C_,
            g_vTh + base, g_vTl + base, C_, 24, acc);
  const float nrm = sqrtf(g_norm2) + EPSF;
  const float f = scale[h] / (nrm*nrm);
  epi_T_bf16(acc, smem, tid, f,
             g_kth + (size_t)bh*D_*D_, g_ktl + (size_t)bh*D_*D_, D_);
}

// ===========================================================================
// out GEMM: out1 = q @ kt (K=128) -> exact gelu -> bf16 hi/lo in-place xh/xl
// ===========================================================================
__global__ void __launch_bounds__(256,1)
k_gemm_out(){
  extern __shared__ __align__(128) char smem[];
  const uint32_t sb = smem_u32(smem);
  const int tid = threadIdx.x;
  const int c0 = blockIdx.x * 128;
  const int bh = blockIdx.y, b = bh >> 3, h = bh & 7;
  const size_t Abase = ((size_t)b*C_ + c0) * N_ + (size_t)h*D_;
  float acc[16][4] = {};
  gemm_main(sb, tid, g_xh + Abase, g_xl + Abase, N_,
            g_kth + (size_t)bh*D_*D_, g_ktl + (size_t)bh*D_*D_, D_, 4, acc);
  const int wid = tid >> 5, lane = tid & 31;
  const int wm = (wid >> 2) * 64, wn = (wid & 3) * 32;
  const int tr = lane >> 2, tc = (lane & 3) * 2;
#pragma unroll
  for (int mi = 0; mi < 4; mi++)
#pragma unroll
    for (int ni = 0; ni < 4; ni++){
      float* a = acc[4*mi+ni];
      const int col = wn + ni*8 + tc;
      const size_t r0 = Abase + (size_t)(wm + mi*16 + tr) * N_ + col;
      const size_t r1 = r0 + 8*N_;
      uint32_t h0, l0;
      split2(gelu_exact(a[0]), gelu_exact(a[1]), h0, l0);
      *(uint32_t*)(g_xh + r0) = h0;
      *(uint32_t*)(g_xl + r0) = l0;
      split2(gelu_exact(a[2]), gelu_exact(a[3]), h0, l0);
      *(uint32_t*)(g_xh + r1) = h0;
      *(uint32_t*)(g_xl + r1) = l0;
    }
}

// ===========================================================================
// proj GEMM: out2 = gelu @ proj_w^T + pb; transposed fp32 write -> d_out [B,N,C]
// ===========================================================================
__global__ void __launch_bounds__(256,1)
k_gemm_proj(const __nv_bfloat16* __restrict__ Wh, const __nv_bfloat16* __restrict__ Wl,
            const float* __restrict__ pb, float* __restrict__ out){
  extern __shared__ __align__(128) char smem[];
  const uint32_t sb = smem_u32(smem);
  const int tid = threadIdx.x;
  const int n0 = blockIdx.x * 128, m0 = blockIdx.y * 128;
  float acc[16][4] = {};
  gemm_main(sb, tid, g_xh + (size_t)m0*N_, g_xl + (size_t)m0*N_, N_,
            Wh + (size_t)n0*N_, Wl + (size_t)n0*N_, N_, 32, acc);
  const int wid = tid >> 5, lane = tid & 31;
  const int wm = (wid >> 2) * 64, wn = (wid & 3) * 32;
  const int tr = lane >> 2, tc = (lane & 3) * 2;
  float* T = (float*)smem;
#pragma unroll
  for (int mi = 0; mi < 4; mi++)
#pragma unroll
    for (int ni = 0; ni < 4; ni++){
      float* a = acc[4*mi+ni];
      const int c = wn + ni*8 + tc;
      const float2 bv = *(const float2*)(pb + n0 + c);
      const int r = wm + mi*16 + tr;
      T[r*TS + c]     = a[0] + bv.x; T[r*TS + c + 1]     = a[1] + bv.y;
      T[(r+8)*TS + c] = a[2] + bv.x; T[(r+8)*TS + c + 1] = a[3] + bv.y;
    }
  __syncthreads();
  const int b = m0 / C_, c0 = m0 % C_;
  float* dst = out + ((size_t)b*N_ + n0) * C_ + c0;
#pragma unroll
  for (int it = 0; it < 4; it++){
    const int j = it*32 + (tid >> 3);
    const int mbase = (tid & 7) * 2;
#pragma unroll
    for (int p = 0; p < 8; p++){
      const int m = mbase + p*16;
      *(float2*)(dst + (size_t)j*C_ + m) = make_float2(T[m*TS + j], T[(m+1)*TS + j]);
    }
  }
}

// ===========================================================================
// x transpose fused with bf16 hi/lo split
// ===========================================================================
__global__ void k_transpose_x(const float* __restrict__ in){
  __shared__ float t[32][33];
  const size_t zo = (size_t)blockIdx.z * C_ * N_;
  const int i0 = blockIdx.y*32, j0 = blockIdx.x*32;
  const float* ip = in + zo;
#pragma unroll
  for (int k = threadIdx.y; k < 32; k += 8)
    t[k][threadIdx.x] = ip[(size_t)(i0+k)*C_ + j0 + threadIdx.x];
  __syncthreads();
#pragma unroll
  for (int k = threadIdx.y; k < 32; k += 8){
    const size_t o = zo + (size_t)(j0+k)*N_ + i0 + threadIdx.x;
    const float v = t[threadIdx.x][k];
    uint32_t h;
    asm("cvt.rn.bf16x2.f32 %0, %1, %1;" : "=r"(h) : "f"(v));
    const float hv = __uint_as_float(h << 16);
    g_xh[o] = __ushort_as_bfloat16((unsigned short)(h & 0xffffu));
    float lv = v - hv;
    uint32_t l;
    asm("cvt.rn.bf16x2.f32 %0, %1, %1;" : "=r"(l) : "f"(lv));
    g_xl[o] = __ushort_as_bfloat16((unsigned short)(l & 0xffffu));
  }
}

// ---------------------------------------------------------------------------
// Launch: graph-capturable, allocation-free, deterministic.
// ---------------------------------------------------------------------------
extern "C" void kernel_launch(void* const* d_in, const int* in_sizes, int n_in,
                              void* d_out, int out_size){
  const float* x   = (const float*)d_in[0];
  const float* qkw = (const float*)d_in[1];
  const float* vw  = (const float*)d_in[2];
  const float* pw  = (const float*)d_in[3];
  const float* pb  = (const float*)d_in[4];
  const float* sc  = (const float*)d_in[5];
  float* out = (float*)d_out;

  __nv_bfloat16 *p_wh=nullptr, *p_wl=nullptr, *p_kTh=nullptr, *p_kTl=nullptr,
                *p_vTh=nullptr, *p_vTl=nullptr;
  cudaGetSymbolAddress((void**)&p_wh,  g_wh);
  cudaGetSymbolAddress((void**)&p_wl,  g_wl);
  cudaGetSymbolAddress((void**)&p_kTh, g_kTh);
  cudaGetSymbolAddress((void**)&p_kTl, g_kTl);
  cudaGetSymbolAddress((void**)&p_vTh, g_vTh);
  cudaGetSymbolAddress((void**)&p_vTl, g_vTl);

  cudaFuncSetAttribute(k_gemm_kv,  cudaFuncAttributeMaxDynamicSharedMemorySize, GSMEM);
  cudaFuncSetAttribute(k_gemm_kt,  cudaFuncAttributeMaxDynamicSharedMemorySize, GSMEM);
  cudaFuncSetAttribute(k_gemm_out, cudaFuncAttributeMaxDynamicSharedMemorySize, GSMEM);
  cudaFuncSetAttribute(k_gemm_proj,cudaFuncAttributeMaxDynamicSharedMemorySize, GSMEM);

  const size_t W2 = (size_t)N_*N_;

  // x -> xt bf16 hi/lo; weight splits
  k_transpose_x<<<dim3(24,32,64), dim3(32,8)>>>(x);
  k_split<<<1024, 256>>>((const float4*)qkw, (uint2*)(p_wh),      (uint2*)(p_wl),      (int)(W2/4));
  k_split<<<1024, 256>>>((const float4*)vw,  (uint2*)(p_wh+W2),   (uint2*)(p_wl+W2),   (int)(W2/4));
  k_split<<<1024, 256>>>((const float4*)pw,  (uint2*)(p_wh+2*W2), (uint2*)(p_wl+2*W2), (int)(W2/4));

  // k -> kT (+ norm partials), v -> vT
  k_gemm_kv<<<dim3(8,384), 256, GSMEM>>>(p_wh,    p_wl,    p_kTh, p_kTl, 1);
  k_gemm_kv<<<dim3(8,384), 256, GSMEM>>>(p_wh+W2, p_wl+W2, p_vTh, p_vTl, 0);
  k_reduce<<<1,1024>>>();

  // kt (HMMA, K=768) -> ktT bf16; out (HMMA, K=128) -> gelu in-place xh/xl
  k_gemm_kt<<<512, 256, GSMEM>>>(sc);
  k_gemm_out<<<dim3(6,512), 256, GSMEM>>>();

  // proj (HMMA, K=1024) + bias, transposed write direct to [B,N,C]
  k_gemm_proj<<<dim3(8,384), 256, GSMEM>>>(p_wh+2*W2, p_wl+2*W2, pb, out);
}

// round 10
// speedup vs baseline: 1.3013x; 1.3013x over previous
#include <cuda_runtime.h>
#include <cuda_bf16.h>
#include <math.h>
#include <stdint.h>

// Problem constants: B=64, N=1024, C=768, heads=8, d=128
#define B_ 64
#define N_ 1024
#define C_ 768
#define H_ 8
#define D_ 128
#define EPSF 1e-8f
#define ROWS_ ((size_t)B_*C_)   // 49152

// ---------------------------------------------------------------------------
// Scratch (device globals — allocation-free rule)
// ---------------------------------------------------------------------------
__device__ __nv_bfloat16 g_xh[ROWS_*N_];   // xt hi (bf16, for out GEMM)
__device__ __nv_bfloat16 g_xl[ROWS_*N_];   // xt lo
__device__ int8_t g_xq1[ROWS_*N_];         // xt int8 chunk1 / later gelu q1
__device__ int8_t g_xq2[ROWS_*N_];         // xt int8 chunk2 / later gelu q2
__device__ int8_t g_wq1[3][(size_t)N_*N_];
__device__ int8_t g_wq2[3][(size_t)N_*N_];
__device__ __nv_bfloat16 g_kTh[(size_t)B_*N_*C_];  // kT [b][n][c] hi
__device__ __nv_bfloat16 g_kTl[(size_t)B_*N_*C_];
__device__ __nv_bfloat16 g_vTh[(size_t)B_*N_*C_];
__device__ __nv_bfloat16 g_vTl[(size_t)B_*N_*C_];
__device__ __nv_bfloat16 g_kth[(size_t)B_*H_*D_*D_];  // ktT [bh][m][n] hi
__device__ __nv_bfloat16 g_ktl[(size_t)B_*H_*D_*D_];
__device__ float g_gelu[ROWS_*N_];         // fp32 gelu output (proj input)
__device__ float g_part[3072];
__device__ float g_norm2;
__device__ float g_mpart[4864];            // amax partials
__device__ float g_scales[8];              // 0:x 1:qkw 2:vw 3:pw 4:gelu

// ---------------------------------------------------------------------------
// Helpers
// ---------------------------------------------------------------------------
__device__ __forceinline__ uint32_t smem_u32(const void* p){
  uint32_t a;
  asm("{ .reg .u64 t; cvta.to.shared.u64 t, %1; cvt.u32.u64 %0, t; }" : "=r"(a) : "l"(p));
  return a;
}
__device__ __forceinline__ void split2(float fx, float fy, uint32_t& hi, uint32_t& lo){
  uint32_t h;
  asm("cvt.rn.bf16x2.f32 %0, %1, %2;" : "=r"(h) : "f"(fy), "f"(fx));
  float hx = __uint_as_float(h << 16);
  float hy = __uint_as_float(h & 0xffff0000u);
  float lx = fx - hx, ly = fy - hy;
  asm("cvt.rn.bf16x2.f32 %0, %1, %2;" : "=r"(lo) : "f"(ly), "f"(lx));
  hi = h;
}
__device__ __forceinline__ float gelu_exact(float x){
  return 0.5f * x * (1.0f + erff(x * 0.7071067811865475f));
}
// int8 2-chunk quantization: x ~= (S/127)*(q1 + q2/254)
__device__ __forceinline__ void quant2(float v, float qs, int8_t& q1, int8_t& q2){
  float q = v * qs;
  float a1 = rintf(q);
  q1 = (int8_t)(int)a1;
  q2 = (int8_t)(int)rintf((q - a1) * 254.0f);
}

#define CP_ASYNC16(s, g) \
  asm volatile("cp.async.cg.shared.global [%0], [%1], 16;" :: "r"(s), "l"(g) : "memory")
#define CP_COMMIT() asm volatile("cp.async.commit_group;" ::: "memory")
#define CP_WAIT1()  asm volatile("cp.async.wait_group 1;" ::: "memory")
#define CP_WAIT0()  asm volatile("cp.async.wait_group 0;" ::: "memory")

__device__ __forceinline__ void ldmx4(uint32_t* r, uint32_t addr){
  asm volatile("ldmatrix.sync.aligned.m8n8.x4.shared.b16 {%0,%1,%2,%3}, [%4];"
    : "=r"(r[0]), "=r"(r[1]), "=r"(r[2]), "=r"(r[3]) : "r"(addr));
}
__device__ __forceinline__ void mma16816(float* c, const uint32_t* a, const uint32_t* b){
  asm volatile("mma.sync.aligned.m16n8k16.row.col.f32.bf16.bf16.f32 "
    "{%0,%1,%2,%3},{%4,%5,%6,%7},{%8,%9},{%0,%1,%2,%3};"
    : "+f"(c[0]), "+f"(c[1]), "+f"(c[2]), "+f"(c[3])
    : "r"(a[0]), "r"(a[1]), "r"(a[2]), "r"(a[3]), "r"(b[0]), "r"(b[1]));
}
__device__ __forceinline__ void imma16832(int* c, const uint32_t* a, const uint32_t* b){
  asm volatile("mma.sync.aligned.m16n8k32.row.col.s32.s8.s8.s32 "
    "{%0,%1,%2,%3},{%4,%5,%6,%7},{%8,%9},{%0,%1,%2,%3};"
    : "+r"(c[0]), "+r"(c[1]), "+r"(c[2]), "+r"(c[3])
    : "r"(a[0]), "r"(a[1]), "r"(a[2]), "r"(a[3]), "r"(b[0]), "r"(b[1]));
}

// ===========================================================================
// amax kernels (exact max — order independent, deterministic)
// ===========================================================================
__global__ void k_amax(const float* __restrict__ src, size_t n, int slot0){
  __shared__ float sm[256];
  float m = 0.f;
  for (size_t i = (size_t)blockIdx.x*256 + threadIdx.x; i < n; i += (size_t)gridDim.x*256)
    m = fmaxf(m, fabsf(src[i]));
  sm[threadIdx.x] = m;
  __syncthreads();
  for (int o = 128; o; o >>= 1){
    if (threadIdx.x < o) sm[threadIdx.x] = fmaxf(sm[threadIdx.x], sm[threadIdx.x+o]);
    __syncthreads();
  }
  if (threadIdx.x == 0) g_mpart[slot0 + blockIdx.x] = sm[0];
}
__global__ void k_amax_fin(){
  __shared__ float sm[1024];
  const int t = threadIdx.x;
  const int base[4] = {0, 1024, 1280, 1536};
  const int cnt[4]  = {1024, 256, 256, 256};
#pragma unroll
  for (int r = 0; r < 4; r++){
    float m = 0.f;
    for (int i = t; i < cnt[r]; i += 1024) m = fmaxf(m, g_mpart[base[r]+i]);
    sm[t] = m;
    __syncthreads();
    for (int o = 512; o; o >>= 1){
      if (t < o) sm[t] = fmaxf(sm[t], sm[t+o]);
      __syncthreads();
    }
    if (t == 0) g_scales[r] = sm[0];
    __syncthreads();
  }
}
__global__ void k_scale_gelu(){
  __shared__ float sm[1024];
  const int t = threadIdx.x;
  float m = 0.f;
  for (int i = t; i < 3072; i += 1024) m = fmaxf(m, g_mpart[1792+i]);
  sm[t] = m;
  __syncthreads();
  for (int o = 512; o; o >>= 1){
    if (t < o) sm[t] = fmaxf(sm[t], sm[t+o]);
    __syncthreads();
  }
  if (t == 0) g_scales[4] = sm[0];
}

// ===========================================================================
// Quantization kernels
// ===========================================================================
__global__ void k_quantW(const float* __restrict__ in, int8_t* __restrict__ q1,
                         int8_t* __restrict__ q2, int sidx, int n4){
  int i = blockIdx.x * blockDim.x + threadIdx.x;
  if (i >= n4) return;
  const float qs = 127.0f / g_scales[sidx];
  float4 v = ((const float4*)in)[i];
  int8_t a1,a2,b1,b2,c1,c2,d1,d2;
  quant2(v.x, qs, a1, a2); quant2(v.y, qs, b1, b2);
  quant2(v.z, qs, c1, c2); quant2(v.w, qs, d1, d2);
  ((uchar4*)q1)[i] = make_uchar4((uint8_t)a1,(uint8_t)b1,(uint8_t)c1,(uint8_t)d1);
  ((uchar4*)q2)[i] = make_uchar4((uint8_t)a2,(uint8_t)b2,(uint8_t)c2,(uint8_t)d2);
}
__global__ void k_quant_gelu(int n4){
  int i = blockIdx.x * blockDim.x + threadIdx.x;
  if (i >= n4) return;
  const float qs = 127.0f / g_scales[4];
  float4 v = ((const float4*)g_gelu)[i];
  int8_t a1,a2,b1,b2,c1,c2,d1,d2;
  quant2(v.x, qs, a1, a2); quant2(v.y, qs, b1, b2);
  quant2(v.z, qs, c1, c2); quant2(v.w, qs, d1, d2);
  ((uchar4*)g_xq1)[i] = make_uchar4((uint8_t)a1,(uint8_t)b1,(uint8_t)c1,(uint8_t)d1);
  ((uchar4*)g_xq2)[i] = make_uchar4((uint8_t)a2,(uint8_t)b2,(uint8_t)c2,(uint8_t)d2);
}

// ===========================================================================
// x transpose: fp32 [B,N,C] -> bf16 hi/lo + int8 q1/q2 planes, [b*C+c][n]
// ===========================================================================
__global__ void k_transpose_x(const float* __restrict__ in){
  __shared__ float t[32][33];
  const size_t zo = (size_t)blockIdx.z * C_ * N_;
  const int i0 = blockIdx.y*32, j0 = blockIdx.x*32;
  const float* ip = in + zo;
  const float qs = 127.0f / g_scales[0];
#pragma unroll
  for (int k = threadIdx.y; k < 32; k += 8)
    t[k][threadIdx.x] = ip[(size_t)(i0+k)*C_ + j0 + threadIdx.x];
  __syncthreads();
#pragma unroll
  for (int k = threadIdx.y; k < 32; k += 8){
    const size_t o = zo + (size_t)(j0+k)*N_ + i0 + threadIdx.x;
    const float v = t[threadIdx.x][k];
    uint32_t h;
    asm("cvt.rn.bf16x2.f32 %0, %1, %1;" : "=r"(h) : "f"(v));
    const float hv = __uint_as_float(h << 16);
    g_xh[o] = __ushort_as_bfloat16((unsigned short)(h & 0xffffu));
    float lv = v - hv;
    uint32_t l;
    asm("cvt.rn.bf16x2.f32 %0, %1, %1;" : "=r"(l) : "f"(lv));
    g_xl[o] = __ushort_as_bfloat16((unsigned short)(l & 0xffffu));
    int8_t q1, q2;
    quant2(v, qs, q1, q2);
    g_xq1[o] = q1;
    g_xq2[o] = q2;
  }
}

// ===========================================================================
// int8 IMMA mainloop: C128x128 over nch*32 K, 2-chunk decomposition.
// Tiles: A1,A2,B1,B2, 128 rows x 32B each (row stride 48B for bank spread).
// accM += a1*b1 ; accC += a1*b2 + a2*b1
// ===========================================================================
#define RSBI 48
#define TILE_I (128*RSBI)            // 6144 B
#define STAGE_I (4*TILE_I)           // 24576 B
#define GSMEM_I (3*STAGE_I)          // 73728 B

__device__ __forceinline__ void gemm_main_i8(
    uint32_t sb, int tid,
    const int8_t* __restrict__ A1, const int8_t* __restrict__ A2, int lda,
    const int8_t* __restrict__ B1, const int8_t* __restrict__ B2, int ldb,
    int nch, int (*accM)[4], int (*accC)[4]){
  const int t64  = tid & 63;
  const int tile = tid >> 6;                 // 0:A1 1:A2 2:B1 3:B2
  const int8_t* gsrc; int ld;
  if      (tile == 0){ gsrc = A1; ld = lda; }
  else if (tile == 1){ gsrc = A2; ld = lda; }
  else if (tile == 2){ gsrc = B1; ld = ldb; }
  else               { gsrc = B2; ld = ldb; }

  auto issue = [&](int ch, int stage){
    const int k0 = ch * 32;
    const uint32_t sbase = sb + stage * STAGE_I + tile * TILE_I;
#pragma unroll
    for (int j = 0; j < 4; j++){
      const int seg = t64 + 64 * j;
      const int row = seg >> 1, s = seg & 1;
      CP_ASYNC16(sbase + row * RSBI + s * 16,
                 (const char*)(gsrc + (size_t)row * ld + k0) + s * 16);
    }
    CP_COMMIT();
  };

  issue(0, 0);
  issue(1, 1);

  const int wid = tid >> 5, lane = tid & 31;
  const int wm = (wid >> 2) * 64, wn = (wid & 3) * 32;
  const int a_row = lane & 15, a_kb = (lane >> 4) * 16;
  const int b_row = (lane & 7) + ((lane >> 4) * 8);
  const int b_kb  = ((lane >> 3) & 1) * 16;

  for (int ch = 0; ch < nch; ch++){
    CP_WAIT1();
    __syncthreads();
    if (ch + 2 < nch) issue(ch + 2, (ch + 2) % 3);
    else CP_COMMIT();

    const uint32_t st = sb + (ch % 3) * STAGE_I;
    const uint32_t a1T = st,            a2T = st + TILE_I;
    const uint32_t b1T = st + 2*TILE_I, b2T = st + 3*TILE_I;

    uint32_t a1[4][4], a2[4][4], b1[4][2], b2[4][2];
#pragma unroll
    for (int mi = 0; mi < 4; mi++){
      const uint32_t ro = (uint32_t)(wm + mi*16 + a_row) * RSBI + a_kb;
      ldmx4(a1[mi], a1T + ro);
      ldmx4(a2[mi], a2T + ro);
    }
#pragma unroll
    for (int nh = 0; nh < 2; nh++){
      const uint32_t ro = (uint32_t)(wn + nh*16 + b_row) * RSBI + b_kb;
      uint32_t r[4];
      ldmx4(r, b1T + ro);
      b1[nh*2+0][0]=r[0]; b1[nh*2+0][1]=r[1]; b1[nh*2+1][0]=r[2]; b1[nh*2+1][1]=r[3];
      ldmx4(r, b2T + ro);
      b2[nh*2+0][0]=r[0]; b2[nh*2+0][1]=r[1]; b2[nh*2+1][0]=r[2]; b2[nh*2+1][1]=r[3];
    }
#pragma unroll
    for (int mi = 0; mi < 4; mi++)
#pragma unroll
      for (int ni = 0; ni < 4; ni++){
        imma16832(accM[4*mi+ni], a1[mi], b1[ni]);
        imma16832(accC[4*mi+ni], a1[mi], b2[ni]);
        imma16832(accC[4*mi+ni], a2[mi], b1[ni]);
      }
  }
  CP_WAIT0();
  __syncthreads();
}

// ===========================================================================
// bf16 HMMA mainloop (unchanged, for kt/out GEMMs)
// ===========================================================================
#define KC 32
#define RSB 80
#define TILE_SB (128*RSB)
#define STAGE_B (4*TILE_SB)
#define GSMEM (3*STAGE_B)            // 122880 B

__device__ __forceinline__ void gemm_main(
    uint32_t sb, int tid,
    const __nv_bfloat16* __restrict__ Ah, const __nv_bfloat16* __restrict__ Al, int lda,
    const __nv_bfloat16* __restrict__ Bh, const __nv_bfloat16* __restrict__ Bl, int ldb,
    int nch, float (*acc)[4]){
  const int t64  = tid & 63;
  const int tile = tid >> 6;
  const __nv_bfloat16* gsrc; int ld;
  if      (tile == 0){ gsrc = Ah; ld = lda; }
  else if (tile == 1){ gsrc = Al; ld = lda; }
  else if (tile == 2){ gsrc = Bh; ld = ldb; }
  else               { gsrc = Bl; ld = ldb; }

  auto issue = [&](int ch, int stage){
    const int k0 = ch * KC;
    const uint32_t sbase = sb + stage * STAGE_B + tile * TILE_SB;
#pragma unroll
    for (int j = 0; j < 8; j++){
      const int seg = t64 + 64 * j;
      const int row = seg >> 2, s4 = seg & 3;
      CP_ASYNC16(sbase + row * RSB + s4 * 16,
                 (const char*)(gsrc + (size_t)row * ld + k0) + s4 * 16);
    }
    CP_COMMIT();
  };

  issue(0, 0);
  issue(1, 1);

  const int wid = tid >> 5, lane = tid & 31;
  const int wm = (wid >> 2) * 64, wn = (wid & 3) * 32;
  const int a_row = lane % 16, a_k8 = (lane >> 4) * 8;
  const int b_row = (lane & 7) + ((lane >> 4) * 8);
  const int b_k8  = ((lane >> 3) & 1) * 8;

  for (int ch = 0; ch < nch; ch++){
    CP_WAIT1();
    __syncthreads();
    if (ch + 2 < nch) issue(ch + 2, (ch + 2) % 3);
    else CP_COMMIT();

    const uint32_t st = sb + (ch % 3) * STAGE_B;
    const uint32_t aH = st,             aL = st + TILE_SB;
    const uint32_t bH = st + 2*TILE_SB, bL = st + 3*TILE_SB;

#pragma unroll
    for (int kk = 0; kk < 2; kk++){
      uint32_t ah[4][4], al[4][4], bh[4][2], bl[4][2];
      const int kc = kk * 32 + a_k8 * 2;
#pragma unroll
      for (int mi = 0; mi < 4; mi++){
        const uint32_t ro = (uint32_t)(wm + mi*16 + a_row) * RSB + kc;
        ldmx4(ah[mi], aH + ro);
        ldmx4(al[mi], aL + ro);
      }
#pragma unroll
      for (int nh = 0; nh < 2; nh++){
        const uint32_t ro = (uint32_t)(wn + nh*16 + b_row) * RSB + kk*32 + b_k8*2;
        uint32_t r[4];
        ldmx4(r, bH + ro);
        bh[nh*2+0][0]=r[0]; bh[nh*2+0][1]=r[1]; bh[nh*2+1][0]=r[2]; bh[nh*2+1][1]=r[3];
        ldmx4(r, bL + ro);
        bl[nh*2+0][0]=r[0]; bl[nh*2+0][1]=r[1]; bl[nh*2+1][0]=r[2]; bl[nh*2+1][1]=r[3];
      }
#pragma unroll
      for (int mi = 0; mi < 4; mi++)
#pragma unroll
        for (int ni = 0; ni < 4; ni++){
          mma16816(acc[4*mi+ni], ah[mi], bh[ni]);
          mma16816(acc[4*mi+ni], ah[mi], bl[ni]);
          mma16816(acc[4*mi+ni], al[mi], bh[ni]);
        }
    }
  }
  CP_WAIT0();
  __syncthreads();
}

// Transposed bf16 hi/lo epilogue via fp32 smem bounce.
#define TS 130
__device__ __forceinline__ void epi_T_bf16(
    float (*acc)[4], char* smem, int tid, float f,
    __nv_bfloat16* dsth, __nv_bfloat16* dstl, int ldd){
  float* T = (float*)smem;
  const int wid = tid >> 5, lane = tid & 31;
  const int wm = (wid >> 2) * 64, wn = (wid & 3) * 32;
  const int tr = lane >> 2, tc = (lane & 3) * 2;
#pragma unroll
  for (int mi = 0; mi < 4; mi++)
#pragma unroll
    for (int ni = 0; ni < 4; ni++){
      float* a = acc[4*mi+ni];
      const int r = wm + mi*16 + tr, c = wn + ni*8 + tc;
      T[r*TS + c]     = a[0]*f; T[r*TS + c + 1]     = a[1]*f;
      T[(r+8)*TS + c] = a[2]*f; T[(r+8)*TS + c + 1] = a[3]*f;
    }
  __syncthreads();
#pragma unroll
  for (int it = 0; it < 4; it++){
    const int j = it*32 + (tid >> 3);
    const int mbase = (tid & 7) * 2;
#pragma unroll
    for (int p = 0; p < 8; p++){
      const int m = mbase + p*16;
      float f0 = T[m*TS + j], f1 = T[(m+1)*TS + j];
      uint32_t h, l; split2(f0, f1, h, l);
      *(uint32_t*)(dsth + (size_t)j*ldd + m) = h;
      *(uint32_t*)(dstl + (size_t)j*ldd + m) = l;
    }
  }
  __syncthreads();
}

// ===========================================================================
// kv GEMM (int8): C = xt @ W^T -> transposed bf16 hi/lo (+ norm partials)
// ===========================================================================
__global__ void __launch_bounds__(256,1)
k_gemm_kv_i8(const int8_t* __restrict__ W1, const int8_t* __restrict__ W2,
             int wsidx,
             __nv_bfloat16* __restrict__ dsth, __nv_bfloat16* __restrict__ dstl,
             int with_norm){
  extern __shared__ __align__(128) char smem[];
  __shared__ float red[8];
  const uint32_t sb = smem_u32(smem);
  const int tid = threadIdx.x;
  const int n0 = blockIdx.x * 128, m0 = blockIdx.y * 128;
  int accM[16][4] = {}, accC[16][4] = {};
  gemm_main_i8(sb, tid, g_xq1 + (size_t)m0*N_, g_xq2 + (size_t)m0*N_, N_,
               W1 + (size_t)n0*N_, W2 + (size_t)n0*N_, N_, 32, accM, accC);
  const float f = g_scales[0] * g_scales[wsidx] / 16129.0f;
  float facc[16][4];
#pragma unroll
  for (int q = 0; q < 16; q++)
#pragma unroll
    for (int e = 0; e < 4; e++)
      facc[q][e] = f * ((float)accM[q][e] + (float)accC[q][e] * (1.0f/254.0f));
  if (with_norm){
    float s2 = 0.f;
#pragma unroll
    for (int q = 0; q < 16; q++)
#pragma unroll
      for (int e = 0; e < 4; e++) s2 += facc[q][e]*facc[q][e];
#pragma unroll
    for (int o = 16; o; o >>= 1) s2 += __shfl_down_sync(0xffffffffu, s2, o);
    if ((tid & 31) == 0) red[tid >> 5] = s2;
    __syncthreads();
    if (tid == 0){
      float t = 0.f;
#pragma unroll
      for (int w = 0; w < 8; w++) t += red[w];
      g_part[blockIdx.y * 8 + blockIdx.x] = t;
    }
  }
  const int b = m0 / C_, c0 = m0 % C_;
  const size_t off = ((size_t)b*N_ + n0) * C_ + c0;
  epi_T_bf16(facc, smem, tid, 1.f, dsth + off, dstl + off, C_);
}

__global__ void k_reduce(){
  __shared__ float sh[1024];
  const int t = threadIdx.x;
  sh[t] = g_part[t] + g_part[t+1024] + g_part[t+2048];
  __syncthreads();
  for (int o = 512; o; o >>= 1){
    if (t < o) sh[t] += sh[t+o];
    __syncthreads();
  }
  if (t == 0) g_norm2 = sh[0];
}

// ===========================================================================
// kt GEMM (bf16): kt[n][m] = sum_c kT[n][c]*vT[m][c]; scaled; store ktT[m][n]
// ===========================================================================
__global__ void __launch_bounds__(256,1)
k_gemm_kt(const float* __restrict__ scale){
  extern __shared__ __align__(128) char smem[];
  const uint32_t sb = smem_u32(smem);
  const int tid = threadIdx.x;
  const int bh = blockIdx.x, b = bh >> 3, h = bh & 7;
  const size_t base = ((size_t)b*N_ + h*D_) * C_;
  float acc[16][4] = {};
  gemm_main(sb, tid, g_kTh + base, g_kTl + base, C_,
            g_vTh + base, g_vTl + base, C_, 24, acc);
  const float nrm = sqrtf(g_norm2) + EPSF;
  const float f = scale[h] / (nrm*nrm);
  epi_T_bf16(acc, smem, tid, f,
             g_kth + (size_t)bh*D_*D_, g_ktl + (size_t)bh*D_*D_, D_);
}

// ===========================================================================
// out GEMM (bf16): out1 = q @ kt -> exact gelu fp32 + per-block amax partial
// ===========================================================================
__global__ void __launch_bounds__(256,1)
k_gemm_out(){
  extern __shared__ __align__(128) char smem[];
  __shared__ float redm[8];
  const uint32_t sb = smem_u32(smem);
  const int tid = threadIdx.x;
  const int c0 = blockIdx.x * 128;
  const int bh = blockIdx.y, b = bh >> 3, h = bh & 7;
  const size_t Abase = ((size_t)b*C_ + c0) * N_ + (size_t)h*D_;
  float acc[16][4] = {};
  gemm_main(sb, tid, g_xh + Abase, g_xl + Abase, N_,
            g_kth + (size_t)bh*D_*D_, g_ktl + (size_t)bh*D_*D_, D_, 4, acc);
  const int wid = tid >> 5, lane = tid & 31;
  const int wm = (wid >> 2) * 64, wn = (wid & 3) * 32;
  const int tr = lane >> 2, tc = (lane & 3) * 2;
  float mx = 0.f;
#pragma unroll
  for (int mi = 0; mi < 4; mi++)
#pragma unroll
    for (int ni = 0; ni < 4; ni++){
      float* a = acc[4*mi+ni];
      const int col = wn + ni*8 + tc;
      const size_t r0 = Abase + (size_t)(wm + mi*16 + tr) * N_ + col;
      const size_t r1 = r0 + 8*N_;
      float g0 = gelu_exact(a[0]), g1 = gelu_exact(a[1]);
      float g2 = gelu_exact(a[2]), g3 = gelu_exact(a[3]);
      *(float2*)(g_gelu + r0) = make_float2(g0, g1);
      *(float2*)(g_gelu + r1) = make_float2(g2, g3);
      mx = fmaxf(mx, fmaxf(fmaxf(fabsf(g0), fabsf(g1)), fmaxf(fabsf(g2), fabsf(g3))));
    }
#pragma unroll
  for (int o = 16; o; o >>= 1) mx = fmaxf(mx, __shfl_down_sync(0xffffffffu, mx, o));
  if (lane == 0) redm[wid] = mx;
  __syncthreads();
  if (tid == 0){
    float t = 0.f;
#pragma unroll
    for (int w = 0; w < 8; w++) t = fmaxf(t, redm[w]);
    g_mpart[1792 + blockIdx.y*6 + blockIdx.x] = t;
  }
}

// ===========================================================================
// proj GEMM (int8): out2 = gelu @ proj_w^T + pb; transposed write -> [B,N,C]
// ===========================================================================
__global__ void __launch_bounds__(256,1)
k_gemm_proj_i8(const int8_t* __restrict__ W1, const int8_t* __restrict__ W2,
               const float* __restrict__ pb, float* __restrict__ out){
  extern __shared__ __align__(128) char smem[];
  const uint32_t sb = smem_u32(smem);
  const int tid = threadIdx.x;
  const int n0 = blockIdx.x * 128, m0 = blockIdx.y * 128;
  int accM[16][4] = {}, accC[16][4] = {};
  gemm_main_i8(sb, tid, g_xq1 + (size_t)m0*N_, g_xq2 + (size_t)m0*N_, N_,
               W1 + (size_t)n0*N_, W2 + (size_t)n0*N_, N_, 32, accM, accC);
  const float f = g_scales[4] * g_scales[3] / 16129.0f;
  const int wid = tid >> 5, lane = tid & 31;
  const int wm = (wid >> 2) * 64, wn = (wid & 3) * 32;
  const int tr = lane >> 2, tc = (lane & 3) * 2;
  float* T = (float*)smem;
#pragma unroll
  for (int mi = 0; mi < 4; mi++)
#pragma unroll
    for (int ni = 0; ni < 4; ni++){
      int* aM = accM[4*mi+ni];
      int* aC = accC[4*mi+ni];
      const int c = wn + ni*8 + tc;
      const float2 bv = *(const float2*)(pb + n0 + c);
      const int r = wm + mi*16 + tr;
      float v0 = f*((float)aM[0] + (float)aC[0]*(1.0f/254.0f)) + bv.x;
      float v1 = f*((float)aM[1] + (float)aC[1]*(1.0f/254.0f)) + bv.y;
      float v2 = f*((float)aM[2] + (float)aC[2]*(1.0f/254.0f)) + bv.x;
      float v3 = f*((float)aM[3] + (float)aC[3]*(1.0f/254.0f)) + bv.y;
      T[r*TS + c]     = v0; T[r*TS + c + 1]     = v1;
      T[(r+8)*TS + c] = v2; T[(r+8)*TS + c + 1] = v3;
    }
  __syncthreads();
  const int b = m0 / C_, c0 = m0 % C_;
  float* dst = out + ((size_t)b*N_ + n0) * C_ + c0;
#pragma unroll
  for (int it = 0; it < 4; it++){
    const int j = it*32 + (tid >> 3);
    const int mbase = (tid & 7) * 2;
#pragma unroll
    for (int p = 0; p < 8; p++){
      const int m = mbase + p*16;
      *(float2*)(dst + (size_t)j*C_ + m) = make_float2(T[m*TS + j], T[(m+1)*TS + j]);
    }
  }
}

// ---------------------------------------------------------------------------
// Launch: graph-capturable, allocation-free, deterministic.
// ---------------------------------------------------------------------------
extern "C" void kernel_launch(void* const* d_in, const int* in_sizes, int n_in,
                              void* d_out, int out_size){
  const float* x   = (const float*)d_in[0];
  const float* qkw = (const float*)d_in[1];
  const float* vw  = (const float*)d_in[2];
  const float* pw  = (const float*)d_in[3];
  const float* pb  = (const float*)d_in[4];
  const float* sc  = (const float*)d_in[5];
  float* out = (float*)d_out;

  int8_t *p_wq1=nullptr, *p_wq2=nullptr;
  __nv_bfloat16 *p_kTh=nullptr, *p_kTl=nullptr, *p_vTh=nullptr, *p_vTl=nullptr;
  cudaGetSymbolAddress((void**)&p_wq1, g_wq1);
  cudaGetSymbolAddress((void**)&p_wq2, g_wq2);
  cudaGetSymbolAddress((void**)&p_kTh, g_kTh);
  cudaGetSymbolAddress((void**)&p_kTl, g_kTl);
  cudaGetSymbolAddress((void**)&p_vTh, g_vTh);
  cudaGetSymbolAddress((void**)&p_vTl, g_vTl);

  cudaFuncSetAttribute(k_gemm_kv_i8,  cudaFuncAttributeMaxDynamicSharedMemorySize, GSMEM_I);
  cudaFuncSetAttribute(k_gemm_proj_i8,cudaFuncAttributeMaxDynamicSharedMemorySize, GSMEM_I);
  cudaFuncSetAttribute(k_gemm_kt,  cudaFuncAttributeMaxDynamicSharedMemorySize, GSMEM);
  cudaFuncSetAttribute(k_gemm_out, cudaFuncAttributeMaxDynamicSharedMemorySize, GSMEM);

  const size_t W2 = (size_t)N_*N_;

  // amax scales (exact, deterministic)
  k_amax<<<1024, 256>>>(x,   ROWS_*N_, 0);
  k_amax<<<256, 256>>>(qkw, W2, 1024);
  k_amax<<<256, 256>>>(vw,  W2, 1280);
  k_amax<<<256, 256>>>(pw,  W2, 1536);
  k_amax_fin<<<1, 1024>>>();

  // x -> xt (bf16 hi/lo + int8 q1/q2); weight quantization
  k_transpose_x<<<dim3(24,32,64), dim3(32,8)>>>(x);
  k_quantW<<<1024, 256>>>(qkw, p_wq1,      p_wq2,      1, (int)(W2/4));
  k_quantW<<<1024, 256>>>(vw,  p_wq1+W2,   p_wq2+W2,   2, (int)(W2/4));
  k_quantW<<<1024, 256>>>(pw,  p_wq1+2*W2, p_wq2+2*W2, 3, (int)(W2/4));

  // k -> kT (+ norm partials), v -> vT  (int8 IMMA)
  k_gemm_kv_i8<<<dim3(8,384), 256, GSMEM_I>>>(p_wq1,    p_wq2,    1, p_kTh, p_kTl, 1);
  k_gemm_kv_i8<<<dim3(8,384), 256, GSMEM_I>>>(p_wq1+W2, p_wq2+W2, 2, p_vTh, p_vTl, 0);
  k_reduce<<<1,1024>>>();

  // kt (bf16) -> ktT; out (bf16) -> gelu fp32 + amax partials
  k_gemm_kt<<<512, 256, GSMEM>>>(sc);
  k_gemm_out<<<dim3(6,512), 256, GSMEM>>>();
  k_scale_gelu<<<1, 1024>>>();
  k_quant_gelu<<<49152, 256>>>((int)(ROWS_*N_/4));

  // proj (int8 IMMA) + bias, transposed write direct to [B,N,C]
  k_gemm_proj_i8<<<dim3(8,384), 256, GSMEM_I>>>(p_wq1+2*W2, p_wq2+2*W2, pb, out);
}

// round 11
// speedup vs baseline: 1.3290x; 1.0213x over previous
#include <cuda_runtime.h>
#include <cuda_bf16.h>
#include <math.h>
#include <stdint.h>

// Problem constants: B=64, N=1024, C=768, heads=8, d=128
#define B_ 64
#define N_ 1024
#define C_ 768
#define H_ 8
#define D_ 128
#define EPSF 1e-8f
#define ROWS_ ((size_t)B_*C_)   // 49152
#define KTN_ ((size_t)B_*H_*D_*D_)   // 8388608

// ---------------------------------------------------------------------------
// Scratch (device globals — allocation-free rule)
// ---------------------------------------------------------------------------
__device__ int8_t g_xq1[ROWS_*N_];         // xt int8 chunk1
__device__ int8_t g_xq2[ROWS_*N_];         // xt int8 chunk2
__device__ int8_t g_wq1[3][(size_t)N_*N_];
__device__ int8_t g_wq2[3][(size_t)N_*N_];
__device__ __nv_bfloat16 g_kTh[(size_t)B_*N_*C_];  // kT [b][n][c] hi
__device__ __nv_bfloat16 g_kTl[(size_t)B_*N_*C_];
__device__ __nv_bfloat16 g_vTh[(size_t)B_*N_*C_];
__device__ __nv_bfloat16 g_vTl[(size_t)B_*N_*C_];
__device__ float  g_ktf[KTN_];             // ktT fp32 [bh][m][n]
__device__ int8_t g_ktq1[KTN_];            // ktT int8 chunk1
__device__ int8_t g_ktq2[KTN_];            // ktT int8 chunk2
__device__ float g_gelu[ROWS_*N_];         // fp32 gelu output (proj input)
__device__ float g_part[3072];
__device__ float g_norm2;
__device__ float g_mpart[6144];            // amax partials
__device__ float g_scales[8];              // 0:x 1:qkw 2:vw 3:pw 4:gelu 5:kt

// ---------------------------------------------------------------------------
// Helpers
// ---------------------------------------------------------------------------
__device__ __forceinline__ uint32_t smem_u32(const void* p){
  uint32_t a;
  asm("{ .reg .u64 t; cvta.to.shared.u64 t, %1; cvt.u32.u64 %0, t; }" : "=r"(a) : "l"(p));
  return a;
}
__device__ __forceinline__ void split2(float fx, float fy, uint32_t& hi, uint32_t& lo){
  uint32_t h;
  asm("cvt.rn.bf16x2.f32 %0, %1, %2;" : "=r"(h) : "f"(fy), "f"(fx));
  float hx = __uint_as_float(h << 16);
  float hy = __uint_as_float(h & 0xffff0000u);
  float lx = fx - hx, ly = fy - hy;
  asm("cvt.rn.bf16x2.f32 %0, %1, %2;" : "=r"(lo) : "f"(ly), "f"(lx));
  hi = h;
}
__device__ __forceinline__ float gelu_exact(float x){
  return 0.5f * x * (1.0f + erff(x * 0.7071067811865475f));
}
// int8 2-chunk quantization: x ~= (S/127)*(q1 + q2/254)
__device__ __forceinline__ void quant2(float v, float qs, int8_t& q1, int8_t& q2){
  float q = v * qs;
  float a1 = rintf(q);
  q1 = (int8_t)(int)a1;
  q2 = (int8_t)(int)rintf((q - a1) * 254.0f);
}

#define CP_ASYNC16(s, g) \
  asm volatile("cp.async.cg.shared.global [%0], [%1], 16;" :: "r"(s), "l"(g) : "memory")
#define CP_COMMIT() asm volatile("cp.async.commit_group;" ::: "memory")
#define CP_WAIT1()  asm volatile("cp.async.wait_group 1;" ::: "memory")
#define CP_WAIT0()  asm volatile("cp.async.wait_group 0;" ::: "memory")

__device__ __forceinline__ void ldmx4(uint32_t* r, uint32_t addr){
  asm volatile("ldmatrix.sync.aligned.m8n8.x4.shared.b16 {%0,%1,%2,%3}, [%4];"
    : "=r"(r[0]), "=r"(r[1]), "=r"(r[2]), "=r"(r[3]) : "r"(addr));
}
__device__ __forceinline__ void mma16816(float* c, const uint32_t* a, const uint32_t* b){
  asm volatile("mma.sync.aligned.m16n8k16.row.col.f32.bf16.bf16.f32 "
    "{%0,%1,%2,%3},{%4,%5,%6,%7},{%8,%9},{%0,%1,%2,%3};"
    : "+f"(c[0]), "+f"(c[1]), "+f"(c[2]), "+f"(c[3])
    : "r"(a[0]), "r"(a[1]), "r"(a[2]), "r"(a[3]), "r"(b[0]), "r"(b[1]));
}
__device__ __forceinline__ void imma16832(int* c, const uint32_t* a, const uint32_t* b){
  asm volatile("mma.sync.aligned.m16n8k32.row.col.s32.s8.s8.s32 "
    "{%0,%1,%2,%3},{%4,%5,%6,%7},{%8,%9},{%0,%1,%2,%3};"
    : "+r"(c[0]), "+r"(c[1]), "+r"(c[2]), "+r"(c[3])
    : "r"(a[0]), "r"(a[1]), "r"(a[2]), "r"(a[3]), "r"(b[0]), "r"(b[1]));
}

// ===========================================================================
// amax kernels (exact max — order independent, deterministic)
// ===========================================================================
__global__ void k_amax(const float* __restrict__ src, size_t n, int slot0){
  __shared__ float sm[256];
  float m = 0.f;
  for (size_t i = (size_t)blockIdx.x*256 + threadIdx.x; i < n; i += (size_t)gridDim.x*256)
    m = fmaxf(m, fabsf(src[i]));
  sm[threadIdx.x] = m;
  __syncthreads();
  for (int o = 128; o; o >>= 1){
    if (threadIdx.x < o) sm[threadIdx.x] = fmaxf(sm[threadIdx.x], sm[threadIdx.x+o]);
    __syncthreads();
  }
  if (threadIdx.x == 0) g_mpart[slot0 + blockIdx.x] = sm[0];
}
__global__ void k_amax_fin(){
  __shared__ float sm[1024];
  const int t = threadIdx.x;
  const int base[4] = {0, 1024, 1280, 1536};
  const int cnt[4]  = {1024, 256, 256, 256};
#pragma unroll
  for (int r = 0; r < 4; r++){
    float m = 0.f;
    for (int i = t; i < cnt[r]; i += 1024) m = fmaxf(m, g_mpart[base[r]+i]);
    sm[t] = m;
    __syncthreads();
    for (int o = 512; o; o >>= 1){
      if (t < o) sm[t] = fmaxf(sm[t], sm[t+o]);
      __syncthreads();
    }
    if (t == 0) g_scales[r] = sm[0];
    __syncthreads();
  }
}
__global__ void k_scale_gelu(){
  __shared__ float sm[1024];
  const int t = threadIdx.x;
  float m = 0.f;
  for (int i = t; i < 3072; i += 1024) m = fmaxf(m, g_mpart[1792+i]);
  sm[t] = m;
  __syncthreads();
  for (int o = 512; o; o >>= 1){
    if (t < o) sm[t] = fmaxf(sm[t], sm[t+o]);
    __syncthreads();
  }
  if (t == 0) g_scales[4] = sm[0];
}
__global__ void k_scale_kt(){
  __shared__ float sm[512];
  const int t = threadIdx.x;
  sm[t] = g_mpart[4864 + t];
  __syncthreads();
  for (int o = 256; o; o >>= 1){
    if (t < o) sm[t] = fmaxf(sm[t], sm[t+o]);
    __syncthreads();
  }
  if (t == 0) g_scales[5] = sm[0];
}

// ===========================================================================
// Quantization kernels
// ===========================================================================
__global__ void k_quantW(const float* __restrict__ in, int8_t* __restrict__ q1,
                         int8_t* __restrict__ q2, int sidx, int n4){
  int i = blockIdx.x * blockDim.x + threadIdx.x;
  if (i >= n4) return;
  const float qs = 127.0f / g_scales[sidx];
  float4 v = ((const float4*)in)[i];
  int8_t a1,a2,b1,b2,c1,c2,d1,d2;
  quant2(v.x, qs, a1, a2); quant2(v.y, qs, b1, b2);
  quant2(v.z, qs, c1, c2); quant2(v.w, qs, d1, d2);
  ((uchar4*)q1)[i] = make_uchar4((uint8_t)a1,(uint8_t)b1,(uint8_t)c1,(uint8_t)d1);
  ((uchar4*)q2)[i] = make_uchar4((uint8_t)a2,(uint8_t)b2,(uint8_t)c2,(uint8_t)d2);
}
__global__ void k_quant_gelu(int n4){
  int i = blockIdx.x * blockDim.x + threadIdx.x;
  if (i >= n4) return;
  const float qs = 127.0f / g_scales[4];
  float4 v = ((const float4*)g_gelu)[i];
  int8_t a1,a2,b1,b2,c1,c2,d1,d2;
  quant2(v.x, qs, a1, a2); quant2(v.y, qs, b1, b2);
  quant2(v.z, qs, c1, c2); quant2(v.w, qs, d1, d2);
  ((uchar4*)g_xq1)[i] = make_uchar4((uint8_t)a1,(uint8_t)b1,(uint8_t)c1,(uint8_t)d1);
  ((uchar4*)g_xq2)[i] = make_uchar4((uint8_t)a2,(uint8_t)b2,(uint8_t)c2,(uint8_t)d2);
}
__global__ void k_quant_kt(int n4){
  int i = blockIdx.x * blockDim.x + threadIdx.x;
  if (i >= n4) return;
  const float qs = 127.0f / g_scales[5];
  float4 v = ((const float4*)g_ktf)[i];
  int8_t a1,a2,b1,b2,c1,c2,d1,d2;
  quant2(v.x, qs, a1, a2); quant2(v.y, qs, b1, b2);
  quant2(v.z, qs, c1, c2); quant2(v.w, qs, d1, d2);
  ((uchar4*)g_ktq1)[i] = make_uchar4((uint8_t)a1,(uint8_t)b1,(uint8_t)c1,(uint8_t)d1);
  ((uchar4*)g_ktq2)[i] = make_uchar4((uint8_t)a2,(uint8_t)b2,(uint8_t)c2,(uint8_t)d2);
}

// ===========================================================================
// x transpose: fp32 [B,N,C] -> int8 q1/q2 planes, [b*C+c][n]
// ===========================================================================
__global__ void k_transpose_x(const float* __restrict__ in){
  __shared__ float t[32][33];
  const size_t zo = (size_t)blockIdx.z * C_ * N_;
  const int i0 = blockIdx.y*32, j0 = blockIdx.x*32;
  const float* ip = in + zo;
  const float qs = 127.0f / g_scales[0];
#pragma unroll
  for (int k = threadIdx.y; k < 32; k += 8)
    t[k][threadIdx.x] = ip[(size_t)(i0+k)*C_ + j0 + threadIdx.x];
  __syncthreads();
#pragma unroll
  for (int k = threadIdx.y; k < 32; k += 8){
    const size_t o = zo + (size_t)(j0+k)*N_ + i0 + threadIdx.x;
    int8_t q1, q2;
    quant2(t[threadIdx.x][k], qs, q1, q2);
    g_xq1[o] = q1;
    g_xq2[o] = q2;
  }
}

// ===========================================================================
// int8 IMMA mainloop: C128x128 over nch*32 K, 2-chunk decomposition.
// accM += a1*b1 ; accC += a1*b2 + a2*b1
// ===========================================================================
#define RSBI 48
#define TILE_I (128*RSBI)            // 6144 B
#define STAGE_I (4*TILE_I)           // 24576 B
#define GSMEM_I (3*STAGE_I)          // 73728 B

__device__ __forceinline__ void gemm_main_i8(
    uint32_t sb, int tid,
    const int8_t* __restrict__ A1, const int8_t* __restrict__ A2, int lda,
    const int8_t* __restrict__ B1, const int8_t* __restrict__ B2, int ldb,
    int nch, int (*accM)[4], int (*accC)[4]){
  const int t64  = tid & 63;
  const int tile = tid >> 6;                 // 0:A1 1:A2 2:B1 3:B2
  const int8_t* gsrc; int ld;
  if      (tile == 0){ gsrc = A1; ld = lda; }
  else if (tile == 1){ gsrc = A2; ld = lda; }
  else if (tile == 2){ gsrc = B1; ld = ldb; }
  else               { gsrc = B2; ld = ldb; }

  auto issue = [&](int ch, int stage){
    const int k0 = ch * 32;
    const uint32_t sbase = sb + stage * STAGE_I + tile * TILE_I;
#pragma unroll
    for (int j = 0; j < 4; j++){
      const int seg = t64 + 64 * j;
      const int row = seg >> 1, s = seg & 1;
      CP_ASYNC16(sbase + row * RSBI + s * 16,
                 (const char*)(gsrc + (size_t)row * ld + k0) + s * 16);
    }
    CP_COMMIT();
  };

  issue(0, 0);
  issue(1, 1);

  const int wid = tid >> 5, lane = tid & 31;
  const int wm = (wid >> 2) * 64, wn = (wid & 3) * 32;
  const int a_row = lane & 15, a_kb = (lane >> 4) * 16;
  const int b_row = (lane & 7) + ((lane >> 4) * 8);
  const int b_kb  = ((lane >> 3) & 1) * 16;

  for (int ch = 0; ch < nch; ch++){
    CP_WAIT1();
    __syncthreads();
    if (ch + 2 < nch) issue(ch + 2, (ch + 2) % 3);
    else CP_COMMIT();

    const uint32_t st = sb + (ch % 3) * STAGE_I;
    const uint32_t a1T = st,            a2T = st + TILE_I;
    const uint32_t b1T = st + 2*TILE_I, b2T = st + 3*TILE_I;

    uint32_t a1[4][4], a2[4][4], b1[4][2], b2[4][2];
#pragma unroll
    for (int mi = 0; mi < 4; mi++){
      const uint32_t ro = (uint32_t)(wm + mi*16 + a_row) * RSBI + a_kb;
      ldmx4(a1[mi], a1T + ro);
      ldmx4(a2[mi], a2T + ro);
    }
#pragma unroll
    for (int nh = 0; nh < 2; nh++){
      const uint32_t ro = (uint32_t)(wn + nh*16 + b_row) * RSBI + b_kb;
      uint32_t r[4];
      ldmx4(r, b1T + ro);
      b1[nh*2+0][0]=r[0]; b1[nh*2+0][1]=r[1]; b1[nh*2+1][0]=r[2]; b1[nh*2+1][1]=r[3];
      ldmx4(r, b2T + ro);
      b2[nh*2+0][0]=r[0]; b2[nh*2+0][1]=r[1]; b2[nh*2+1][0]=r[2]; b2[nh*2+1][1]=r[3];
    }
#pragma unroll
    for (int mi = 0; mi < 4; mi++)
#pragma unroll
      for (int ni = 0; ni < 4; ni++){
        imma16832(accM[4*mi+ni], a1[mi], b1[ni]);
        imma16832(accC[4*mi+ni], a1[mi], b2[ni]);
        imma16832(accC[4*mi+ni], a2[mi], b1[ni]);
      }
  }
  CP_WAIT0();
  __syncthreads();
}

// ===========================================================================
// bf16 HMMA mainloop (for kt GEMM)
// ===========================================================================
#define KC 32
#define RSB 80
#define TILE_SB (128*RSB)
#define STAGE_B (4*TILE_SB)
#define GSMEM (3*STAGE_B)            // 122880 B

__device__ __forceinline__ void gemm_main(
    uint32_t sb, int tid,
    const __nv_bfloat16* __restrict__ Ah, const __nv_bfloat16* __restrict__ Al, int lda,
    const __nv_bfloat16* __restrict__ Bh, const __nv_bfloat16* __restrict__ Bl, int ldb,
    int nch, float (*acc)[4]){
  const int t64  = tid & 63;
  const int tile = tid >> 6;
  const __nv_bfloat16* gsrc; int ld;
  if      (tile == 0){ gsrc = Ah; ld = lda; }
  else if (tile == 1){ gsrc = Al; ld = lda; }
  else if (tile == 2){ gsrc = Bh; ld = ldb; }
  else               { gsrc = Bl; ld = ldb; }

  auto issue = [&](int ch, int stage){
    const int k0 = ch * KC;
    const uint32_t sbase = sb + stage * STAGE_B + tile * TILE_SB;
#pragma unroll
    for (int j = 0; j < 8; j++){
      const int seg = t64 + 64 * j;
      const int row = seg >> 2, s4 = seg & 3;
      CP_ASYNC16(sbase + row * RSB + s4 * 16,
                 (const char*)(gsrc + (size_t)row * ld + k0) + s4 * 16);
    }
    CP_COMMIT();
  };

  issue(0, 0);
  issue(1, 1);

  const int wid = tid >> 5, lane = tid & 31;
  const int wm = (wid >> 2) * 64, wn = (wid & 3) * 32;
  const int a_row = lane % 16, a_k8 = (lane >> 4) * 8;
  const int b_row = (lane & 7) + ((lane >> 4) * 8);
  const int b_k8  = ((lane >> 3) & 1) * 8;

  for (int ch = 0; ch < nch; ch++){
    CP_WAIT1();
    __syncthreads();
    if (ch + 2 < nch) issue(ch + 2, (ch + 2) % 3);
    else CP_COMMIT();

    const uint32_t st = sb + (ch % 3) * STAGE_B;
    const uint32_t aH = st,             aL = st + TILE_SB;
    const uint32_t bH = st + 2*TILE_SB, bL = st + 3*TILE_SB;

#pragma unroll
    for (int kk = 0; kk < 2; kk++){
      uint32_t ah[4][4], al[4][4], bh[4][2], bl[4][2];
      const int kc = kk * 32 + a_k8 * 2;
#pragma unroll
      for (int mi = 0; mi < 4; mi++){
        const uint32_t ro = (uint32_t)(wm + mi*16 + a_row) * RSB + kc;
        ldmx4(ah[mi], aH + ro);
        ldmx4(al[mi], aL + ro);
      }
#pragma unroll
      for (int nh = 0; nh < 2; nh++){
        const uint32_t ro = (uint32_t)(wn + nh*16 + b_row) * RSB + kk*32 + b_k8*2;
        uint32_t r[4];
        ldmx4(r, bH + ro);
        bh[nh*2+0][0]=r[0]; bh[nh*2+0][1]=r[1]; bh[nh*2+1][0]=r[2]; bh[nh*2+1][1]=r[3];
        ldmx4(r, bL + ro);
        bl[nh*2+0][0]=r[0]; bl[nh*2+0][1]=r[1]; bl[nh*2+1][0]=r[2]; bl[nh*2+1][1]=r[3];
      }
#pragma unroll
      for (int mi = 0; mi < 4; mi++)
#pragma unroll
        for (int ni = 0; ni < 4; ni++){
          mma16816(acc[4*mi+ni], ah[mi], bh[ni]);
          mma16816(acc[4*mi+ni], ah[mi], bl[ni]);
          mma16816(acc[4*mi+ni], al[mi], bh[ni]);
        }
    }
  }
  CP_WAIT0();
  __syncthreads();
}

// Transposed bf16 hi/lo epilogue via fp32 smem bounce.
#define TS 130
__device__ __forceinline__ void epi_T_bf16(
    float (*acc)[4], char* smem, int tid, float f,
    __nv_bfloat16* dsth, __nv_bfloat16* dstl, int ldd){
  float* T = (float*)smem;
  const int wid = tid >> 5, lane = tid & 31;
  const int wm = (wid >> 2) * 64, wn = (wid & 3) * 32;
  const int tr = lane >> 2, tc = (lane & 3) * 2;
#pragma unroll
  for (int mi = 0; mi < 4; mi++)
#pragma unroll
    for (int ni = 0; ni < 4; ni++){
      float* a = acc[4*mi+ni];
      const int r = wm + mi*16 + tr, c = wn + ni*8 + tc;
      T[r*TS + c]     = a[0]*f; T[r*TS + c + 1]     = a[1]*f;
      T[(r+8)*TS + c] = a[2]*f; T[(r+8)*TS + c + 1] = a[3]*f;
    }
  __syncthreads();
#pragma unroll
  for (int it = 0; it < 4; it++){
    const int j = it*32 + (tid >> 3);
    const int mbase = (tid & 7) * 2;
#pragma unroll
    for (int p = 0; p < 8; p++){
      const int m = mbase + p*16;
      float f0 = T[m*TS + j], f1 = T[(m+1)*TS + j];
      uint32_t h, l; split2(f0, f1, h, l);
      *(uint32_t*)(dsth + (size_t)j*ldd + m) = h;
      *(uint32_t*)(dstl + (size_t)j*ldd + m) = l;
    }
  }
  __syncthreads();
}

// ===========================================================================
// kv GEMM (int8): C = xt @ W^T -> transposed bf16 hi/lo (+ norm partials)
// ===========================================================================
__global__ void __launch_bounds__(256,1)
k_gemm_kv_i8(const int8_t* __restrict__ W1, const int8_t* __restrict__ W2,
             int wsidx,
             __nv_bfloat16* __restrict__ dsth, __nv_bfloat16* __restrict__ dstl,
             int with_norm){
  extern __shared__ __align__(128) char smem[];
  __shared__ float red[8];
  const uint32_t sb = smem_u32(smem);
  const int tid = threadIdx.x;
  const int n0 = blockIdx.x * 128, m0 = blockIdx.y * 128;
  int accM[16][4] = {}, accC[16][4] = {};
  gemm_main_i8(sb, tid, g_xq1 + (size_t)m0*N_, g_xq2 + (size_t)m0*N_, N_,
               W1 + (size_t)n0*N_, W2 + (size_t)n0*N_, N_, 32, accM, accC);
  const float f = g_scales[0] * g_scales[wsidx] / 16129.0f;
  float facc[16][4];
#pragma unroll
  for (int q = 0; q < 16; q++)
#pragma unroll
    for (int e = 0; e < 4; e++)
      facc[q][e] = f * ((float)accM[q][e] + (float)accC[q][e] * (1.0f/254.0f));
  if (with_norm){
    float s2 = 0.f;
#pragma unroll
    for (int q = 0; q < 16; q++)
#pragma unroll
      for (int e = 0; e < 4; e++) s2 += facc[q][e]*facc[q][e];
#pragma unroll
    for (int o = 16; o; o >>= 1) s2 += __shfl_down_sync(0xffffffffu, s2, o);
    if ((tid & 31) == 0) red[tid >> 5] = s2;
    __syncthreads();
    if (tid == 0){
      float t = 0.f;
#pragma unroll
      for (int w = 0; w < 8; w++) t += red[w];
      g_part[blockIdx.y * 8 + blockIdx.x] = t;
    }
  }
  const int b = m0 / C_, c0 = m0 % C_;
  const size_t off = ((size_t)b*N_ + n0) * C_ + c0;
  epi_T_bf16(facc, smem, tid, 1.f, dsth + off, dstl + off, C_);
}

__global__ void k_reduce(){
  __shared__ float sh[1024];
  const int t = threadIdx.x;
  sh[t] = g_part[t] + g_part[t+1024] + g_part[t+2048];
  __syncthreads();
  for (int o = 512; o; o >>= 1){
    if (t < o) sh[t] += sh[t+o];
    __syncthreads();
  }
  if (t == 0) g_norm2 = sh[0];
}

// ===========================================================================
// kt GEMM (bf16): kt[n][m] = sum_c kT[n][c]*vT[m][c]; scaled;
// store ktT[m][n] fp32 + amax partials
// ===========================================================================
__global__ void __launch_bounds__(256,1)
k_gemm_kt(const float* __restrict__ scale){
  extern __shared__ __align__(128) char smem[];
  __shared__ float redm[8];
  const uint32_t sb = smem_u32(smem);
  const int tid = threadIdx.x;
  const int bh = blockIdx.x, b = bh >> 3, h = bh & 7;
  const size_t base = ((size_t)b*N_ + h*D_) * C_;
  float acc[16][4] = {};
  gemm_main(sb, tid, g_kTh + base, g_kTl + base, C_,
            g_vTh + base, g_vTl + base, C_, 24, acc);
  const float nrm = sqrtf(g_norm2) + EPSF;
  const float f = scale[h] / (nrm*nrm);
  // scale in place + amax
  float mx = 0.f;
#pragma unroll
  for (int q = 0; q < 16; q++)
#pragma unroll
    for (int e = 0; e < 4; e++){
      acc[q][e] *= f;
      mx = fmaxf(mx, fabsf(acc[q][e]));
    }
#pragma unroll
  for (int o = 16; o; o >>= 1) mx = fmaxf(mx, __shfl_down_sync(0xffffffffu, mx, o));
  const int wid = tid >> 5, lane = tid & 31;
  if (lane == 0) redm[wid] = mx;
  // transposed fp32 write via smem bounce
  float* T = (float*)smem;
  const int wm = (wid >> 2) * 64, wn = (wid & 3) * 32;
  const int tr = lane >> 2, tc = (lane & 3) * 2;
#pragma unroll
  for (int mi = 0; mi < 4; mi++)
#pragma unroll
    for (int ni = 0; ni < 4; ni++){
      float* a = acc[4*mi+ni];
      const int r = wm + mi*16 + tr, c = wn + ni*8 + tc;
      T[r*TS + c]     = a[0]; T[r*TS + c + 1]     = a[1];
      T[(r+8)*TS + c] = a[2]; T[(r+8)*TS + c + 1] = a[3];
    }
  __syncthreads();
  float* dst = g_ktf + (size_t)bh*D_*D_;
#pragma unroll
  for (int it = 0; it < 4; it++){
    const int j = it*32 + (tid >> 3);
    const int mbase = (tid & 7) * 2;
#pragma unroll
    for (int p = 0; p < 8; p++){
      const int m = mbase + p*16;
      *(float2*)(dst + (size_t)j*D_ + m) = make_float2(T[m*TS + j], T[(m+1)*TS + j]);
    }
  }
  if (tid == 0){
    float t = 0.f;
#pragma unroll
    for (int w = 0; w < 8; w++) t = fmaxf(t, redm[w]);
    g_mpart[4864 + bh] = t;
  }
}

// ===========================================================================
// out GEMM (int8): out1 = q @ kt -> exact gelu fp32 + per-block amax partial
// ===========================================================================
__global__ void __launch_bounds__(256,1)
k_gemm_out_i8(){
  extern __shared__ __align__(128) char smem[];
  __shared__ float redm[8];
  const uint32_t sb = smem_u32(smem);
  const int tid = threadIdx.x;
  const int c0 = blockIdx.x * 128;
  const int bh = blockIdx.y, b = bh >> 3, h = bh & 7;
  const size_t Abase = ((size_t)b*C_ + c0) * N_ + (size_t)h*D_;
  int accM[16][4] = {}, accC[16][4] = {};
  gemm_main_i8(sb, tid, g_xq1 + Abase, g_xq2 + Abase, N_,
               g_ktq1 + (size_t)bh*D_*D_, g_ktq2 + (size_t)bh*D_*D_, D_, 4,
               accM, accC);
  const float f = g_scales[0] * g_scales[5] / 16129.0f;
  const int wid = tid >> 5, lane = tid & 31;
  const int wm = (wid >> 2) * 64, wn = (wid & 3) * 32;
  const int tr = lane >> 2, tc = (lane & 3) * 2;
  float mx = 0.f;
#pragma unroll
  for (int mi = 0; mi < 4; mi++)
#pragma unroll
    for (int ni = 0; ni < 4; ni++){
      int* aM = accM[4*mi+ni];
      int* aC = accC[4*mi+ni];
      const int col = wn + ni*8 + tc;
      const size_t r0 = Abase + (size_t)(wm + mi*16 + tr) * N_ + col;
      const size_t r1 = r0 + 8*N_;
      float v0 = f*((float)aM[0] + (float)aC[0]*(1.0f/254.0f));
      float v1 = f*((float)aM[1] + (float)aC[1]*(1.0f/254.0f));
      float v2 = f*((float)aM[2] + (float)aC[2]*(1.0f/254.0f));
      float v3 = f*((float)aM[3] + (float)aC[3]*(1.0f/254.0f));
      float g0 = gelu_exact(v0), g1 = gelu_exact(v1);
      float g2 = gelu_exact(v2), g3 = gelu_exact(v3);
      *(float2*)(g_gelu + r0) = make_float2(g0, g1);
      *(float2*)(g_gelu + r1) = make_float2(g2, g3);
      mx = fmaxf(mx, fmaxf(fmaxf(fabsf(g0), fabsf(g1)), fmaxf(fabsf(g2), fabsf(g3))));
    }
#pragma unroll
  for (int o = 16; o; o >>= 1) mx = fmaxf(mx, __shfl_down_sync(0xffffffffu, mx, o));
  if (lane == 0) redm[wid] = mx;
  __syncthreads();
  if (tid == 0){
    float t = 0.f;
#pragma unroll
    for (int w = 0; w < 8; w++) t = fmaxf(t, redm[w]);
    g_mpart[1792 + blockIdx.y*6 + blockIdx.x] = t;
  }
}

// ===========================================================================
// proj GEMM (int8): out2 = gelu @ proj_w^T + pb; transposed write -> [B,N,C]
// ===========================================================================
__global__ void __launch_bounds__(256,1)
k_gemm_proj_i8(const int8_t* __restrict__ W1, const int8_t* __restrict__ W2,
               const float* __restrict__ pb, float* __restrict__ out){
  extern __shared__ __align__(128) char smem[];
  const uint32_t sb = smem_u32(smem);
  const int tid = threadIdx.x;
  const int n0 = blockIdx.x * 128, m0 = blockIdx.y * 128;
  int accM[16][4] = {}, accC[16][4] = {};
  gemm_main_i8(sb, tid, g_xq1 + (size_t)m0*N_, g_xq2 + (size_t)m0*N_, N_,
               W1 + (size_t)n0*N_, W2 + (size_t)n0*N_, N_, 32, accM, accC);
  const float f = g_scales[4] * g_scales[3] / 16129.0f;
  const int wid = tid >> 5, lane = tid & 31;
  const int wm = (wid >> 2) * 64, wn = (wid & 3) * 32;
  const int tr = lane >> 2, tc = (lane & 3) * 2;
  float* T = (float*)smem;
#pragma unroll
  for (int mi = 0; mi < 4; mi++)
#pragma unroll
    for (int ni = 0; ni < 4; ni++){
      int* aM = accM[4*mi+ni];
      int* aC = accC[4*mi+ni];
      const int c = wn + ni*8 + tc;
      const float2 bv = *(const float2*)(pb + n0 + c);
      const int r = wm + mi*16 + tr;
      float v0 = f*((float)aM[0] + (float)aC[0]*(1.0f/254.0f)) + bv.x;
      float v1 = f*((float)aM[1] + (float)aC[1]*(1.0f/254.0f)) + bv.y;
      float v2 = f*((float)aM[2] + (float)aC[2]*(1.0f/254.0f)) + bv.x;
      float v3 = f*((float)aM[3] + (float)aC[3]*(1.0f/254.0f)) + bv.y;
      T[r*TS + c]     = v0; T[r*TS + c + 1]     = v1;
      T[(r+8)*TS + c] = v2; T[(r+8)*TS + c + 1] = v3;
    }
  __syncthreads();
  const int b = m0 / C_, c0 = m0 % C_;
  float* dst = out + ((size_t)b*N_ + n0) * C_ + c0;
#pragma unroll
  for (int it = 0; it < 4; it++){
    const int j = it*32 + (tid >> 3);
    const int mbase = (tid & 7) * 2;
#pragma unroll
    for (int p = 0; p < 8; p++){
      const int m = mbase + p*16;
      *(float2*)(dst + (size_t)j*C_ + m) = make_float2(T[m*TS + j], T[(m+1)*TS + j]);
    }
  }
}

// ---------------------------------------------------------------------------
// Launch: graph-capturable, allocation-free, deterministic.
// ---------------------------------------------------------------------------
extern "C" void kernel_launch(void* const* d_in, const int* in_sizes, int n_in,
                              void* d_out, int out_size){
  const float* x   = (const float*)d_in[0];
  const float* qkw = (const float*)d_in[1];
  const float* vw  = (const float*)d_in[2];
  const float* pw  = (const float*)d_in[3];
  const float* pb  = (const float*)d_in[4];
  const float* sc  = (const float*)d_in[5];
  float* out = (float*)d_out;

  int8_t *p_wq1=nullptr, *p_wq2=nullptr;
  __nv_bfloat16 *p_kTh=nullptr, *p_kTl=nullptr, *p_vTh=nullptr, *p_vTl=nullptr;
  cudaGetSymbolAddress((void**)&p_wq1, g_wq1);
  cudaGetSymbolAddress((void**)&p_wq2, g_wq2);
  cudaGetSymbolAddress((void**)&p_kTh, g_kTh);
  cudaGetSymbolAddress((void**)&p_kTl, g_kTl);
  cudaGetSymbolAddress((void**)&p_vTh, g_vTh);
  cudaGetSymbolAddress((void**)&p_vTl, g_vTl);

  cudaFuncSetAttribute(k_gemm_kv_i8,  cudaFuncAttributeMaxDynamicSharedMemorySize, GSMEM_I);
  cudaFuncSetAttribute(k_gemm_out_i8, cudaFuncAttributeMaxDynamicSharedMemorySize, GSMEM_I);
  cudaFuncSetAttribute(k_gemm_proj_i8,cudaFuncAttributeMaxDynamicSharedMemorySize, GSMEM_I);
  cudaFuncSetAttribute(k_gemm_kt,  cudaFuncAttributeMaxDynamicSharedMemorySize, GSMEM);

  const size_t W2 = (size_t)N_*N_;

  // amax scales (exact, deterministic)
  k_amax<<<1024, 256>>>(x,   ROWS_*N_, 0);
  k_amax<<<256, 256>>>(qkw, W2, 1024);
  k_amax<<<256, 256>>>(vw,  W2, 1280);
  k_amax<<<256, 256>>>(pw,  W2, 1536);
  k_amax_fin<<<1, 1024>>>();

  // x -> xt int8 q1/q2; weight quantization
  k_transpose_x<<<dim3(24,32,64), dim3(32,8)>>>(x);
  k_quantW<<<1024, 256>>>(qkw, p_wq1,      p_wq2,      1, (int)(W2/4));
  k_quantW<<<1024, 256>>>(vw,  p_wq1+W2,   p_wq2+W2,   2, (int)(W2/4));
  k_quantW<<<1024, 256>>>(pw,  p_wq1+2*W2, p_wq2+2*W2, 3, (int)(W2/4));

  // k -> kT (+ norm partials), v -> vT  (int8 IMMA)
  k_gemm_kv_i8<<<dim3(8,384), 256, GSMEM_I>>>(p_wq1,    p_wq2,    1, p_kTh, p_kTl, 1);
  k_gemm_kv_i8<<<dim3(8,384), 256, GSMEM_I>>>(p_wq1+W2, p_wq2+W2, 2, p_vTh, p_vTl, 0);
  k_reduce<<<1,1024>>>();

  // kt (bf16) -> ktT fp32 + amax; quantize kt; out (int8) -> gelu + amax
  k_gemm_kt<<<512, 256, GSMEM>>>(sc);
  k_scale_kt<<<1, 512>>>();
  k_quant_kt<<<8192, 256>>>((int)(KTN_/4));
  k_gemm_out_i8<<<dim3(6,512), 256, GSMEM_I>>>();
  k_scale_gelu<<<1, 1024>>>();
  k_quant_gelu<<<49152, 256>>>((int)(ROWS_*N_/4));

  // proj (int8 IMMA) + bias, transposed write direct to [B,N,C]
  k_gemm_proj_i8<<<dim3(8,384), 256, GSMEM_I>>>(p_wq1+2*W2, p_wq2+2*W2, pb, out);
}

// round 14
// speedup vs baseline: 1.3738x; 1.0337x over previous
#include <cuda_runtime.h>
#include <cuda_bf16.h>
#include <math.h>
#include <stdint.h>

// Problem constants: B=64, N=1024, C=768, heads=8, d=128
#define B_ 64
#define N_ 1024
#define C_ 768
#define H_ 8
#define D_ 128
#define EPSF 1e-8f
#define ROWS_ ((size_t)B_*C_)   // 49152
#define KTN_ ((size_t)B_*H_*D_*D_)   // 8388608

// ---------------------------------------------------------------------------
// Scratch (device globals — allocation-free rule)
// ---------------------------------------------------------------------------
__device__ int8_t g_xq1[ROWS_*N_];         // xt int8 chunk1
__device__ int8_t g_xq2[ROWS_*N_];         // xt int8 chunk2
__device__ int8_t g_wq1[3][(size_t)N_*N_];
__device__ int8_t g_wq2[3][(size_t)N_*N_];
__device__ __nv_bfloat16 g_kTh[(size_t)B_*N_*C_];  // kT [b][n][c] hi
__device__ __nv_bfloat16 g_kTl[(size_t)B_*N_*C_];
__device__ __nv_bfloat16 g_vTh[(size_t)B_*N_*C_];
__device__ __nv_bfloat16 g_vTl[(size_t)B_*N_*C_];
__device__ float  g_ktf[KTN_];             // ktT fp32 [bh][m][n]
__device__ int8_t g_ktq1[KTN_];            // ktT int8 chunk1
__device__ int8_t g_ktq2[KTN_];            // ktT int8 chunk2
__device__ float g_gelu[ROWS_*N_];         // fp32 gelu output (proj input)
__device__ float g_part[3072];
__device__ float g_norm2;
__device__ float g_mpart[6144];            // amax partials
__device__ float g_scales[8];              // 0:x 1:qkw 2:vw 3:pw 4:gelu 5:kt

// ---------------------------------------------------------------------------
// Helpers
// ---------------------------------------------------------------------------
__device__ __forceinline__ uint32_t smem_u32(const void* p){
  uint32_t a;
  asm("{ .reg .u64 t; cvta.to.shared.u64 t, %1; cvt.u32.u64 %0, t; }" : "=r"(a) : "l"(p));
  return a;
}
__device__ __forceinline__ void split2(float fx, float fy, uint32_t& hi, uint32_t& lo){
  uint32_t h;
  asm("cvt.rn.bf16x2.f32 %0, %1, %2;" : "=r"(h) : "f"(fy), "f"(fx));
  float hx = __uint_as_float(h << 16);
  float hy = __uint_as_float(h & 0xffff0000u);
  float lx = fx - hx, ly = fy - hy;
  asm("cvt.rn.bf16x2.f32 %0, %1, %2;" : "=r"(lo) : "f"(ly), "f"(lx));
  hi = h;
}
__device__ __forceinline__ float gelu_exact(float x){
  return 0.5f * x * (1.0f + erff(x * 0.7071067811865475f));
}
// int8 2-chunk quantization: x ~= (S/127)*(q1 + q2/254)
__device__ __forceinline__ void quant2(float v, float qs, int8_t& q1, int8_t& q2){
  float q = v * qs;
  float a1 = rintf(q);
  q1 = (int8_t)(int)a1;
  q2 = (int8_t)(int)rintf((q - a1) * 254.0f);
}

#define CP_ASYNC16(s, g) \
  asm volatile("cp.async.cg.shared.global [%0], [%1], 16;" :: "r"(s), "l"(g) : "memory")
#define CP_COMMIT() asm volatile("cp.async.commit_group;" ::: "memory")
#define CP_WAIT1()  asm volatile("cp.async.wait_group 1;" ::: "memory")
#define CP_WAIT0()  asm volatile("cp.async.wait_group 0;" ::: "memory")

__device__ __forceinline__ void ldmx4(uint32_t* r, uint32_t addr){
  asm volatile("ldmatrix.sync.aligned.m8n8.x4.shared.b16 {%0,%1,%2,%3}, [%4];"
    : "=r"(r[0]), "=r"(r[1]), "=r"(r[2]), "=r"(r[3]) : "r"(addr));
}
__device__ __forceinline__ void mma16816(float* c, const uint32_t* a, const uint32_t* b){
  asm volatile("mma.sync.aligned.m16n8k16.row.col.f32.bf16.bf16.f32 "
    "{%0,%1,%2,%3},{%4,%5,%6,%7},{%8,%9},{%0,%1,%2,%3};"
    : "+f"(c[0]), "+f"(c[1]), "+f"(c[2]), "+f"(c[3])
    : "r"(a[0]), "r"(a[1]), "r"(a[2]), "r"(a[3]), "r"(b[0]), "r"(b[1]));
}
__device__ __forceinline__ void imma16832(int* c, const uint32_t* a, const uint32_t* b){
  asm volatile("mma.sync.aligned.m16n8k32.row.col.s32.s8.s8.s32 "
    "{%0,%1,%2,%3},{%4,%5,%6,%7},{%8,%9},{%0,%1,%2,%3};"
    : "+r"(c[0]), "+r"(c[1]), "+r"(c[2]), "+r"(c[3])
    : "r"(a[0]), "r"(a[1]), "r"(a[2]), "r"(a[3]), "r"(b[0]), "r"(b[1]));
}

// ===========================================================================
// Fused amax over x + 3 weights (float4 streaming; exact max, deterministic)
// grid (512, 4): y=0 -> x, y=1..3 -> weights. Partials at [y*512 + x].
// ===========================================================================
__global__ void k_amax_all(const float4* __restrict__ x4,
                           const float4* __restrict__ w1,
                           const float4* __restrict__ w2,
                           const float4* __restrict__ w3){
  __shared__ float sm[256];
  const int y = blockIdx.y;
  const float4* src; int n4;
  if      (y == 0){ src = x4; n4 = (int)(ROWS_*N_/4); }
  else if (y == 1){ src = w1; n4 = (int)((size_t)N_*N_/4); }
  else if (y == 2){ src = w2; n4 = (int)((size_t)N_*N_/4); }
  else            { src = w3; n4 = (int)((size_t)N_*N_/4); }
  float m = 0.f;
  for (int i = blockIdx.x*256 + threadIdx.x; i < n4; i += 512*256){
    float4 v = src[i];
    m = fmaxf(m, fmaxf(fmaxf(fabsf(v.x), fabsf(v.y)), fmaxf(fabsf(v.z), fabsf(v.w))));
  }
  sm[threadIdx.x] = m;
  __syncthreads();
  for (int o = 128; o; o >>= 1){
    if (threadIdx.x < o) sm[threadIdx.x] = fmaxf(sm[threadIdx.x], sm[threadIdx.x+o]);
    __syncthreads();
  }
  if (threadIdx.x == 0) g_mpart[y*512 + blockIdx.x] = sm[0];
}
__global__ void k_amax_fin(){
  __shared__ float sm[512];
  const int t = threadIdx.x;
#pragma unroll
  for (int r = 0; r < 4; r++){
    sm[t] = g_mpart[r*512 + t];
    __syncthreads();
    for (int o = 256; o; o >>= 1){
      if (t < o) sm[t] = fmaxf(sm[t], sm[t+o]);
      __syncthreads();
    }
    if (t == 0) g_scales[r] = sm[0];
    __syncthreads();
  }
}
__global__ void k_scale_gelu(){
  __shared__ float sm[1024];
  const int t = threadIdx.x;
  float m = 0.f;
  for (int i = t; i < 3072; i += 1024) m = fmaxf(m, g_mpart[2048+i]);
  sm[t] = m;
  __syncthreads();
  for (int o = 512; o; o >>= 1){
    if (t < o) sm[t] = fmaxf(sm[t], sm[t+o]);
    __syncthreads();
  }
  if (t == 0) g_scales[4] = sm[0];
}
__global__ void k_scale_kt(){
  __shared__ float sm[512];
  const int t = threadIdx.x;
  sm[t] = g_mpart[5120 + t];
  __syncthreads();
  for (int o = 256; o; o >>= 1){
    if (t < o) sm[t] = fmaxf(sm[t], sm[t+o]);
    __syncthreads();
  }
  if (t == 0) g_scales[5] = sm[0];
}

// ===========================================================================
// Quantization kernels
// ===========================================================================
__global__ void k_quantW(const float* __restrict__ in, int8_t* __restrict__ q1,
                         int8_t* __restrict__ q2, int sidx, int n4){
  int i = blockIdx.x * blockDim.x + threadIdx.x;
  if (i >= n4) return;
  const float qs = 127.0f / g_scales[sidx];
  float4 v = ((const float4*)in)[i];
  int8_t a1,a2,b1,b2,c1,c2,d1,d2;
  quant2(v.x, qs, a1, a2); quant2(v.y, qs, b1, b2);
  quant2(v.z, qs, c1, c2); quant2(v.w, qs, d1, d2);
  ((uchar4*)q1)[i] = make_uchar4((uint8_t)a1,(uint8_t)b1,(uint8_t)c1,(uint8_t)d1);
  ((uchar4*)q2)[i] = make_uchar4((uint8_t)a2,(uint8_t)b2,(uint8_t)c2,(uint8_t)d2);
}
__global__ void k_quant_gelu(int n4){
  int i = blockIdx.x * blockDim.x + threadIdx.x;
  if (i >= n4) return;
  const float qs = 127.0f / g_scales[4];
  float4 v = ((const float4*)g_gelu)[i];
  int8_t a1,a2,b1,b2,c1,c2,d1,d2;
  quant2(v.x, qs, a1, a2); quant2(v.y, qs, b1, b2);
  quant2(v.z, qs, c1, c2); quant2(v.w, qs, d1, d2);
  ((uchar4*)g_xq1)[i] = make_uchar4((uint8_t)a1,(uint8_t)b1,(uint8_t)c1,(uint8_t)d1);
  ((uchar4*)g_xq2)[i] = make_uchar4((uint8_t)a2,(uint8_t)b2,(uint8_t)c2,(uint8_t)d2);
}
__global__ void k_quant_kt(int n4){
  int i = blockIdx.x * blockDim.x + threadIdx.x;
  if (i >= n4) return;
  const float qs = 127.0f / g_scales[5];
  float4 v = ((const float4*)g_ktf)[i];
  int8_t a1,a2,b1,b2,c1,c2,d1,d2;
  quant2(v.x, qs, a1, a2); quant2(v.y, qs, b1, b2);
  quant2(v.z, qs, c1, c2); quant2(v.w, qs, d1, d2);
  ((uchar4*)g_ktq1)[i] = make_uchar4((uint8_t)a1,(uint8_t)b1,(uint8_t)c1,(uint8_t)d1);
  ((uchar4*)g_ktq2)[i] = make_uchar4((uint8_t)a2,(uint8_t)b2,(uint8_t)c2,(uint8_t)d2);
}

// ===========================================================================
// x transpose: fp32 [B,N,C] -> int8 q1/q2 planes, [b*C+c][n]
// ===========================================================================
__global__ void k_transpose_x(const float* __restrict__ in){
  __shared__ float t[32][33];
  const size_t zo = (size_t)blockIdx.z * C_ * N_;
  const int i0 = blockIdx.y*32, j0 = blockIdx.x*32;
  const float* ip = in + zo;
  const float qs = 127.0f / g_scales[0];
#pragma unroll
  for (int k = threadIdx.y; k < 32; k += 8)
    t[k][threadIdx.x] = ip[(size_t)(i0+k)*C_ + j0 + threadIdx.x];
  __syncthreads();
#pragma unroll
  for (int k = threadIdx.y; k < 32; k += 8){
    const size_t o = zo + (size_t)(j0+k)*N_ + i0 + threadIdx.x;
    int8_t q1, q2;
    quant2(t[threadIdx.x][k], qs, q1, q2);
    g_xq1[o] = q1;
    g_xq2[o] = q2;
  }
}

// ===========================================================================
// int8 IMMA mainloop: 3-stage pipeline, sync every chunk (proven form;
// the every-chunk barrier publishes each thread's cp.async fills).
// accM += a1*b1 ; accC += a1*b2 + a2*b1
// ===========================================================================
#define RSBI 48
#define TILE_I (128*RSBI)            // 6144 B
#define STAGE_I (4*TILE_I)           // 24576 B
#define GSMEM_I (3*STAGE_I)          // 73728 B

__device__ __forceinline__ void gemm_main_i8(
    uint32_t sb, int tid,
    const int8_t* __restrict__ A1, const int8_t* __restrict__ A2, int lda,
    const int8_t* __restrict__ B1, const int8_t* __restrict__ B2, int ldb,
    int nch, int (*accM)[4], int (*accC)[4]){
  const int t64  = tid & 63;
  const int tile = tid >> 6;                 // 0:A1 1:A2 2:B1 3:B2
  const int8_t* gsrc; int ld;
  if      (tile == 0){ gsrc = A1; ld = lda; }
  else if (tile == 1){ gsrc = A2; ld = lda; }
  else if (tile == 2){ gsrc = B1; ld = ldb; }
  else               { gsrc = B2; ld = ldb; }

  auto issue = [&](int ch, int stage){
    const int k0 = ch * 32;
    const uint32_t sbase = sb + stage * STAGE_I + tile * TILE_I;
#pragma unroll
    for (int j = 0; j < 4; j++){
      const int seg = t64 + 64 * j;
      const int row = seg >> 1, s = seg & 1;
      CP_ASYNC16(sbase + row * RSBI + s * 16,
                 (const char*)(gsrc + (size_t)row * ld + k0) + s * 16);
    }
    CP_COMMIT();
  };

  issue(0, 0);
  issue(1, 1);

  const int wid = tid >> 5, lane = tid & 31;
  const int wm = (wid >> 2) * 64, wn = (wid & 3) * 32;
  const int a_row = lane & 15, a_kb = (lane >> 4) * 16;
  const int b_row = (lane & 7) + ((lane >> 4) * 8);
  const int b_kb  = ((lane >> 3) & 1) * 16;

  for (int ch = 0; ch < nch; ch++){
    CP_WAIT1();
    __syncthreads();
    if (ch + 2 < nch) issue(ch + 2, (ch + 2) % 3);
    else CP_COMMIT();

    const uint32_t st = sb + (ch % 3) * STAGE_I;
    const uint32_t a1T = st,            a2T = st + TILE_I;
    const uint32_t b1T = st + 2*TILE_I, b2T = st + 3*TILE_I;

    uint32_t a1[4][4], a2[4][4], b1[4][2], b2[4][2];
#pragma unroll
    for (int mi = 0; mi < 4; mi++){
      const uint32_t ro = (uint32_t)(wm + mi*16 + a_row) * RSBI + a_kb;
      ldmx4(a1[mi], a1T + ro);
      ldmx4(a2[mi], a2T + ro);
    }
#pragma unroll
    for (int nh = 0; nh < 2; nh++){
      const uint32_t ro = (uint32_t)(wn + nh*16 + b_row) * RSBI + b_kb;
      uint32_t r[4];
      ldmx4(r, b1T + ro);
      b1[nh*2+0][0]=r[0]; b1[nh*2+0][1]=r[1]; b1[nh*2+1][0]=r[2]; b1[nh*2+1][1]=r[3];
      ldmx4(r, b2T + ro);
      b2[nh*2+0][0]=r[0]; b2[nh*2+0][1]=r[1]; b2[nh*2+1][0]=r[2]; b2[nh*2+1][1]=r[3];
    }
#pragma unroll
    for (int mi = 0; mi < 4; mi++)
#pragma unroll
      for (int ni = 0; ni < 4; ni++){
        imma16832(accM[4*mi+ni], a1[mi], b1[ni]);
        imma16832(accC[4*mi+ni], a1[mi], b2[ni]);
        imma16832(accC[4*mi+ni], a2[mi], b1[ni]);
      }
  }
  CP_WAIT0();
  __syncthreads();
}

// ===========================================================================
// bf16 HMMA mainloop (kt GEMM): 3-stage, sync every chunk (proven form)
// ===========================================================================
#define KC 32
#define RSB 80
#define TILE_SB (128*RSB)
#define STAGE_B (4*TILE_SB)
#define GSMEM (3*STAGE_B)            // 122880 B

__device__ __forceinline__ void gemm_main(
    uint32_t sb, int tid,
    const __nv_bfloat16* __restrict__ Ah, const __nv_bfloat16* __restrict__ Al, int lda,
    const __nv_bfloat16* __restrict__ Bh, const __nv_bfloat16* __restrict__ Bl, int ldb,
    int nch, float (*acc)[4]){
  const int t64  = tid & 63;
  const int tile = tid >> 6;
  const __nv_bfloat16* gsrc; int ld;
  if      (tile == 0){ gsrc = Ah; ld = lda; }
  else if (tile == 1){ gsrc = Al; ld = lda; }
  else if (tile == 2){ gsrc = Bh; ld = ldb; }
  else               { gsrc = Bl; ld = ldb; }

  auto issue = [&](int ch, int stage){
    const int k0 = ch * KC;
    const uint32_t sbase = sb + stage * STAGE_B + tile * TILE_SB;
#pragma unroll
    for (int j = 0; j < 8; j++){
      const int seg = t64 + 64 * j;
      const int row = seg >> 2, s4 = seg & 3;
      CP_ASYNC16(sbase + row * RSB + s4 * 16,
                 (const char*)(gsrc + (size_t)row * ld + k0) + s4 * 16);
    }
    CP_COMMIT();
  };

  issue(0, 0);
  issue(1, 1);

  const int wid = tid >> 5, lane = tid & 31;
  const int wm = (wid >> 2) * 64, wn = (wid & 3) * 32;
  const int a_row = lane % 16, a_k8 = (lane >> 4) * 8;
  const int b_row = (lane & 7) + ((lane >> 4) * 8);
  const int b_k8  = ((lane >> 3) & 1) * 8;

  for (int ch = 0; ch < nch; ch++){
    CP_WAIT1();
    __syncthreads();
    if (ch + 2 < nch) issue(ch + 2, (ch + 2) % 3);
    else CP_COMMIT();

    const uint32_t st = sb + (ch % 3) * STAGE_B;
    const uint32_t aH = st,             aL = st + TILE_SB;
    const uint32_t bH = st + 2*TILE_SB, bL = st + 3*TILE_SB;

#pragma unroll
    for (int kk = 0; kk < 2; kk++){
      uint32_t ah[4][4], al[4][4], bh[4][2], bl[4][2];
      const int kc = kk * 32 + a_k8 * 2;
#pragma unroll
      for (int mi = 0; mi < 4; mi++){
        const uint32_t ro = (uint32_t)(wm + mi*16 + a_row) * RSB + kc;
        ldmx4(ah[mi], aH + ro);
        ldmx4(al[mi], aL + ro);
      }
#pragma unroll
      for (int nh = 0; nh < 2; nh++){
        const uint32_t ro = (uint32_t)(wn + nh*16 + b_row) * RSB + kk*32 + b_k8*2;
        uint32_t r[4];
        ldmx4(r, bH + ro);
        bh[nh*2+0][0]=r[0]; bh[nh*2+0][1]=r[1]; bh[nh*2+1][0]=r[2]; bh[nh*2+1][1]=r[3];
        ldmx4(r, bL + ro);
        bl[nh*2+0][0]=r[0]; bl[nh*2+0][1]=r[1]; bl[nh*2+1][0]=r[2]; bl[nh*2+1][1]=r[3];
      }
#pragma unroll
      for (int mi = 0; mi < 4; mi++)
#pragma unroll
        for (int ni = 0; ni < 4; ni++){
          mma16816(acc[4*mi+ni], ah[mi], bh[ni]);
          mma16816(acc[4*mi+ni], ah[mi], bl[ni]);
          mma16816(acc[4*mi+ni], al[mi], bh[ni]);
        }
    }
  }
  CP_WAIT0();
  __syncthreads();
}

// Transposed bf16 hi/lo epilogue via fp32 smem bounce.
#define TS 130
__device__ __forceinline__ void epi_T_bf16(
    float (*acc)[4], char* smem, int tid, float f,
    __nv_bfloat16* dsth, __nv_bfloat16* dstl, int ldd){
  float* T = (float*)smem;
  const int wid = tid >> 5, lane = tid & 31;
  const int wm = (wid >> 2) * 64, wn = (wid & 3) * 32;
  const int tr = lane >> 2, tc = (lane & 3) * 2;
#pragma unroll
  for (int mi = 0; mi < 4; mi++)
#pragma unroll
    for (int ni = 0; ni < 4; ni++){
      float* a = acc[4*mi+ni];
      const int r = wm + mi*16 + tr, c = wn + ni*8 + tc;
      T[r*TS + c]     = a[0]*f; T[r*TS + c + 1]     = a[1]*f;
      T[(r+8)*TS + c] = a[2]*f; T[(r+8)*TS + c + 1] = a[3]*f;
    }
  __syncthreads();
#pragma unroll
  for (int it = 0; it < 4; it++){
    const int j = it*32 + (tid >> 3);
    const int mbase = (tid & 7) * 2;
#pragma unroll
    for (int p = 0; p < 8; p++){
      const int m = mbase + p*16;
      float f0 = T[m*TS + j], f1 = T[(m+1)*TS + j];
      uint32_t h, l; split2(f0, f1, h, l);
      *(uint32_t*)(dsth + (size_t)j*ldd + m) = h;
      *(uint32_t*)(dstl + (size_t)j*ldd + m) = l;
    }
  }
  __syncthreads();
}

// ===========================================================================
// kv GEMM (int8): C = xt @ W^T -> transposed bf16 hi/lo (+ norm partials)
// ===========================================================================
__global__ void __launch_bounds__(256,1)
k_gemm_kv_i8(const int8_t* __restrict__ W1, const int8_t* __restrict__ W2,
             int wsidx,
             __nv_bfloat16* __restrict__ dsth, __nv_bfloat16* __restrict__ dstl,
             int with_norm){
  extern __shared__ __align__(128) char smem[];
  __shared__ float red[8];
  const uint32_t sb = smem_u32(smem);
  const int tid = threadIdx.x;
  const int n0 = blockIdx.x * 128, m0 = blockIdx.y * 128;
  int accM[16][4] = {}, accC[16][4] = {};
  gemm_main_i8(sb, tid, g_xq1 + (size_t)m0*N_, g_xq2 + (size_t)m0*N_, N_,
               W1 + (size_t)n0*N_, W2 + (size_t)n0*N_, N_, 32, accM, accC);
  const float f = g_scales[0] * g_scales[wsidx] / 16129.0f;
  float facc[16][4];
#pragma unroll
  for (int q = 0; q < 16; q++)
#pragma unroll
    for (int e = 0; e < 4; e++)
      facc[q][e] = f * ((float)accM[q][e] + (float)accC[q][e] * (1.0f/254.0f));
  if (with_norm){
    float s2 = 0.f;
#pragma unroll
    for (int q = 0; q < 16; q++)
#pragma unroll
      for (int e = 0; e < 4; e++) s2 += facc[q][e]*facc[q][e];
#pragma unroll
    for (int o = 16; o; o >>= 1) s2 += __shfl_down_sync(0xffffffffu, s2, o);
    if ((tid & 31) == 0) red[tid >> 5] = s2;
    __syncthreads();
    if (tid == 0){
      float t = 0.f;
#pragma unroll
      for (int w = 0; w < 8; w++) t += red[w];
      g_part[blockIdx.y * 8 + blockIdx.x] = t;
    }
  }
  const int b = m0 / C_, c0 = m0 % C_;
  const size_t off = ((size_t)b*N_ + n0) * C_ + c0;
  epi_T_bf16(facc, smem, tid, 1.f, dsth + off, dstl + off, C_);
}

__global__ void k_reduce(){
  __shared__ float sh[1024];
  const int t = threadIdx.x;
  sh[t] = g_part[t] + g_part[t+1024] + g_part[t+2048];
  __syncthreads();
  for (int o = 512; o; o >>= 1){
    if (t < o) sh[t] += sh[t+o];
    __syncthreads();
  }
  if (t == 0) g_norm2 = sh[0];
}

// ===========================================================================
// kt GEMM (bf16): kt[n][m] = sum_c kT[n][c]*vT[m][c]; scaled;
// store ktT[m][n] fp32 + amax partials
// ===========================================================================
__global__ void __launch_bounds__(256,1)
k_gemm_kt(const float* __restrict__ scale){
  extern __shared__ __align__(128) char smem[];
  __shared__ float redm[8];
  const uint32_t sb = smem_u32(smem);
  const int tid = threadIdx.x;
  const int bh = blockIdx.x, b = bh >> 3, h = bh & 7;
  const size_t base = ((size_t)b*N_ + h*D_) * C_;
  float acc[16][4] = {};
  gemm_main(sb, tid, g_kTh + base, g_kTl + base, C_,
            g_vTh + base, g_vTl + base, C_, 24, acc);
  const float nrm = sqrtf(g_norm2) + EPSF;
  const float f = scale[h] / (nrm*nrm);
  float mx = 0.f;
#pragma unroll
  for (int q = 0; q < 16; q++)
#pragma unroll
    for (int e = 0; e < 4; e++){
      acc[q][e] *= f;
      mx = fmaxf(mx, fabsf(acc[q][e]));
    }
#pragma unroll
  for (int o = 16; o; o >>= 1) mx = fmaxf(mx, __shfl_down_sync(0xffffffffu, mx, o));
  const int wid = tid >> 5, lane = tid & 31;
  if (lane == 0) redm[wid] = mx;
  float* T = (float*)smem;
  const int wm = (wid >> 2) * 64, wn = (wid & 3) * 32;
  const int tr = lane >> 2, tc = (lane & 3) * 2;
#pragma unroll
  for (int mi = 0; mi < 4; mi++)
#pragma unroll
    for (int ni = 0; ni < 4; ni++){
      float* a = acc[4*mi+ni];
      const int r = wm + mi*16 + tr, c = wn + ni*8 + tc;
      T[r*TS + c]     = a[0]; T[r*TS + c + 1]     = a[1];
      T[(r+8)*TS + c] = a[2]; T[(r+8)*TS + c + 1] = a[3];
    }
  __syncthreads();
  float* dst = g_ktf + (size_t)bh*D_*D_;
#pragma unroll
  for (int it = 0; it < 4; it++){
    const int j = it*32 + (tid >> 3);
    const int mbase = (tid & 7) * 2;
#pragma unroll
    for (int p = 0; p < 8; p++){
      const int m = mbase + p*16;
      *(float2*)(dst + (size_t)j*D_ + m) = make_float2(T[m*TS + j], T[(m+1)*TS + j]);
    }
  }
  if (tid == 0){
    float t = 0.f;
#pragma unroll
    for (int w = 0; w < 8; w++) t = fmaxf(t, redm[w]);
    g_mpart[5120 + bh] = t;
  }
}

// ===========================================================================
// out GEMM (int8): out1 = q @ kt -> exact gelu fp32 + per-block amax partial
// ===========================================================================
__global__ void __launch_bounds__(256,1)
k_gemm_out_i8(){
  extern __shared__ __align__(128) char smem[];
  __shared__ float redm[8];
  const uint32_t sb = smem_u32(smem);
  const int tid = threadIdx.x;
  const int c0 = blockIdx.x * 128;
  const int bh = blockIdx.y, b = bh >> 3, h = bh & 7;
  const size_t Abase = ((size_t)b*C_ + c0) * N_ + (size_t)h*D_;
  int accM[16][4] = {}, accC[16][4] = {};
  gemm_main_i8(sb, tid, g_xq1 + Abase, g_xq2 + Abase, N_,
               g_ktq1 + (size_t)bh*D_*D_, g_ktq2 + (size_t)bh*D_*D_, D_, 4,
               accM, accC);
  const float f = g_scales[0] * g_scales[5] / 16129.0f;
  const int wid = tid >> 5, lane = tid & 31;
  const int wm = (wid >> 2) * 64, wn = (wid & 3) * 32;
  const int tr = lane >> 2, tc = (lane & 3) * 2;
  float mx = 0.f;
#pragma unroll
  for (int mi = 0; mi < 4; mi++)
#pragma unroll
    for (int ni = 0; ni < 4; ni++){
      int* aM = accM[4*mi+ni];
      int* aC = accC[4*mi+ni];
      const int col = wn + ni*8 + tc;
      const size_t r0 = Abase + (size_t)(wm + mi*16 + tr) * N_ + col;
      const size_t r1 = r0 + 8*N_;
      float v0 = f*((float)aM[0] + (float)aC[0]*(1.0f/254.0f));
      float v1 = f*((float)aM[1] + (float)aC[1]*(1.0f/254.0f));
      float v2 = f*((float)aM[2] + (float)aC[2]*(1.0f/254.0f));
      float v3 = f*((float)aM[3] + (float)aC[3]*(1.0f/254.0f));
      float g0 = gelu_exact(v0), g1 = gelu_exact(v1);
      float g2 = gelu_exact(v2), g3 = gelu_exact(v3);
      *(float2*)(g_gelu + r0) = make_float2(g0, g1);
      *(float2*)(g_gelu + r1) = make_float2(g2, g3);
      mx = fmaxf(mx, fmaxf(fmaxf(fabsf(g0), fabsf(g1)), fmaxf(fabsf(g2), fabsf(g3))));
    }
#pragma unroll
  for (int o = 16; o; o >>= 1) mx = fmaxf(mx, __shfl_down_sync(0xffffffffu, mx, o));
  if (lane == 0) redm[wid] = mx;
  __syncthreads();
  if (tid == 0){
    float t = 0.f;
#pragma unroll
    for (int w = 0; w < 8; w++) t = fmaxf(t, redm[w]);
    g_mpart[2048 + blockIdx.y*6 + blockIdx.x] = t;
  }
}

// ===========================================================================
// proj GEMM (int8): out2 = gelu @ proj_w^T + pb; transposed write -> [B,N,C]
// ===========================================================================
__global__ void __launch_bounds__(256,1)
k_gemm_proj_i8(const int8_t* __restrict__ W1, const int8_t* __restrict__ W2,
               const float* __restrict__ pb, float* __restrict__ out){
  extern __shared__ __align__(128) char smem[];
  const uint32_t sb = smem_u32(smem);
  const int tid = threadIdx.x;
  const int n0 = blockIdx.x * 128, m0 = blockIdx.y * 128;
  int accM[16][4] = {}, accC[16][4] = {};
  gemm_main_i8(sb, tid, g_xq1 + (size_t)m0*N_, g_xq2 + (size_t)m0*N_, N_,
               W1 + (size_t)n0*N_, W2 + (size_t)n0*N_, N_, 32, accM, accC);
  const float f = g_scales[4] * g_scales[3] / 16129.0f;
  const int wid = tid >> 5, lane = tid & 31;
  const int wm = (wid >> 2) * 64, wn = (wid & 3) * 32;
  const int tr = lane >> 2, tc = (lane & 3) * 2;
  float* T = (float*)smem;
#pragma unroll
  for (int mi = 0; mi < 4; mi++)
#pragma unroll
    for (int ni = 0; ni < 4; ni++){
      int* aM = accM[4*mi+ni];
      int* aC = accC[4*mi+ni];
      const int c = wn + ni*8 + tc;
      const float2 bv = *(const float2*)(pb + n0 + c);
      const int r = wm + mi*16 + tr;
      float v0 = f*((float)aM[0] + (float)aC[0]*(1.0f/254.0f)) + bv.x;
      float v1 = f*((float)aM[1] + (float)aC[1]*(1.0f/254.0f)) + bv.y;
      float v2 = f*((float)aM[2] + (float)aC[2]*(1.0f/254.0f)) + bv.x;
      float v3 = f*((float)aM[3] + (float)aC[3]*(1.0f/254.0f)) + bv.y;
      T[r*TS + c]     = v0; T[r*TS + c + 1]     = v1;
      T[(r+8)*TS + c] = v2; T[(r+8)*TS + c + 1] = v3;
    }
  __syncthreads();
  const int b = m0 / C_, c0 = m0 % C_;
  float* dst = out + ((size_t)b*N_ + n0) * C_ + c0;
#pragma unroll
  for (int it = 0; it < 4; it++){
    const int j = it*32 + (tid >> 3);
    const int mbase = (tid & 7) * 2;
#pragma unroll
    for (int p = 0; p < 8; p++){
      const int m = mbase + p*16;
      *(float2*)(dst + (size_t)j*C_ + m) = make_float2(T[m*TS + j], T[(m+1)*TS + j]);
    }
  }
}

// ---------------------------------------------------------------------------
// Launch: graph-capturable, allocation-free, deterministic.
// ---------------------------------------------------------------------------
extern "C" void kernel_launch(void* const* d_in, const int* in_sizes, int n_in,
                              void* d_out, int out_size){
  const float* x   = (const float*)d_in[0];
  const float* qkw = (const float*)d_in[1];
  const float* vw  = (const float*)d_in[2];
  const float* pw  = (const float*)d_in[3];
  const float* pb  = (const float*)d_in[4];
  const float* sc  = (const float*)d_in[5];
  float* out = (float*)d_out;

  int8_t *p_wq1=nullptr, *p_wq2=nullptr;
  __nv_bfloat16 *p_kTh=nullptr, *p_kTl=nullptr, *p_vTh=nullptr, *p_vTl=nullptr;
  cudaGetSymbolAddress((void**)&p_wq1, g_wq1);
  cudaGetSymbolAddress((void**)&p_wq2, g_wq2);
  cudaGetSymbolAddress((void**)&p_kTh, g_kTh);
  cudaGetSymbolAddress((void**)&p_kTl, g_kTl);
  cudaGetSymbolAddress((void**)&p_vTh, g_vTh);
  cudaGetSymbolAddress((void**)&p_vTl, g_vTl);

  cudaFuncSetAttribute(k_gemm_kv_i8,  cudaFuncAttributeMaxDynamicSharedMemorySize, GSMEM_I);
  cudaFuncSetAttribute(k_gemm_out_i8, cudaFuncAttributeMaxDynamicSharedMemorySize, GSMEM_I);
  cudaFuncSetAttribute(k_gemm_proj_i8,cudaFuncAttributeMaxDynamicSharedMemorySize, GSMEM_I);
  cudaFuncSetAttribute(k_gemm_kt,  cudaFuncAttributeMaxDynamicSharedMemorySize, GSMEM);

  const size_t W2 = (size_t)N_*N_;

  // amax scales (exact, deterministic) — one fused kernel
  k_amax_all<<<dim3(512,4), 256>>>((const float4*)x, (const float4*)qkw,
                                   (const float4*)vw, (const float4*)pw);
  k_amax_fin<<<1, 512>>>();

  // x -> xt int8 q1/q2; weight quantization
  k_transpose_x<<<dim3(24,32,64), dim3(32,8)>>>(x);
  k_quantW<<<1024, 256>>>(qkw, p_wq1,      p_wq2,      1, (int)(W2/4));
  k_quantW<<<1024, 256>>>(vw,  p_wq1+W2,   p_wq2+W2,   2, (int)(W2/4));
  k_quantW<<<1024, 256>>>(pw,  p_wq1+2*W2, p_wq2+2*W2, 3, (int)(W2/4));

  // k -> kT (+ norm partials), v -> vT  (int8 IMMA)
  k_gemm_kv_i8<<<dim3(8,384), 256, GSMEM_I>>>(p_wq1,    p_wq2,    1, p_kTh, p_kTl, 1);
  k_gemm_kv_i8<<<dim3(8,384), 256, GSMEM_I>>>(p_wq1+W2, p_wq2+W2, 2, p_vTh, p_vTl, 0);
  k_reduce<<<1,1024>>>();

  // kt (bf16) -> ktT fp32 + amax; quantize kt; out (int8) -> gelu + amax
  k_gemm_kt<<<512, 256, GSMEM>>>(sc);
  k_scale_kt<<<1, 512>>>();
  k_quant_kt<<<8192, 256>>>((int)(KTN_/4));
  k_gemm_out_i8<<<dim3(6,512), 256, GSMEM_I>>>();
  k_scale_gelu<<<1, 1024>>>();
  k_quant_gelu<<<49152, 256>>>((int)(ROWS_*N_/4));

  // proj (int8 IMMA) + bias, transposed write direct to [B,N,C]
  k_gemm_proj_i8<<<dim3(8,384), 256, GSMEM_I>>>(p_wq1+2*W2, p_wq2+2*W2, pb, out);
}

// round 15
// speedup vs baseline: 1.5884x; 1.1562x over previous
#include <cuda_runtime.h>
#include <cuda_bf16.h>
#include <math.h>
#include <stdint.h>

// Problem constants: B=64, N=1024, C=768, heads=8, d=128
#define B_ 64
#define N_ 1024
#define C_ 768
#define H_ 8
#define D_ 128
#define EPSF 1e-8f
#define ROWS_ ((size_t)B_*C_)   // 49152
#define KTN_ ((size_t)B_*H_*D_*D_)   // 8388608

// ---------------------------------------------------------------------------
// Scratch (device globals — allocation-free rule)
// ---------------------------------------------------------------------------
__device__ int8_t g_xq1[ROWS_*N_];         // xt int8 chunk1
__device__ int8_t g_xq2[ROWS_*N_];         // xt int8 chunk2
__device__ int8_t g_wq1[3][(size_t)N_*N_];
__device__ int8_t g_wq2[3][(size_t)N_*N_];
__device__ __nv_bfloat16 g_kTh[(size_t)B_*N_*C_];  // kT [b][n][c] hi
__device__ __nv_bfloat16 g_kTl[(size_t)B_*N_*C_];
__device__ __nv_bfloat16 g_vTh[(size_t)B_*N_*C_];
__device__ __nv_bfloat16 g_vTl[(size_t)B_*N_*C_];
__device__ float  g_ktf[KTN_];             // ktT fp32 [bh][m][n]
__device__ int8_t g_ktq1[KTN_];            // ktT int8 chunk1
__device__ int8_t g_ktq2[KTN_];            // ktT int8 chunk2
__device__ float g_gelu[ROWS_*N_];         // fp32 gelu output (proj input)
__device__ float g_part[3072];
__device__ float g_norm2;
__device__ float g_mpart[6144];            // amax partials
__device__ float g_scales[8];              // 0:x 1:qkw 2:vw 3:pw 4:gelu 5:kt

// ---------------------------------------------------------------------------
// Helpers
// ---------------------------------------------------------------------------
__device__ __forceinline__ uint32_t smem_u32(const void* p){
  uint32_t a;
  asm("{ .reg .u64 t; cvta.to.shared.u64 t, %1; cvt.u32.u64 %0, t; }" : "=r"(a) : "l"(p));
  return a;
}
__device__ __forceinline__ void split2(float fx, float fy, uint32_t& hi, uint32_t& lo){
  uint32_t h;
  asm("cvt.rn.bf16x2.f32 %0, %1, %2;" : "=r"(h) : "f"(fy), "f"(fx));
  float hx = __uint_as_float(h << 16);
  float hy = __uint_as_float(h & 0xffff0000u);
  float lx = fx - hx, ly = fy - hy;
  asm("cvt.rn.bf16x2.f32 %0, %1, %2;" : "=r"(lo) : "f"(ly), "f"(lx));
  hi = h;
}
__device__ __forceinline__ float gelu_exact(float x){
  return 0.5f * x * (1.0f + erff(x * 0.7071067811865475f));
}
// int8 2-chunk quantization: x ~= (S/127)*(q1 + q2/254)
__device__ __forceinline__ void quant2(float v, float qs, int8_t& q1, int8_t& q2){
  float q = v * qs;
  float a1 = rintf(q);
  q1 = (int8_t)(int)a1;
  q2 = (int8_t)(int)rintf((q - a1) * 254.0f);
}

#define CP_ASYNC16(s, g) \
  asm volatile("cp.async.cg.shared.global [%0], [%1], 16;" :: "r"(s), "l"(g) : "memory")
#define CP_COMMIT() asm volatile("cp.async.commit_group;" ::: "memory")
#define CP_WAIT1()  asm volatile("cp.async.wait_group 1;" ::: "memory")
#define CP_WAIT0()  asm volatile("cp.async.wait_group 0;" ::: "memory")

__device__ __forceinline__ void ldmx4(uint32_t* r, uint32_t addr){
  asm volatile("ldmatrix.sync.aligned.m8n8.x4.shared.b16 {%0,%1,%2,%3}, [%4];"
    : "=r"(r[0]), "=r"(r[1]), "=r"(r[2]), "=r"(r[3]) : "r"(addr));
}
__device__ __forceinline__ void mma16816(float* c, const uint32_t* a, const uint32_t* b){
  asm volatile("mma.sync.aligned.m16n8k16.row.col.f32.bf16.bf16.f32 "
    "{%0,%1,%2,%3},{%4,%5,%6,%7},{%8,%9},{%0,%1,%2,%3};"
    : "+f"(c[0]), "+f"(c[1]), "+f"(c[2]), "+f"(c[3])
    : "r"(a[0]), "r"(a[1]), "r"(a[2]), "r"(a[3]), "r"(b[0]), "r"(b[1]));
}
__device__ __forceinline__ void imma16832(int* c, const uint32_t* a, const uint32_t* b){
  asm volatile("mma.sync.aligned.m16n8k32.row.col.s32.s8.s8.s32 "
    "{%0,%1,%2,%3},{%4,%5,%6,%7},{%8,%9},{%0,%1,%2,%3};"
    : "+r"(c[0]), "+r"(c[1]), "+r"(c[2]), "+r"(c[3])
    : "r"(a[0]), "r"(a[1]), "r"(a[2]), "r"(a[3]), "r"(b[0]), "r"(b[1]));
}

// ===========================================================================
// Fused amax over x + 3 weights (float4 streaming; exact max, deterministic)
// grid (512, 4): y=0 -> x, y=1..3 -> weights. Partials at [y*512 + x].
// ===========================================================================
__global__ void k_amax_all(const float4* __restrict__ x4,
                           const float4* __restrict__ w1,
                           const float4* __restrict__ w2,
                           const float4* __restrict__ w3){
  __shared__ float sm[256];
  const int y = blockIdx.y;
  const float4* src; int n4;
  if      (y == 0){ src = x4; n4 = (int)(ROWS_*N_/4); }
  else if (y == 1){ src = w1; n4 = (int)((size_t)N_*N_/4); }
  else if (y == 2){ src = w2; n4 = (int)((size_t)N_*N_/4); }
  else            { src = w3; n4 = (int)((size_t)N_*N_/4); }
  float m = 0.f;
  for (int i = blockIdx.x*256 + threadIdx.x; i < n4; i += 512*256){
    float4 v = src[i];
    m = fmaxf(m, fmaxf(fmaxf(fabsf(v.x), fabsf(v.y)), fmaxf(fabsf(v.z), fabsf(v.w))));
  }
  sm[threadIdx.x] = m;
  __syncthreads();
  for (int o = 128; o; o >>= 1){
    if (threadIdx.x < o) sm[threadIdx.x] = fmaxf(sm[threadIdx.x], sm[threadIdx.x+o]);
    __syncthreads();
  }
  if (threadIdx.x == 0) g_mpart[y*512 + blockIdx.x] = sm[0];
}
__global__ void k_amax_fin(){
  __shared__ float sm[512];
  const int t = threadIdx.x;
#pragma unroll
  for (int r = 0; r < 4; r++){
    sm[t] = g_mpart[r*512 + t];
    __syncthreads();
    for (int o = 256; o; o >>= 1){
      if (t < o) sm[t] = fmaxf(sm[t], sm[t+o]);
      __syncthreads();
    }
    if (t == 0) g_scales[r] = sm[0];
    __syncthreads();
  }
}
__global__ void k_scale_gelu(){
  __shared__ float sm[1024];
  const int t = threadIdx.x;
  float m = 0.f;
  for (int i = t; i < 3072; i += 1024) m = fmaxf(m, g_mpart[2048+i]);
  sm[t] = m;
  __syncthreads();
  for (int o = 512; o; o >>= 1){
    if (t < o) sm[t] = fmaxf(sm[t], sm[t+o]);
    __syncthreads();
  }
  if (t == 0) g_scales[4] = sm[0];
}
__global__ void k_scale_kt(){
  __shared__ float sm[512];
  const int t = threadIdx.x;
  sm[t] = g_mpart[5120 + t];
  __syncthreads();
  for (int o = 256; o; o >>= 1){
    if (t < o) sm[t] = fmaxf(sm[t], sm[t+o]);
    __syncthreads();
  }
  if (t == 0) g_scales[5] = sm[0];
}

// ===========================================================================
// Quantization kernels
// ===========================================================================
__global__ void k_quantW(const float* __restrict__ in, int8_t* __restrict__ q1,
                         int8_t* __restrict__ q2, int sidx, int n4){
  int i = blockIdx.x * blockDim.x + threadIdx.x;
  if (i >= n4) return;
  const float qs = 127.0f / g_scales[sidx];
  float4 v = ((const float4*)in)[i];
  int8_t a1,a2,b1,b2,c1,c2,d1,d2;
  quant2(v.x, qs, a1, a2); quant2(v.y, qs, b1, b2);
  quant2(v.z, qs, c1, c2); quant2(v.w, qs, d1, d2);
  ((uchar4*)q1)[i] = make_uchar4((uint8_t)a1,(uint8_t)b1,(uint8_t)c1,(uint8_t)d1);
  ((uchar4*)q2)[i] = make_uchar4((uint8_t)a2,(uint8_t)b2,(uint8_t)c2,(uint8_t)d2);
}
__global__ void k_quant_gelu(int n4){
  int i = blockIdx.x * blockDim.x + threadIdx.x;
  if (i >= n4) return;
  const float qs = 127.0f / g_scales[4];
  float4 v = ((const float4*)g_gelu)[i];
  int8_t a1,a2,b1,b2,c1,c2,d1,d2;
  quant2(v.x, qs, a1, a2); quant2(v.y, qs, b1, b2);
  quant2(v.z, qs, c1, c2); quant2(v.w, qs, d1, d2);
  ((uchar4*)g_xq1)[i] = make_uchar4((uint8_t)a1,(uint8_t)b1,(uint8_t)c1,(uint8_t)d1);
  ((uchar4*)g_xq2)[i] = make_uchar4((uint8_t)a2,(uint8_t)b2,(uint8_t)c2,(uint8_t)d2);
}
__global__ void k_quant_kt(int n4){
  int i = blockIdx.x * blockDim.x + threadIdx.x;
  if (i >= n4) return;
  const float qs = 127.0f / g_scales[5];
  float4 v = ((const float4*)g_ktf)[i];
  int8_t a1,a2,b1,b2,c1,c2,d1,d2;
  quant2(v.x, qs, a1, a2); quant2(v.y, qs, b1, b2);
  quant2(v.z, qs, c1, c2); quant2(v.w, qs, d1, d2);
  ((uchar4*)g_ktq1)[i] = make_uchar4((uint8_t)a1,(uint8_t)b1,(uint8_t)c1,(uint8_t)d1);
  ((uchar4*)g_ktq2)[i] = make_uchar4((uint8_t)a2,(uint8_t)b2,(uint8_t)c2,(uint8_t)d2);
}

// ===========================================================================
// x transpose: fp32 [B,N,C] -> int8 q1/q2 planes, [b*C+c][n]
// ===========================================================================
__global__ void k_transpose_x(const float* __restrict__ in){
  __shared__ float t[32][33];
  const size_t zo = (size_t)blockIdx.z * C_ * N_;
  const int i0 = blockIdx.y*32, j0 = blockIdx.x*32;
  const float* ip = in + zo;
  const float qs = 127.0f / g_scales[0];
#pragma unroll
  for (int k = threadIdx.y; k < 32; k += 8)
    t[k][threadIdx.x] = ip[(size_t)(i0+k)*C_ + j0 + threadIdx.x];
  __syncthreads();
#pragma unroll
  for (int k = threadIdx.y; k < 32; k += 8){
    const size_t o = zo + (size_t)(j0+k)*N_ + i0 + threadIdx.x;
    int8_t q1, q2;
    quant2(t[threadIdx.x][k], qs, q1, q2);
    g_xq1[o] = q1;
    g_xq2[o] = q2;
  }
}

// ===========================================================================
// int8 IMMA mainloop: KC=64, 3-stage pipeline, sync every chunk (each barrier
// publishes each thread's cp.async fills before anyone reads the stage).
// Half the barriers of KC=32 at identical numerics.
// Row stride 80B: 8-row ldmatrix groups hit banks {0,20,8,28,16,4,24,12}.
// accM += a1*b1 ; accC += a1*b2 + a2*b1
// ===========================================================================
#define RSBI 80
#define TILE_I (128*RSBI)            // 10240 B
#define STAGE_I (4*TILE_I)           // 40960 B
#define GSMEM_I (3*STAGE_I)          // 122880 B

__device__ __forceinline__ void gemm_main_i8(
    uint32_t sb, int tid,
    const int8_t* __restrict__ A1, const int8_t* __restrict__ A2, int lda,
    const int8_t* __restrict__ B1, const int8_t* __restrict__ B2, int ldb,
    int nch, int (*accM)[4], int (*accC)[4]){
  const int t64  = tid & 63;
  const int tile = tid >> 6;                 // 0:A1 1:A2 2:B1 3:B2
  const int8_t* gsrc; int ld;
  if      (tile == 0){ gsrc = A1; ld = lda; }
  else if (tile == 1){ gsrc = A2; ld = lda; }
  else if (tile == 2){ gsrc = B1; ld = ldb; }
  else               { gsrc = B2; ld = ldb; }

  auto issue = [&](int ch, int stage){
    const int k0 = ch * 64;
    const uint32_t sbase = sb + stage * STAGE_I + tile * TILE_I;
#pragma unroll
    for (int j = 0; j < 8; j++){
      const int seg = t64 + 64 * j;        // 512 segs = 128 rows x 4
      const int row = seg >> 2, s = seg & 3;
      CP_ASYNC16(sbase + row * RSBI + s * 16,
                 (const char*)(gsrc + (size_t)row * ld + k0) + s * 16);
    }
    CP_COMMIT();
  };

  issue(0, 0);
  issue(1, 1);

  const int wid = tid >> 5, lane = tid & 31;
  const int wm = (wid >> 2) * 64, wn = (wid & 3) * 32;
  const int a_row = lane & 15, a_kb = (lane >> 4) * 16;
  const int b_row = (lane & 7) + ((lane >> 4) * 8);
  const int b_kb  = ((lane >> 3) & 1) * 16;

  for (int ch = 0; ch < nch; ch++){
    CP_WAIT1();
    __syncthreads();
    if (ch + 2 < nch) issue(ch + 2, (ch + 2) % 3);
    else CP_COMMIT();

    const uint32_t st = sb + (ch % 3) * STAGE_I;
    const uint32_t a1T = st,            a2T = st + TILE_I;
    const uint32_t b1T = st + 2*TILE_I, b2T = st + 3*TILE_I;

#pragma unroll
    for (int kk = 0; kk < 2; kk++){
      const int kb = kk * 32;
      uint32_t a1[4][4], a2[4][4], b1[4][2], b2[4][2];
#pragma unroll
      for (int mi = 0; mi < 4; mi++){
        const uint32_t ro = (uint32_t)(wm + mi*16 + a_row) * RSBI + kb + a_kb;
        ldmx4(a1[mi], a1T + ro);
        ldmx4(a2[mi], a2T + ro);
      }
#pragma unroll
      for (int nh = 0; nh < 2; nh++){
        const uint32_t ro = (uint32_t)(wn + nh*16 + b_row) * RSBI + kb + b_kb;
        uint32_t r[4];
        ldmx4(r, b1T + ro);
        b1[nh*2+0][0]=r[0]; b1[nh*2+0][1]=r[1]; b1[nh*2+1][0]=r[2]; b1[nh*2+1][1]=r[3];
        ldmx4(r, b2T + ro);
        b2[nh*2+0][0]=r[0]; b2[nh*2+0][1]=r[1]; b2[nh*2+1][0]=r[2]; b2[nh*2+1][1]=r[3];
      }
#pragma unroll
      for (int mi = 0; mi < 4; mi++)
#pragma unroll
        for (int ni = 0; ni < 4; ni++){
          imma16832(accM[4*mi+ni], a1[mi], b1[ni]);
          imma16832(accC[4*mi+ni], a1[mi], b2[ni]);
          imma16832(accC[4*mi+ni], a2[mi], b1[ni]);
        }
    }
  }
  CP_WAIT0();
  __syncthreads();
}

// ===========================================================================
// bf16 HMMA mainloop (kt GEMM): 3-stage, sync every chunk (proven form)
// ===========================================================================
#define KC 32
#define RSB 80
#define TILE_SB (128*RSB)
#define STAGE_B (4*TILE_SB)
#define GSMEM (3*STAGE_B)            // 122880 B

__device__ __forceinline__ void gemm_main(
    uint32_t sb, int tid,
    const __nv_bfloat16* __restrict__ Ah, const __nv_bfloat16* __restrict__ Al, int lda,
    const __nv_bfloat16* __restrict__ Bh, const __nv_bfloat16* __restrict__ Bl, int ldb,
    int nch, float (*acc)[4]){
  const int t64  = tid & 63;
  const int tile = tid >> 6;
  const __nv_bfloat16* gsrc; int ld;
  if      (tile == 0){ gsrc = Ah; ld = lda; }
  else if (tile == 1){ gsrc = Al; ld = lda; }
  else if (tile == 2){ gsrc = Bh; ld = ldb; }
  else               { gsrc = Bl; ld = ldb; }

  auto issue = [&](int ch, int stage){
    const int k0 = ch * KC;
    const uint32_t sbase = sb + stage * STAGE_B + tile * TILE_SB;
#pragma unroll
    for (int j = 0; j < 8; j++){
      const int seg = t64 + 64 * j;
      const int row = seg >> 2, s4 = seg & 3;
      CP_ASYNC16(sbase + row * RSB + s4 * 16,
                 (const char*)(gsrc + (size_t)row * ld + k0) + s4 * 16);
    }
    CP_COMMIT();
  };

  issue(0, 0);
  issue(1, 1);

  const int wid = tid >> 5, lane = tid & 31;
  const int wm = (wid >> 2) * 64, wn = (wid & 3) * 32;
  const int a_row = lane % 16, a_k8 = (lane >> 4) * 8;
  const int b_row = (lane & 7) + ((lane >> 4) * 8);
  const int b_k8  = ((lane >> 3) & 1) * 8;

  for (int ch = 0; ch < nch; ch++){
    CP_WAIT1();
    __syncthreads();
    if (ch + 2 < nch) issue(ch + 2, (ch + 2) % 3);
    else CP_COMMIT();

    const uint32_t st = sb + (ch % 3) * STAGE_B;
    const uint32_t aH = st,             aL = st + TILE_SB;
    const uint32_t bH = st + 2*TILE_SB, bL = st + 3*TILE_SB;

#pragma unroll
    for (int kk = 0; kk < 2; kk++){
      uint32_t ah[4][4], al[4][4], bh[4][2], bl[4][2];
      const int kc = kk * 32 + a_k8 * 2;
#pragma unroll
      for (int mi = 0; mi < 4; mi++){
        const uint32_t ro = (uint32_t)(wm + mi*16 + a_row) * RSB + kc;
        ldmx4(ah[mi], aH + ro);
        ldmx4(al[mi], aL + ro);
      }
#pragma unroll
      for (int nh = 0; nh < 2; nh++){
        const uint32_t ro = (uint32_t)(wn + nh*16 + b_row) * RSB + kk*32 + b_k8*2;
        uint32_t r[4];
        ldmx4(r, bH + ro);
        bh[nh*2+0][0]=r[0]; bh[nh*2+0][1]=r[1]; bh[nh*2+1][0]=r[2]; bh[nh*2+1][1]=r[3];
        ldmx4(r, bL + ro);
        bl[nh*2+0][0]=r[0]; bl[nh*2+0][1]=r[1]; bl[nh*2+1][0]=r[2]; bl[nh*2+1][1]=r[3];
      }
#pragma unroll
      for (int mi = 0; mi < 4; mi++)
#pragma unroll
        for (int ni = 0; ni < 4; ni++){
          mma16816(acc[4*mi+ni], ah[mi], bh[ni]);
          mma16816(acc[4*mi+ni], ah[mi], bl[ni]);
          mma16816(acc[4*mi+ni], al[mi], bh[ni]);
        }
    }
  }
  CP_WAIT0();
  __syncthreads();
}

// Transposed bf16 hi/lo epilogue via fp32 smem bounce.
#define TS 130
__device__ __forceinline__ void epi_T_bf16(
    float (*acc)[4], char* smem, int tid, float f,
    __nv_bfloat16* dsth, __nv_bfloat16* dstl, int ldd){
  float* T = (float*)smem;
  const int wid = tid >> 5, lane = tid & 31;
  const int wm = (wid >> 2) * 64, wn = (wid & 3) * 32;
  const int tr = lane >> 2, tc = (lane & 3) * 2;
#pragma unroll
  for (int mi = 0; mi < 4; mi++)
#pragma unroll
    for (int ni = 0; ni < 4; ni++){
      float* a = acc[4*mi+ni];
      const int r = wm + mi*16 + tr, c = wn + ni*8 + tc;
      T[r*TS + c]     = a[0]*f; T[r*TS + c + 1]     = a[1]*f;
      T[(r+8)*TS + c] = a[2]*f; T[(r+8)*TS + c + 1] = a[3]*f;
    }
  __syncthreads();
#pragma unroll
  for (int it = 0; it < 4; it++){
    const int j = it*32 + (tid >> 3);
    const int mbase = (tid & 7) * 2;
#pragma unroll
    for (int p = 0; p < 8; p++){
      const int m = mbase + p*16;
      float f0 = T[m*TS + j], f1 = T[(m+1)*TS + j];
      uint32_t h, l; split2(f0, f1, h, l);
      *(uint32_t*)(dsth + (size_t)j*ldd + m) = h;
      *(uint32_t*)(dstl + (size_t)j*ldd + m) = l;
    }
  }
  __syncthreads();
}

// ===========================================================================
// kv GEMM (int8): C = xt @ W^T -> transposed bf16 hi/lo (+ norm partials)
// ===========================================================================
__global__ void __launch_bounds__(256,1)
k_gemm_kv_i8(const int8_t* __restrict__ W1, const int8_t* __restrict__ W2,
             int wsidx,
             __nv_bfloat16* __restrict__ dsth, __nv_bfloat16* __restrict__ dstl,
             int with_norm){
  extern __shared__ __align__(128) char smem[];
  __shared__ float red[8];
  const uint32_t sb = smem_u32(smem);
  const int tid = threadIdx.x;
  const int n0 = blockIdx.x * 128, m0 = blockIdx.y * 128;
  int accM[16][4] = {}, accC[16][4] = {};
  gemm_main_i8(sb, tid, g_xq1 + (size_t)m0*N_, g_xq2 + (size_t)m0*N_, N_,
               W1 + (size_t)n0*N_, W2 + (size_t)n0*N_, N_, 16, accM, accC);
  const float f = g_scales[0] * g_scales[wsidx] / 16129.0f;
  float facc[16][4];
#pragma unroll
  for (int q = 0; q < 16; q++)
#pragma unroll
    for (int e = 0; e < 4; e++)
      facc[q][e] = f * ((float)accM[q][e] + (float)accC[q][e] * (1.0f/254.0f));
  if (with_norm){
    float s2 = 0.f;
#pragma unroll
    for (int q = 0; q < 16; q++)
#pragma unroll
      for (int e = 0; e < 4; e++) s2 += facc[q][e]*facc[q][e];
#pragma unroll
    for (int o = 16; o; o >>= 1) s2 += __shfl_down_sync(0xffffffffu, s2, o);
    if ((tid & 31) == 0) red[tid >> 5] = s2;
    __syncthreads();
    if (tid == 0){
      float t = 0.f;
#pragma unroll
      for (int w = 0; w < 8; w++) t += red[w];
      g_part[blockIdx.y * 8 + blockIdx.x] = t;
    }
  }
  const int b = m0 / C_, c0 = m0 % C_;
  const size_t off = ((size_t)b*N_ + n0) * C_ + c0;
  epi_T_bf16(facc, smem, tid, 1.f, dsth + off, dstl + off, C_);
}

__global__ void k_reduce(){
  __shared__ float sh[1024];
  const int t = threadIdx.x;
  sh[t] = g_part[t] + g_part[t+1024] + g_part[t+2048];
  __syncthreads();
  for (int o = 512; o; o >>= 1){
    if (t < o) sh[t] += sh[t+o];
    __syncthreads();
  }
  if (t == 0) g_norm2 = sh[0];
}

// ===========================================================================
// kt GEMM (bf16): kt[n][m] = sum_c kT[n][c]*vT[m][c]; scaled;
// store ktT[m][n] fp32 + amax partials
// ===========================================================================
__global__ void __launch_bounds__(256,1)
k_gemm_kt(const float* __restrict__ scale){
  extern __shared__ __align__(128) char smem[];
  __shared__ float redm[8];
  const uint32_t sb = smem_u32(smem);
  const int tid = threadIdx.x;
  const int bh = blockIdx.x, b = bh >> 3, h = bh & 7;
  const size_t base = ((size_t)b*N_ + h*D_) * C_;
  float acc[16][4] = {};
  gemm_main(sb, tid, g_kTh + base, g_kTl + base, C_,
            g_vTh + base, g_vTl + base, C_, 24, acc);
  const float nrm = sqrtf(g_norm2) + EPSF;
  const float f = scale[h] / (nrm*nrm);
  float mx = 0.f;
#pragma unroll
  for (int q = 0; q < 16; q++)
#pragma unroll
    for (int e = 0; e < 4; e++){
      acc[q][e] *= f;
      mx = fmaxf(mx, fabsf(acc[q][e]));
    }
#pragma unroll
  for (int o = 16; o; o >>= 1) mx = fmaxf(mx, __shfl_down_sync(0xffffffffu, mx, o));
  const int wid = tid >> 5, lane = tid & 31;
  if (lane == 0) redm[wid] = mx;
  float* T = (float*)smem;
  const int wm = (wid >> 2) * 64, wn = (wid & 3) * 32;
  const int tr = lane >> 2, tc = (lane & 3) * 2;
#pragma unroll
  for (int mi = 0; mi < 4; mi++)
#pragma unroll
    for (int ni = 0; ni < 4; ni++){
      float* a = acc[4*mi+ni];
      const int r = wm + mi*16 + tr, c = wn + ni*8 + tc;
      T[r*TS + c]     = a[0]; T[r*TS + c + 1]     = a[1];
      T[(r+8)*TS + c] = a[2]; T[(r+8)*TS + c + 1] = a[3];
    }
  __syncthreads();
  float* dst = g_ktf + (size_t)bh*D_*D_;
#pragma unroll
  for (int it = 0; it < 4; it++){
    const int j = it*32 + (tid >> 3);
    const int mbase = (tid & 7) * 2;
#pragma unroll
    for (int p = 0; p < 8; p++){
      const int m = mbase + p*16;
      *(float2*)(dst + (size_t)j*D_ + m) = make_float2(T[m*TS + j], T[(m+1)*TS + j]);
    }
  }
  if (tid == 0){
    float t = 0.f;
#pragma unroll
    for (int w = 0; w < 8; w++) t = fmaxf(t, redm[w]);
    g_mpart[5120 + bh] = t;
  }
}

// ===========================================================================
// out GEMM (int8): out1 = q @ kt -> exact gelu fp32 + per-block amax partial
// K=128 -> nch=2 (KC=64)
// ===========================================================================
__global__ void __launch_bounds__(256,1)
k_gemm_out_i8(){
  extern __shared__ __align__(128) char smem[];
  __shared__ float redm[8];
  const uint32_t sb = smem_u32(smem);
  const int tid = threadIdx.x;
  const int c0 = blockIdx.x * 128;
  const int bh = blockIdx.y, b = bh >> 3, h = bh & 7;
  const size_t Abase = ((size_t)b*C_ + c0) * N_ + (size_t)h*D_;
  int accM[16][4] = {}, accC[16][4] = {};
  gemm_main_i8(sb, tid, g_xq1 + Abase, g_xq2 + Abase, N_,
               g_ktq1 + (size_t)bh*D_*D_, g_ktq2 + (size_t)bh*D_*D_, D_, 2,
               accM, accC);
  const float f = g_scales[0] * g_scales[5] / 16129.0f;
  const int wid = tid >> 5, lane = tid & 31;
  const int wm = (wid >> 2) * 64, wn = (wid & 3) * 32;
  const int tr = lane >> 2, tc = (lane & 3) * 2;
  float mx = 0.f;
#pragma unroll
  for (int mi = 0; mi < 4; mi++)
#pragma unroll
    for (int ni = 0; ni < 4; ni++){
      int* aM = accM[4*mi+ni];
      int* aC = accC[4*mi+ni];
      const int col = wn + ni*8 + tc;
      const size_t r0 = Abase + (size_t)(wm + mi*16 + tr) * N_ + col;
      const size_t r1 = r0 + 8*N_;
      float v0 = f*((float)aM[0] + (float)aC[0]*(1.0f/254.0f));
      float v1 = f*((float)aM[1] + (float)aC[1]*(1.0f/254.0f));
      float v2 = f*((float)aM[2] + (float)aC[2]*(1.0f/254.0f));
      float v3 = f*((float)aM[3] + (float)aC[3]*(1.0f/254.0f));
      float g0 = gelu_exact(v0), g1 = gelu_exact(v1);
      float g2 = gelu_exact(v2), g3 = gelu_exact(v3);
      *(float2*)(g_gelu + r0) = make_float2(g0, g1);
      *(float2*)(g_gelu + r1) = make_float2(g2, g3);
      mx = fmaxf(mx, fmaxf(fmaxf(fabsf(g0), fabsf(g1)), fmaxf(fabsf(g2), fabsf(g3))));
    }
#pragma unroll
  for (int o = 16; o; o >>= 1) mx = fmaxf(mx, __shfl_down_sync(0xffffffffu, mx, o));
  if (lane == 0) redm[wid] = mx;
  __syncthreads();
  if (tid == 0){
    float t = 0.f;
#pragma unroll
    for (int w = 0; w < 8; w++) t = fmaxf(t, redm[w]);
    g_mpart[2048 + blockIdx.y*6 + blockIdx.x] = t;
  }
}

// ===========================================================================
// proj GEMM (int8): out2 = gelu @ proj_w^T + pb; transposed write -> [B,N,C]
// ===========================================================================
__global__ void __launch_bounds__(256,1)
k_gemm_proj_i8(const int8_t* __restrict__ W1, const int8_t* __restrict__ W2,
               const float* __restrict__ pb, float* __restrict__ out){
  extern __shared__ __align__(128) char smem[];
  const uint32_t sb = smem_u32(smem);
  const int tid = threadIdx.x;
  const int n0 = blockIdx.x * 128, m0 = blockIdx.y * 128;
  int accM[16][4] = {}, accC[16][4] = {};
  gemm_main_i8(sb, tid, g_xq1 + (size_t)m0*N_, g_xq2 + (size_t)m0*N_, N_,
               W1 + (size_t)n0*N_, W2 + (size_t)n0*N_, N_, 16, accM, accC);
  const float f = g_scales[4] * g_scales[3] / 16129.0f;
  const int wid = tid >> 5, lane = tid & 31;
  const int wm = (wid >> 2) * 64, wn = (wid & 3) * 32;
  const int tr = lane >> 2, tc = (lane & 3) * 2;
  float* T = (float*)smem;
#pragma unroll
  for (int mi = 0; mi < 4; mi++)
#pragma unroll
    for (int ni = 0; ni < 4; ni++){
      int* aM = accM[4*mi+ni];
      int* aC = accC[4*mi+ni];
      const int c = wn + ni*8 + tc;
      const float2 bv = *(const float2*)(pb + n0 + c);
      const int r = wm + mi*16 + tr;
      float v0 = f*((float)aM[0] + (float)aC[0]*(1.0f/254.0f)) + bv.x;
      float v1 = f*((float)aM[1] + (float)aC[1]*(1.0f/254.0f)) + bv.y;
      float v2 = f*((float)aM[2] + (float)aC[2]*(1.0f/254.0f)) + bv.x;
      float v3 = f*((float)aM[3] + (float)aC[3]*(1.0f/254.0f)) + bv.y;
      T[r*TS + c]     = v0; T[r*TS + c + 1]     = v1;
      T[(r+8)*TS + c] = v2; T[(r+8)*TS + c + 1] = v3;
    }
  __syncthreads();
  const int b = m0 / C_, c0 = m0 % C_;
  float* dst = out + ((size_t)b*N_ + n0) * C_ + c0;
#pragma unroll
  for (int it = 0; it < 4; it++){
    const int j = it*32 + (tid >> 3);
    const int mbase = (tid & 7) * 2;
#pragma unroll
    for (int p = 0; p < 8; p++){
      const int m = mbase + p*16;
      *(float2*)(dst + (size_t)j*C_ + m) = make_float2(T[m*TS + j], T[(m+1)*TS + j]);
    }
  }
}

// ---------------------------------------------------------------------------
// Launch: graph-capturable, allocation-free, deterministic.
// ---------------------------------------------------------------------------
extern "C" void kernel_launch(void* const* d_in, const int* in_sizes, int n_in,
                              void* d_out, int out_size){
  const float* x   = (const float*)d_in[0];
  const float* qkw = (const float*)d_in[1];
  const float* vw  = (const float*)d_in[2];
  const float* pw  = (const float*)d_in[3];
  const float* pb  = (const float*)d_in[4];
  const float* sc  = (const float*)d_in[5];
  float* out = (float*)d_out;

  int8_t *p_wq1=nullptr, *p_wq2=nullptr;
  __nv_bfloat16 *p_kTh=nullptr, *p_kTl=nullptr, *p_vTh=nullptr, *p_vTl=nullptr;
  cudaGetSymbolAddress((void**)&p_wq1, g_wq1);
  cudaGetSymbolAddress((void**)&p_wq2, g_wq2);
  cudaGetSymbolAddress((void**)&p_kTh, g_kTh);
  cudaGetSymbolAddress((void**)&p_kTl, g_kTl);
  cudaGetSymbolAddress((void**)&p_vTh, g_vTh);
  cudaGetSymbolAddress((void**)&p_vTl, g_vTl);

  cudaFuncSetAttribute(k_gemm_kv_i8,  cudaFuncAttributeMaxDynamicSharedMemorySize, GSMEM_I);
  cudaFuncSetAttribute(k_gemm_out_i8, cudaFuncAttributeMaxDynamicSharedMemorySize, GSMEM_I);
  cudaFuncSetAttribute(k_gemm_proj_i8,cudaFuncAttributeMaxDynamicSharedMemorySize, GSMEM_I);
  cudaFuncSetAttribute(k_gemm_kt,  cudaFuncAttributeMaxDynamicSharedMemorySize, GSMEM);

  const size_t W2 = (size_t)N_*N_;

  // amax scales (exact, deterministic) — one fused kernel
  k_amax_all<<<dim3(512,4), 256>>>((const float4*)x, (const float4*)qkw,
                                   (const float4*)vw, (const float4*)pw);
  k_amax_fin<<<1, 512>>>();

  // x -> xt int8 q1/q2; weight quantization
  k_transpose_x<<<dim3(24,32,64), dim3(32,8)>>>(x);
  k_quantW<<<1024, 256>>>(qkw, p_wq1,      p_wq2,      1, (int)(W2/4));
  k_quantW<<<1024, 256>>>(vw,  p_wq1+W2,   p_wq2+W2,   2, (int)(W2/4));
  k_quantW<<<1024, 256>>>(pw,  p_wq1+2*W2, p_wq2+2*W2, 3, (int)(W2/4));

  // k -> kT (+ norm partials), v -> vT  (int8 IMMA, KC=64)
  k_gemm_kv_i8<<<dim3(8,384), 256, GSMEM_I>>>(p_wq1,    p_wq2,    1, p_kTh, p_kTl, 1);
  k_gemm_kv_i8<<<dim3(8,384), 256, GSMEM_I>>>(p_wq1+W2, p_wq2+W2, 2, p_vTh, p_vTl, 0);
  k_reduce<<<1,1024>>>();

  // kt (bf16) -> ktT fp32 + amax; quantize kt; out (int8) -> gelu + amax
  k_gemm_kt<<<512, 256, GSMEM>>>(sc);
  k_scale_kt<<<1, 512>>>();
  k_quant_kt<<<8192, 256>>>((int)(KTN_/4));
  k_gemm_out_i8<<<dim3(6,512), 256, GSMEM_I>>>();
  k_scale_gelu<<<1, 1024>>>();
  k_quant_gelu<<<49152, 256>>>((int)(ROWS_*N_/4));

  // proj (int8 IMMA, KC=64) + bias, transposed write direct to [B,N,C]
  k_gemm_proj_i8<<<dim3(8,384), 256, GSMEM_I>>>(p_wq1+2*W2, p_wq2+2*W2, pb, out);
}

// round 16
// speedup vs baseline: 1.7685x; 1.1134x over previous
#include <cuda_runtime.h>
#include <cuda_bf16.h>
#include <math.h>
#include <stdint.h>

// Problem constants: B=64, N=1024, C=768, heads=8, d=128
#define B_ 64
#define N_ 1024
#define C_ 768
#define H_ 8
#define D_ 128
#define EPSF 1e-8f
#define ROWS_ ((size_t)B_*C_)   // 49152
#define KTN_ ((size_t)B_*H_*D_*D_)   // 8388608

// ---------------------------------------------------------------------------
// Scratch (device globals — allocation-free rule)
// ---------------------------------------------------------------------------
__device__ int8_t g_xq1[ROWS_*N_];         // xt int8 chunk1
__device__ int8_t g_xq2[ROWS_*N_];         // xt int8 chunk2
__device__ int8_t g_wq1[3][(size_t)N_*N_];
__device__ int8_t g_wq2[3][(size_t)N_*N_];
__device__ __nv_bfloat16 g_kTh[(size_t)B_*N_*C_];  // kT [b][n][c] hi
__device__ __nv_bfloat16 g_kTl[(size_t)B_*N_*C_];
__device__ __nv_bfloat16 g_vTh[(size_t)B_*N_*C_];
__device__ __nv_bfloat16 g_vTl[(size_t)B_*N_*C_];
__device__ float  g_ktf[KTN_];             // ktT fp32 [bh][m][n]
__device__ int8_t g_ktq1[KTN_];            // ktT int8 chunk1
__device__ int8_t g_ktq2[KTN_];            // ktT int8 chunk2
__device__ float g_gelu[ROWS_*N_];         // fp32 gelu output (proj input)
__device__ float g_part[3072];
__device__ float g_norm2;
__device__ float g_mpart[6144];            // amax partials
__device__ float g_scales[8];              // 0:x 1:qkw 2:vw 3:pw 4:gelu 5:kt

// ---------------------------------------------------------------------------
// Helpers
// ---------------------------------------------------------------------------
__device__ __forceinline__ uint32_t smem_u32(const void* p){
  uint32_t a;
  asm("{ .reg .u64 t; cvta.to.shared.u64 t, %1; cvt.u32.u64 %0, t; }" : "=r"(a) : "l"(p));
  return a;
}
__device__ __forceinline__ void split2(float fx, float fy, uint32_t& hi, uint32_t& lo){
  uint32_t h;
  asm("cvt.rn.bf16x2.f32 %0, %1, %2;" : "=r"(h) : "f"(fy), "f"(fx));
  float hx = __uint_as_float(h << 16);
  float hy = __uint_as_float(h & 0xffff0000u);
  float lx = fx - hx, ly = fy - hy;
  asm("cvt.rn.bf16x2.f32 %0, %1, %2;" : "=r"(lo) : "f"(ly), "f"(lx));
  hi = h;
}
__device__ __forceinline__ float gelu_exact(float x){
  return 0.5f * x * (1.0f + erff(x * 0.7071067811865475f));
}
// int8 2-chunk quantization: x ~= (S/127)*(q1 + q2/254)
__device__ __forceinline__ void quant2(float v, float qs, int8_t& q1, int8_t& q2){
  float q = v * qs;
  float a1 = rintf(q);
  q1 = (int8_t)(int)a1;
  q2 = (int8_t)(int)rintf((q - a1) * 254.0f);
}

#define CP_ASYNC16(s, g) \
  asm volatile("cp.async.cg.shared.global [%0], [%1], 16;" :: "r"(s), "l"(g) : "memory")
#define CP_COMMIT() asm volatile("cp.async.commit_group;" ::: "memory")
#define CP_WAIT1()  asm volatile("cp.async.wait_group 1;" ::: "memory")
#define CP_WAIT0()  asm volatile("cp.async.wait_group 0;" ::: "memory")

__device__ __forceinline__ void ldmx4(uint32_t* r, uint32_t addr){
  asm volatile("ldmatrix.sync.aligned.m8n8.x4.shared.b16 {%0,%1,%2,%3}, [%4];"
    : "=r"(r[0]), "=r"(r[1]), "=r"(r[2]), "=r"(r[3]) : "r"(addr));
}
__device__ __forceinline__ void mma16816(float* c, const uint32_t* a, const uint32_t* b){
  asm volatile("mma.sync.aligned.m16n8k16.row.col.f32.bf16.bf16.f32 "
    "{%0,%1,%2,%3},{%4,%5,%6,%7},{%8,%9},{%0,%1,%2,%3};"
    : "+f"(c[0]), "+f"(c[1]), "+f"(c[2]), "+f"(c[3])
    : "r"(a[0]), "r"(a[1]), "r"(a[2]), "r"(a[3]), "r"(b[0]), "r"(b[1]));
}
__device__ __forceinline__ void imma16832(int* c, const uint32_t* a, const uint32_t* b){
  asm volatile("mma.sync.aligned.m16n8k32.row.col.s32.s8.s8.s32 "
    "{%0,%1,%2,%3},{%4,%5,%6,%7},{%8,%9},{%0,%1,%2,%3};"
    : "+r"(c[0]), "+r"(c[1]), "+r"(c[2]), "+r"(c[3])
    : "r"(a[0]), "r"(a[1]), "r"(a[2]), "r"(a[3]), "r"(b[0]), "r"(b[1]));
}

// ===========================================================================
// Fused amax over x + 3 weights (float4 streaming; exact max, deterministic)
// ===========================================================================
__global__ void k_amax_all(const float4* __restrict__ x4,
                           const float4* __restrict__ w1,
                           const float4* __restrict__ w2,
                           const float4* __restrict__ w3){
  __shared__ float sm[256];
  const int y = blockIdx.y;
  const float4* src; int n4;
  if      (y == 0){ src = x4; n4 = (int)(ROWS_*N_/4); }
  else if (y == 1){ src = w1; n4 = (int)((size_t)N_*N_/4); }
  else if (y == 2){ src = w2; n4 = (int)((size_t)N_*N_/4); }
  else            { src = w3; n4 = (int)((size_t)N_*N_/4); }
  float m = 0.f;
  for (int i = blockIdx.x*256 + threadIdx.x; i < n4; i += 512*256){
    float4 v = src[i];
    m = fmaxf(m, fmaxf(fmaxf(fabsf(v.x), fabsf(v.y)), fmaxf(fabsf(v.z), fabsf(v.w))));
  }
  sm[threadIdx.x] = m;
  __syncthreads();
  for (int o = 128; o; o >>= 1){
    if (threadIdx.x < o) sm[threadIdx.x] = fmaxf(sm[threadIdx.x], sm[threadIdx.x+o]);
    __syncthreads();
  }
  if (threadIdx.x == 0) g_mpart[y*512 + blockIdx.x] = sm[0];
}
__global__ void k_amax_fin(){
  __shared__ float sm[512];
  const int t = threadIdx.x;
#pragma unroll
  for (int r = 0; r < 4; r++){
    sm[t] = g_mpart[r*512 + t];
    __syncthreads();
    for (int o = 256; o; o >>= 1){
      if (t < o) sm[t] = fmaxf(sm[t], sm[t+o]);
      __syncthreads();
    }
    if (t == 0) g_scales[r] = sm[0];
    __syncthreads();
  }
}
__global__ void k_scale_gelu(){
  __shared__ float sm[1024];
  const int t = threadIdx.x;
  float m = 0.f;
  for (int i = t; i < 3072; i += 1024) m = fmaxf(m, g_mpart[2048+i]);
  sm[t] = m;
  __syncthreads();
  for (int o = 512; o; o >>= 1){
    if (t < o) sm[t] = fmaxf(sm[t], sm[t+o]);
    __syncthreads();
  }
  if (t == 0) g_scales[4] = sm[0];
}
__global__ void k_scale_kt(){
  __shared__ float sm[512];
  const int t = threadIdx.x;
  sm[t] = g_mpart[5120 + t];
  __syncthreads();
  for (int o = 256; o; o >>= 1){
    if (t < o) sm[t] = fmaxf(sm[t], sm[t+o]);
    __syncthreads();
  }
  if (t == 0) g_scales[5] = sm[0];
}

// ===========================================================================
// Quantization kernels
// ===========================================================================
__global__ void k_quantW(const float* __restrict__ in, int8_t* __restrict__ q1,
                         int8_t* __restrict__ q2, int sidx, int n4){
  int i = blockIdx.x * blockDim.x + threadIdx.x;
  if (i >= n4) return;
  const float qs = 127.0f / g_scales[sidx];
  float4 v = ((const float4*)in)[i];
  int8_t a1,a2,b1,b2,c1,c2,d1,d2;
  quant2(v.x, qs, a1, a2); quant2(v.y, qs, b1, b2);
  quant2(v.z, qs, c1, c2); quant2(v.w, qs, d1, d2);
  ((uchar4*)q1)[i] = make_uchar4((uint8_t)a1,(uint8_t)b1,(uint8_t)c1,(uint8_t)d1);
  ((uchar4*)q2)[i] = make_uchar4((uint8_t)a2,(uint8_t)b2,(uint8_t)c2,(uint8_t)d2);
}
__global__ void k_quant_gelu(int n4){
  int i = blockIdx.x * blockDim.x + threadIdx.x;
  if (i >= n4) return;
  const float qs = 127.0f / g_scales[4];
  float4 v = ((const float4*)g_gelu)[i];
  int8_t a1,a2,b1,b2,c1,c2,d1,d2;
  quant2(v.x, qs, a1, a2); quant2(v.y, qs, b1, b2);
  quant2(v.z, qs, c1, c2); quant2(v.w, qs, d1, d2);
  ((uchar4*)g_xq1)[i] = make_uchar4((uint8_t)a1,(uint8_t)b1,(uint8_t)c1,(uint8_t)d1);
  ((uchar4*)g_xq2)[i] = make_uchar4((uint8_t)a2,(uint8_t)b2,(uint8_t)c2,(uint8_t)d2);
}
__global__ void k_quant_kt(int n4){
  int i = blockIdx.x * blockDim.x + threadIdx.x;
  if (i >= n4) return;
  const float qs = 127.0f / g_scales[5];
  float4 v = ((const float4*)g_ktf)[i];
  int8_t a1,a2,b1,b2,c1,c2,d1,d2;
  quant2(v.x, qs, a1, a2); quant2(v.y, qs, b1, b2);
  quant2(v.z, qs, c1, c2); quant2(v.w, qs, d1, d2);
  ((uchar4*)g_ktq1)[i] = make_uchar4((uint8_t)a1,(uint8_t)b1,(uint8_t)c1,(uint8_t)d1);
  ((uchar4*)g_ktq2)[i] = make_uchar4((uint8_t)a2,(uint8_t)b2,(uint8_t)c2,(uint8_t)d2);
}

// ===========================================================================
// x transpose: fp32 [B,N,C] -> int8 q1/q2 planes, [b*C+c][n]
// ===========================================================================
__global__ void k_transpose_x(const float* __restrict__ in){
  __shared__ float t[32][33];
  const size_t zo = (size_t)blockIdx.z * C_ * N_;
  const int i0 = blockIdx.y*32, j0 = blockIdx.x*32;
  const float* ip = in + zo;
  const float qs = 127.0f / g_scales[0];
#pragma unroll
  for (int k = threadIdx.y; k < 32; k += 8)
    t[k][threadIdx.x] = ip[(size_t)(i0+k)*C_ + j0 + threadIdx.x];
  __syncthreads();
#pragma unroll
  for (int k = threadIdx.y; k < 32; k += 8){
    const size_t o = zo + (size_t)(j0+k)*N_ + i0 + threadIdx.x;
    int8_t q1, q2;
    quant2(t[threadIdx.x][k], qs, q1, q2);
    g_xq1[o] = q1;
    g_xq2[o] = q2;
  }
}

// ===========================================================================
// int8 IMMA mainloop, templated on K-chunk KCI (multiple of 32, pow2/16).
// 3-stage pipeline, sync every chunk (each barrier publishes cp.async fills).
// Row stride KCI+16 bytes keeps 8-row ldmatrix groups conflict-free.
// accM += a1*b1 ; accC += a1*b2 + a2*b1
// ===========================================================================
template<int KCI>
__device__ __forceinline__ void gemm_main_i8(
    uint32_t sb, int tid,
    const int8_t* __restrict__ A1, const int8_t* __restrict__ A2, int lda,
    const int8_t* __restrict__ B1, const int8_t* __restrict__ B2, int ldb,
    int nch, int (*accM)[4], int (*accC)[4]){
  constexpr int RSBI = KCI + 16;
  constexpr int TILE = 128 * RSBI;
  constexpr int STAGE = 4 * TILE;
  constexpr int SPR = KCI / 16;           // 16B segs per row
  const int t64  = tid & 63;
  const int tile = tid >> 6;                 // 0:A1 1:A2 2:B1 3:B2
  const int8_t* gsrc; int ld;
  if      (tile == 0){ gsrc = A1; ld = lda; }
  else if (tile == 1){ gsrc = A2; ld = lda; }
  else if (tile == 2){ gsrc = B1; ld = ldb; }
  else               { gsrc = B2; ld = ldb; }

  auto issue = [&](int ch, int stage){
    const int k0 = ch * KCI;
    const uint32_t sbase = sb + stage * STAGE + tile * TILE;
#pragma unroll
    for (int j = 0; j < 2*SPR; j++){        // 128*SPR segs / 64 threads
      const int seg = t64 + 64 * j;
      const int row = seg / SPR, s = seg % SPR;
      CP_ASYNC16(sbase + row * RSBI + s * 16,
                 (const char*)(gsrc + (size_t)row * ld + k0) + s * 16);
    }
    CP_COMMIT();
  };

  issue(0, 0);
  issue(1, 1);

  const int wid = tid >> 5, lane = tid & 31;
  const int wm = (wid >> 2) * 64, wn = (wid & 3) * 32;
  const int a_row = lane & 15, a_kb = (lane >> 4) * 16;
  const int b_row = (lane & 7) + ((lane >> 4) * 8);
  const int b_kb  = ((lane >> 3) & 1) * 16;

  for (int ch = 0; ch < nch; ch++){
    CP_WAIT1();
    __syncthreads();
    if (ch + 2 < nch) issue(ch + 2, (ch + 2) % 3);
    else CP_COMMIT();

    const uint32_t st = sb + (ch % 3) * STAGE;
    const uint32_t a1T = st,           a2T = st + TILE;
    const uint32_t b1T = st + 2*TILE,  b2T = st + 3*TILE;

#pragma unroll
    for (int kk = 0; kk < KCI/32; kk++){
      const int kb = kk * 32;
      uint32_t a1[4][4], a2[4][4], b1[4][2], b2[4][2];
#pragma unroll
      for (int mi = 0; mi < 4; mi++){
        const uint32_t ro = (uint32_t)(wm + mi*16 + a_row) * RSBI + kb + a_kb;
        ldmx4(a1[mi], a1T + ro);
        ldmx4(a2[mi], a2T + ro);
      }
#pragma unroll
      for (int nh = 0; nh < 2; nh++){
        const uint32_t ro = (uint32_t)(wn + nh*16 + b_row) * RSBI + kb + b_kb;
        uint32_t r[4];
        ldmx4(r, b1T + ro);
        b1[nh*2+0][0]=r[0]; b1[nh*2+0][1]=r[1]; b1[nh*2+1][0]=r[2]; b1[nh*2+1][1]=r[3];
        ldmx4(r, b2T + ro);
        b2[nh*2+0][0]=r[0]; b2[nh*2+0][1]=r[1]; b2[nh*2+1][0]=r[2]; b2[nh*2+1][1]=r[3];
      }
#pragma unroll
      for (int mi = 0; mi < 4; mi++)
#pragma unroll
        for (int ni = 0; ni < 4; ni++){
          imma16832(accM[4*mi+ni], a1[mi], b1[ni]);
          imma16832(accC[4*mi+ni], a1[mi], b2[ni]);
          imma16832(accC[4*mi+ni], a2[mi], b1[ni]);
        }
    }
  }
  CP_WAIT0();
  __syncthreads();
}

#define GSMEM_I128 (3*4*128*(128+16))   // 221184 B (KCI=128)
#define GSMEM_I64  (3*4*128*(64+16))    // 122880 B (KCI=64)

// ===========================================================================
// bf16 HMMA mainloop (kt GEMM): 3-stage, sync every chunk (proven form)
// ===========================================================================
#define KC 32
#define RSB 80
#define TILE_SB (128*RSB)
#define STAGE_B (4*TILE_SB)
#define GSMEM (3*STAGE_B)            // 122880 B

__device__ __forceinline__ void gemm_main(
    uint32_t sb, int tid,
    const __nv_bfloat16* __restrict__ Ah, const __nv_bfloat16* __restrict__ Al, int lda,
    const __nv_bfloat16* __restrict__ Bh, const __nv_bfloat16* __restrict__ Bl, int ldb,
    int nch, float (*acc)[4]){
  const int t64  = tid & 63;
  const int tile = tid >> 6;
  const __nv_bfloat16* gsrc; int ld;
  if      (tile == 0){ gsrc = Ah; ld = lda; }
  else if (tile == 1){ gsrc = Al; ld = lda; }
  else if (tile == 2){ gsrc = Bh; ld = ldb; }
  else               { gsrc = Bl; ld = ldb; }

  auto issue = [&](int ch, int stage){
    const int k0 = ch * KC;
    const uint32_t sbase = sb + stage * STAGE_B + tile * TILE_SB;
#pragma unroll
    for (int j = 0; j < 8; j++){
      const int seg = t64 + 64 * j;
      const int row = seg >> 2, s4 = seg & 3;
      CP_ASYNC16(sbase + row * RSB + s4 * 16,
                 (const char*)(gsrc + (size_t)row * ld + k0) + s4 * 16);
    }
    CP_COMMIT();
  };

  issue(0, 0);
  issue(1, 1);

  const int wid = tid >> 5, lane = tid & 31;
  const int wm = (wid >> 2) * 64, wn = (wid & 3) * 32;
  const int a_row = lane % 16, a_k8 = (lane >> 4) * 8;
  const int b_row = (lane & 7) + ((lane >> 4) * 8);
  const int b_k8  = ((lane >> 3) & 1) * 8;

  for (int ch = 0; ch < nch; ch++){
    CP_WAIT1();
    __syncthreads();
    if (ch + 2 < nch) issue(ch + 2, (ch + 2) % 3);
    else CP_COMMIT();

    const uint32_t st = sb + (ch % 3) * STAGE_B;
    const uint32_t aH = st,             aL = st + TILE_SB;
    const uint32_t bH = st + 2*TILE_SB, bL = st + 3*TILE_SB;

#pragma unroll
    for (int kk = 0; kk < 2; kk++){
      uint32_t ah[4][4], al[4][4], bh[4][2], bl[4][2];
      const int kc = kk * 32 + a_k8 * 2;
#pragma unroll
      for (int mi = 0; mi < 4; mi++){
        const uint32_t ro = (uint32_t)(wm + mi*16 + a_row) * RSB + kc;
        ldmx4(ah[mi], aH + ro);
        ldmx4(al[mi], aL + ro);
      }
#pragma unroll
      for (int nh = 0; nh < 2; nh++){
        const uint32_t ro = (uint32_t)(wn + nh*16 + b_row) * RSB + kk*32 + b_k8*2;
        uint32_t r[4];
        ldmx4(r, bH + ro);
        bh[nh*2+0][0]=r[0]; bh[nh*2+0][1]=r[1]; bh[nh*2+1][0]=r[2]; bh[nh*2+1][1]=r[3];
        ldmx4(r, bL + ro);
        bl[nh*2+0][0]=r[0]; bl[nh*2+0][1]=r[1]; bl[nh*2+1][0]=r[2]; bl[nh*2+1][1]=r[3];
      }
#pragma unroll
      for (int mi = 0; mi < 4; mi++)
#pragma unroll
        for (int ni = 0; ni < 4; ni++){
          mma16816(acc[4*mi+ni], ah[mi], bh[ni]);
          mma16816(acc[4*mi+ni], ah[mi], bl[ni]);
          mma16816(acc[4*mi+ni], al[mi], bh[ni]);
        }
    }
  }
  CP_WAIT0();
  __syncthreads();
}

// Transposed bf16 hi/lo epilogue via fp32 smem bounce.
#define TS 130
__device__ __forceinline__ void epi_T_bf16(
    float (*acc)[4], char* smem, int tid, float f,
    __nv_bfloat16* dsth, __nv_bfloat16* dstl, int ldd){
  float* T = (float*)smem;
  const int wid = tid >> 5, lane = tid & 31;
  const int wm = (wid >> 2) * 64, wn = (wid & 3) * 32;
  const int tr = lane >> 2, tc = (lane & 3) * 2;
#pragma unroll
  for (int mi = 0; mi < 4; mi++)
#pragma unroll
    for (int ni = 0; ni < 4; ni++){
      float* a = acc[4*mi+ni];
      const int r = wm + mi*16 + tr, c = wn + ni*8 + tc;
      T[r*TS + c]     = a[0]*f; T[r*TS + c + 1]     = a[1]*f;
      T[(r+8)*TS + c] = a[2]*f; T[(r+8)*TS + c + 1] = a[3]*f;
    }
  __syncthreads();
#pragma unroll
  for (int it = 0; it < 4; it++){
    const int j = it*32 + (tid >> 3);
    const int mbase = (tid & 7) * 2;
#pragma unroll
    for (int p = 0; p < 8; p++){
      const int m = mbase + p*16;
      float f0 = T[m*TS + j], f1 = T[(m+1)*TS + j];
      uint32_t h, l; split2(f0, f1, h, l);
      *(uint32_t*)(dsth + (size_t)j*ldd + m) = h;
      *(uint32_t*)(dstl + (size_t)j*ldd + m) = l;
    }
  }
  __syncthreads();
}

// ===========================================================================
// kv GEMM (int8, KCI=128): C = xt @ W^T -> transposed bf16 hi/lo (+ norm)
// ===========================================================================
__global__ void __launch_bounds__(256,1)
k_gemm_kv_i8(const int8_t* __restrict__ W1, const int8_t* __restrict__ W2,
             int wsidx,
             __nv_bfloat16* __restrict__ dsth, __nv_bfloat16* __restrict__ dstl,
             int with_norm){
  extern __shared__ __align__(128) char smem[];
  __shared__ float red[8];
  const uint32_t sb = smem_u32(smem);
  const int tid = threadIdx.x;
  const int n0 = blockIdx.x * 128, m0 = blockIdx.y * 128;
  int accM[16][4] = {}, accC[16][4] = {};
  gemm_main_i8<128>(sb, tid, g_xq1 + (size_t)m0*N_, g_xq2 + (size_t)m0*N_, N_,
                    W1 + (size_t)n0*N_, W2 + (size_t)n0*N_, N_, 8, accM, accC);
  const float f = g_scales[0] * g_scales[wsidx] / 16129.0f;
  float facc[16][4];
#pragma unroll
  for (int q = 0; q < 16; q++)
#pragma unroll
    for (int e = 0; e < 4; e++)
      facc[q][e] = f * ((float)accM[q][e] + (float)accC[q][e] * (1.0f/254.0f));
  if (with_norm){
    float s2 = 0.f;
#pragma unroll
    for (int q = 0; q < 16; q++)
#pragma unroll
      for (int e = 0; e < 4; e++) s2 += facc[q][e]*facc[q][e];
#pragma unroll
    for (int o = 16; o; o >>= 1) s2 += __shfl_down_sync(0xffffffffu, s2, o);
    if ((tid & 31) == 0) red[tid >> 5] = s2;
    __syncthreads();
    if (tid == 0){
      float t = 0.f;
#pragma unroll
      for (int w = 0; w < 8; w++) t += red[w];
      g_part[blockIdx.y * 8 + blockIdx.x] = t;
    }
  }
  const int b = m0 / C_, c0 = m0 % C_;
  const size_t off = ((size_t)b*N_ + n0) * C_ + c0;
  epi_T_bf16(facc, smem, tid, 1.f, dsth + off, dstl + off, C_);
}

__global__ void k_reduce(){
  __shared__ float sh[1024];
  const int t = threadIdx.x;
  sh[t] = g_part[t] + g_part[t+1024] + g_part[t+2048];
  __syncthreads();
  for (int o = 512; o; o >>= 1){
    if (t < o) sh[t] += sh[t+o];
    __syncthreads();
  }
  if (t == 0) g_norm2 = sh[0];
}

// ===========================================================================
// kt GEMM (bf16): kt[n][m] = sum_c kT[n][c]*vT[m][c]; scaled;
// store ktT[m][n] fp32 + amax partials
// ===========================================================================
__global__ void __launch_bounds__(256,1)
k_gemm_kt(const float* __restrict__ scale){
  extern __shared__ __align__(128) char smem[];
  __shared__ float redm[8];
  const uint32_t sb = smem_u32(smem);
  const int tid = threadIdx.x;
  const int bh = blockIdx.x, b = bh >> 3, h = bh & 7;
  const size_t base = ((size_t)b*N_ + h*D_) * C_;
  float acc[16][4] = {};
  gemm_main(sb, tid, g_kTh + base, g_kTl + base, C_,
            g_vTh + base, g_vTl + base, C_, 24, acc);
  const float nrm = sqrtf(g_norm2) + EPSF;
  const float f = scale[h] / (nrm*nrm);
  float mx = 0.f;
#pragma unroll
  for (int q = 0; q < 16; q++)
#pragma unroll
    for (int e = 0; e < 4; e++){
      acc[q][e] *= f;
      mx = fmaxf(mx, fabsf(acc[q][e]));
    }
#pragma unroll
  for (int o = 16; o; o >>= 1) mx = fmaxf(mx, __shfl_down_sync(0xffffffffu, mx, o));
  const int wid = tid >> 5, lane = tid & 31;
  if (lane == 0) redm[wid] = mx;
  float* T = (float*)smem;
  const int wm = (wid >> 2) * 64, wn = (wid & 3) * 32;
  const int tr = lane >> 2, tc = (lane & 3) * 2;
#pragma unroll
  for (int mi = 0; mi < 4; mi++)
#pragma unroll
    for (int ni = 0; ni < 4; ni++){
      float* a = acc[4*mi+ni];
      const int r = wm + mi*16 + tr, c = wn + ni*8 + tc;
      T[r*TS + c]     = a[0]; T[r*TS + c + 1]     = a[1];
      T[(r+8)*TS + c] = a[2]; T[(r+8)*TS + c + 1] = a[3];
    }
  __syncthreads();
  float* dst = g_ktf + (size_t)bh*D_*D_;
#pragma unroll
  for (int it = 0; it < 4; it++){
    const int j = it*32 + (tid >> 3);
    const int mbase = (tid & 7) * 2;
#pragma unroll
    for (int p = 0; p < 8; p++){
      const int m = mbase + p*16;
      *(float2*)(dst + (size_t)j*D_ + m) = make_float2(T[m*TS + j], T[(m+1)*TS + j]);
    }
  }
  if (tid == 0){
    float t = 0.f;
#pragma unroll
    for (int w = 0; w < 8; w++) t = fmaxf(t, redm[w]);
    g_mpart[5120 + bh] = t;
  }
}

// ===========================================================================
// out GEMM (int8, KCI=64, nch=2): out1 = q @ kt -> gelu fp32 + amax partial
// ===========================================================================
__global__ void __launch_bounds__(256,1)
k_gemm_out_i8(){
  extern __shared__ __align__(128) char smem[];
  __shared__ float redm[8];
  const uint32_t sb = smem_u32(smem);
  const int tid = threadIdx.x;
  const int c0 = blockIdx.x * 128;
  const int bh = blockIdx.y, b = bh >> 3, h = bh & 7;
  const size_t Abase = ((size_t)b*C_ + c0) * N_ + (size_t)h*D_;
  int accM[16][4] = {}, accC[16][4] = {};
  gemm_main_i8<64>(sb, tid, g_xq1 + Abase, g_xq2 + Abase, N_,
                   g_ktq1 + (size_t)bh*D_*D_, g_ktq2 + (size_t)bh*D_*D_, D_, 2,
                   accM, accC);
  const float f = g_scales[0] * g_scales[5] / 16129.0f;
  const int wid = tid >> 5, lane = tid & 31;
  const int wm = (wid >> 2) * 64, wn = (wid & 3) * 32;
  const int tr = lane >> 2, tc = (lane & 3) * 2;
  float mx = 0.f;
#pragma unroll
  for (int mi = 0; mi < 4; mi++)
#pragma unroll
    for (int ni = 0; ni < 4; ni++){
      int* aM = accM[4*mi+ni];
      int* aC = accC[4*mi+ni];
      const int col = wn + ni*8 + tc;
      const size_t r0 = Abase + (size_t)(wm + mi*16 + tr) * N_ + col;
      const size_t r1 = r0 + 8*N_;
      float v0 = f*((float)aM[0] + (float)aC[0]*(1.0f/254.0f));
      float v1 = f*((float)aM[1] + (float)aC[1]*(1.0f/254.0f));
      float v2 = f*((float)aM[2] + (float)aC[2]*(1.0f/254.0f));
      float v3 = f*((float)aM[3] + (float)aC[3]*(1.0f/254.0f));
      float g0 = gelu_exact(v0), g1 = gelu_exact(v1);
      float g2 = gelu_exact(v2), g3 = gelu_exact(v3);
      *(float2*)(g_gelu + r0) = make_float2(g0, g1);
      *(float2*)(g_gelu + r1) = make_float2(g2, g3);
      mx = fmaxf(mx, fmaxf(fmaxf(fabsf(g0), fabsf(g1)), fmaxf(fabsf(g2), fabsf(g3))));
    }
#pragma unroll
  for (int o = 16; o; o >>= 1) mx = fmaxf(mx, __shfl_down_sync(0xffffffffu, mx, o));
  if (lane == 0) redm[wid] = mx;
  __syncthreads();
  if (tid == 0){
    float t = 0.f;
#pragma unroll
    for (int w = 0; w < 8; w++) t = fmaxf(t, redm[w]);
    g_mpart[2048 + blockIdx.y*6 + blockIdx.x] = t;
  }
}

// ===========================================================================
// proj GEMM (int8, KCI=128): out2 = gelu @ proj_w^T + pb; -> [B,N,C]
// ===========================================================================
__global__ void __launch_bounds__(256,1)
k_gemm_proj_i8(const int8_t* __restrict__ W1, const int8_t* __restrict__ W2,
               const float* __restrict__ pb, float* __restrict__ out){
  extern __shared__ __align__(128) char smem[];
  const uint32_t sb = smem_u32(smem);
  const int tid = threadIdx.x;
  const int n0 = blockIdx.x * 128, m0 = blockIdx.y * 128;
  int accM[16][4] = {}, accC[16][4] = {};
  gemm_main_i8<128>(sb, tid, g_xq1 + (size_t)m0*N_, g_xq2 + (size_t)m0*N_, N_,
                    W1 + (size_t)n0*N_, W2 + (size_t)n0*N_, N_, 8, accM, accC);
  const float f = g_scales[4] * g_scales[3] / 16129.0f;
  const int wid = tid >> 5, lane = tid & 31;
  const int wm = (wid >> 2) * 64, wn = (wid & 3) * 32;
  const int tr = lane >> 2, tc = (lane & 3) * 2;
  float* T = (float*)smem;
#pragma unroll
  for (int mi = 0; mi < 4; mi++)
#pragma unroll
    for (int ni = 0; ni < 4; ni++){
      int* aM = accM[4*mi+ni];
      int* aC = accC[4*mi+ni];
      const int c = wn + ni*8 + tc;
      const float2 bv = *(const float2*)(pb + n0 + c);
      const int r = wm + mi*16 + tr;
      float v0 = f*((float)aM[0] + (float)aC[0]*(1.0f/254.0f)) + bv.x;
      float v1 = f*((float)aM[1] + (float)aC[1]*(1.0f/254.0f)) + bv.y;
      float v2 = f*((float)aM[2] + (float)aC[2]*(1.0f/254.0f)) + bv.x;
      float v3 = f*((float)aM[3] + (float)aC[3]*(1.0f/254.0f)) + bv.y;
      T[r*TS + c]     = v0; T[r*TS + c + 1]     = v1;
      T[(r+8)*TS + c] = v2; T[(r+8)*TS + c + 1] = v3;
    }
  __syncthreads();
  const int b = m0 / C_, c0 = m0 % C_;
  float* dst = out + ((size_t)b*N_ + n0) * C_ + c0;
#pragma unroll
  for (int it = 0; it < 4; it++){
    const int j = it*32 + (tid >> 3);
    const int mbase = (tid & 7) * 2;
#pragma unroll
    for (int p = 0; p < 8; p++){
      const int m = mbase + p*16;
      *(float2*)(dst + (size_t)j*C_ + m) = make_float2(T[m*TS + j], T[(m+1)*TS + j]);
    }
  }
}

// ---------------------------------------------------------------------------
// Launch: graph-capturable, allocation-free, deterministic.
// ---------------------------------------------------------------------------
extern "C" void kernel_launch(void* const* d_in, const int* in_sizes, int n_in,
                              void* d_out, int out_size){
  const float* x   = (const float*)d_in[0];
  const float* qkw = (const float*)d_in[1];
  const float* vw  = (const float*)d_in[2];
  const float* pw  = (const float*)d_in[3];
  const float* pb  = (const float*)d_in[4];
  const float* sc  = (const float*)d_in[5];
  float* out = (float*)d_out;

  int8_t *p_wq1=nullptr, *p_wq2=nullptr;
  __nv_bfloat16 *p_kTh=nullptr, *p_kTl=nullptr, *p_vTh=nullptr, *p_vTl=nullptr;
  cudaGetSymbolAddress((void**)&p_wq1, g_wq1);
  cudaGetSymbolAddress((void**)&p_wq2, g_wq2);
  cudaGetSymbolAddress((void**)&p_kTh, g_kTh);
  cudaGetSymbolAddress((void**)&p_kTl, g_kTl);
  cudaGetSymbolAddress((void**)&p_vTh, g_vTh);
  cudaGetSymbolAddress((void**)&p_vTl, g_vTl);

  cudaFuncSetAttribute(k_gemm_kv_i8,  cudaFuncAttributeMaxDynamicSharedMemorySize, GSMEM_I128);
  cudaFuncSetAttribute(k_gemm_proj_i8,cudaFuncAttributeMaxDynamicSharedMemorySize, GSMEM_I128);
  cudaFuncSetAttribute(k_gemm_out_i8, cudaFuncAttributeMaxDynamicSharedMemorySize, GSMEM_I64);
  cudaFuncSetAttribute(k_gemm_kt,  cudaFuncAttributeMaxDynamicSharedMemorySize, GSMEM);

  const size_t W2 = (size_t)N_*N_;

  // amax scales (exact, deterministic) — one fused kernel
  k_amax_all<<<dim3(512,4), 256>>>((const float4*)x, (const float4*)qkw,
                                   (const float4*)vw, (const float4*)pw);
  k_amax_fin<<<1, 512>>>();

  // x -> xt int8 q1/q2; weight quantization
  k_transpose_x<<<dim3(24,32,64), dim3(32,8)>>>(x);
  k_quantW<<<1024, 256>>>(qkw, p_wq1,      p_wq2,      1, (int)(W2/4));
  k_quantW<<<1024, 256>>>(vw,  p_wq1+W2,   p_wq2+W2,   2, (int)(W2/4));
  k_quantW<<<1024, 256>>>(pw,  p_wq1+2*W2, p_wq2+2*W2, 3, (int)(W2/4));

  // k -> kT (+ norm partials), v -> vT  (int8 IMMA, KC=128)
  k_gemm_kv_i8<<<dim3(8,384), 256, GSMEM_I128>>>(p_wq1,    p_wq2,    1, p_kTh, p_kTl, 1);
  k_gemm_kv_i8<<<dim3(8,384), 256, GSMEM_I128>>>(p_wq1+W2, p_wq2+W2, 2, p_vTh, p_vTl, 0);
  k_reduce<<<1,1024>>>();

  // kt (bf16) -> ktT fp32 + amax; quantize kt; out (int8, KC=64) -> gelu + amax
  k_gemm_kt<<<512, 256, GSMEM>>>(sc);
  k_scale_kt<<<1, 512>>>();
  k_quant_kt<<<8192, 256>>>((int)(KTN_/4));
  k_gemm_out_i8<<<dim3(6,512), 256, GSMEM_I64>>>();
  k_scale_gelu<<<1, 1024>>>();
  k_quant_gelu<<<49152, 256>>>((int)(ROWS_*N_/4));

  // proj (int8 IMMA, KC=128) + bias, transposed write direct to [B,N,C]
  k_gemm_proj_i8<<<dim3(8,384), 256, GSMEM_I128>>>(p_wq1+2*W2, p_wq2+2*W2, pb, out);
}

// round 17
// speedup vs baseline: 1.8512x; 1.0468x over previous
#include <cuda_runtime.h>
#include <cuda_bf16.h>
#include <math.h>
#include <stdint.h>

// Problem constants: B=64, N=1024, C=768, heads=8, d=128
#define B_ 64
#define N_ 1024
#define C_ 768
#define H_ 8
#define D_ 128
#define EPSF 1e-8f
#define ROWS_ ((size_t)B_*C_)   // 49152
#define KTN_ ((size_t)B_*H_*D_*D_)   // 8388608

// ---------------------------------------------------------------------------
// Scratch (device globals — allocation-free rule)
// ---------------------------------------------------------------------------
__device__ int8_t g_xq1[ROWS_*N_];         // xt int8 chunk1
__device__ int8_t g_xq2[ROWS_*N_];         // xt int8 chunk2
__device__ int8_t g_wq1[3][(size_t)N_*N_];
__device__ int8_t g_wq2[3][(size_t)N_*N_];
__device__ __nv_bfloat16 g_kTh[(size_t)B_*N_*C_];  // kT [b][n][c] hi
__device__ __nv_bfloat16 g_kTl[(size_t)B_*N_*C_];
__device__ __nv_bfloat16 g_vTh[(size_t)B_*N_*C_];
__device__ __nv_bfloat16 g_vTl[(size_t)B_*N_*C_];
__device__ float  g_ktf[KTN_];             // ktT fp32 [bh][m][n]
__device__ int8_t g_ktq1[KTN_];            // ktT int8 chunk1
__device__ int8_t g_ktq2[KTN_];            // ktT int8 chunk2
__device__ float g_gelu[ROWS_*N_];         // fp32 gelu output (proj input)
__device__ float g_part[3072];
__device__ float g_norm2;
__device__ float g_mpart[6144];            // amax partials
__device__ float g_scales[8];              // 0:x 1:qkw 2:vw 3:pw 4:gelu 5:kt

// ---------------------------------------------------------------------------
// Helpers
// ---------------------------------------------------------------------------
__device__ __forceinline__ uint32_t smem_u32(const void* p){
  uint32_t a;
  asm("{ .reg .u64 t; cvta.to.shared.u64 t, %1; cvt.u32.u64 %0, t; }" : "=r"(a) : "l"(p));
  return a;
}
__device__ __forceinline__ void split2(float fx, float fy, uint32_t& hi, uint32_t& lo){
  uint32_t h;
  asm("cvt.rn.bf16x2.f32 %0, %1, %2;" : "=r"(h) : "f"(fy), "f"(fx));
  float hx = __uint_as_float(h << 16);
  float hy = __uint_as_float(h & 0xffff0000u);
  float lx = fx - hx, ly = fy - hy;
  asm("cvt.rn.bf16x2.f32 %0, %1, %2;" : "=r"(lo) : "f"(ly), "f"(lx));
  hi = h;
}
__device__ __forceinline__ float gelu_exact(float x){
  return 0.5f * x * (1.0f + erff(x * 0.7071067811865475f));
}
// int8 2-chunk quantization: x ~= (S/127)*(q1 + q2/254)
__device__ __forceinline__ void quant2(float v, float qs, int8_t& q1, int8_t& q2){
  float q = v * qs;
  float a1 = rintf(q);
  q1 = (int8_t)(int)a1;
  q2 = (int8_t)(int)rintf((q - a1) * 254.0f);
}

#define CP_ASYNC16(s, g) \
  asm volatile("cp.async.cg.shared.global [%0], [%1], 16;" :: "r"(s), "l"(g) : "memory")
#define CP_COMMIT() asm volatile("cp.async.commit_group;" ::: "memory")
#define CP_WAIT1()  asm volatile("cp.async.wait_group 1;" ::: "memory")
#define CP_WAIT0()  asm volatile("cp.async.wait_group 0;" ::: "memory")

__device__ __forceinline__ void ldmx4(uint32_t* r, uint32_t addr){
  asm volatile("ldmatrix.sync.aligned.m8n8.x4.shared.b16 {%0,%1,%2,%3}, [%4];"
    : "=r"(r[0]), "=r"(r[1]), "=r"(r[2]), "=r"(r[3]) : "r"(addr));
}
__device__ __forceinline__ void mma16816(float* c, const uint32_t* a, const uint32_t* b){
  asm volatile("mma.sync.aligned.m16n8k16.row.col.f32.bf16.bf16.f32 "
    "{%0,%1,%2,%3},{%4,%5,%6,%7},{%8,%9},{%0,%1,%2,%3};"
    : "+f"(c[0]), "+f"(c[1]), "+f"(c[2]), "+f"(c[3])
    : "r"(a[0]), "r"(a[1]), "r"(a[2]), "r"(a[3]), "r"(b[0]), "r"(b[1]));
}
__device__ __forceinline__ void imma16832(int* c, const uint32_t* a, const uint32_t* b){
  asm volatile("mma.sync.aligned.m16n8k32.row.col.s32.s8.s8.s32 "
    "{%0,%1,%2,%3},{%4,%5,%6,%7},{%8,%9},{%0,%1,%2,%3};"
    : "+r"(c[0]), "+r"(c[1]), "+r"(c[2]), "+r"(c[3])
    : "r"(a[0]), "r"(a[1]), "r"(a[2]), "r"(a[3]), "r"(b[0]), "r"(b[1]));
}

// ===========================================================================
// Fused amax over x + 3 weights (float4 streaming; exact max, deterministic)
// ===========================================================================
__global__ void k_amax_all(const float4* __restrict__ x4,
                           const float4* __restrict__ w1,
                           const float4* __restrict__ w2,
                           const float4* __restrict__ w3){
  __shared__ float sm[256];
  const int y = blockIdx.y;
  const float4* src; int n4;
  if      (y == 0){ src = x4; n4 = (int)(ROWS_*N_/4); }
  else if (y == 1){ src = w1; n4 = (int)((size_t)N_*N_/4); }
  else if (y == 2){ src = w2; n4 = (int)((size_t)N_*N_/4); }
  else            { src = w3; n4 = (int)((size_t)N_*N_/4); }
  float m = 0.f;
  for (int i = blockIdx.x*256 + threadIdx.x; i < n4; i += 512*256){
    float4 v = src[i];
    m = fmaxf(m, fmaxf(fmaxf(fabsf(v.x), fabsf(v.y)), fmaxf(fabsf(v.z), fabsf(v.w))));
  }
  sm[threadIdx.x] = m;
  __syncthreads();
  for (int o = 128; o; o >>= 1){
    if (threadIdx.x < o) sm[threadIdx.x] = fmaxf(sm[threadIdx.x], sm[threadIdx.x+o]);
    __syncthreads();
  }
  if (threadIdx.x == 0) g_mpart[y*512 + blockIdx.x] = sm[0];
}
__global__ void k_amax_fin(){
  __shared__ float sm[512];
  const int t = threadIdx.x;
#pragma unroll
  for (int r = 0; r < 4; r++){
    sm[t] = g_mpart[r*512 + t];
    __syncthreads();
    for (int o = 256; o; o >>= 1){
      if (t < o) sm[t] = fmaxf(sm[t], sm[t+o]);
      __syncthreads();
    }
    if (t == 0) g_scales[r] = sm[0];
    __syncthreads();
  }
}
__global__ void k_scale_gelu(){
  __shared__ float sm[1024];
  const int t = threadIdx.x;
  float m = 0.f;
  for (int i = t; i < 3072; i += 1024) m = fmaxf(m, g_mpart[2048+i]);
  sm[t] = m;
  __syncthreads();
  for (int o = 512; o; o >>= 1){
    if (t < o) sm[t] = fmaxf(sm[t], sm[t+o]);
    __syncthreads();
  }
  if (t == 0) g_scales[4] = sm[0];
}
__global__ void k_scale_kt(){
  __shared__ float sm[512];
  const int t = threadIdx.x;
  sm[t] = g_mpart[5120 + t];
  __syncthreads();
  for (int o = 256; o; o >>= 1){
    if (t < o) sm[t] = fmaxf(sm[t], sm[t+o]);
    __syncthreads();
  }
  if (t == 0) g_scales[5] = sm[0];
}

// ===========================================================================
// Quantization kernels
// ===========================================================================
__global__ void k_quantW(const float* __restrict__ in, int8_t* __restrict__ q1,
                         int8_t* __restrict__ q2, int sidx, int n4){
  int i = blockIdx.x * blockDim.x + threadIdx.x;
  if (i >= n4) return;
  const float qs = 127.0f / g_scales[sidx];
  float4 v = ((const float4*)in)[i];
  int8_t a1,a2,b1,b2,c1,c2,d1,d2;
  quant2(v.x, qs, a1, a2); quant2(v.y, qs, b1, b2);
  quant2(v.z, qs, c1, c2); quant2(v.w, qs, d1, d2);
  ((uchar4*)q1)[i] = make_uchar4((uint8_t)a1,(uint8_t)b1,(uint8_t)c1,(uint8_t)d1);
  ((uchar4*)q2)[i] = make_uchar4((uint8_t)a2,(uint8_t)b2,(uint8_t)c2,(uint8_t)d2);
}
__global__ void k_quant_gelu(int n4){
  int i = blockIdx.x * blockDim.x + threadIdx.x;
  if (i >= n4) return;
  const float qs = 127.0f / g_scales[4];
  float4 v = ((const float4*)g_gelu)[i];
  int8_t a1,a2,b1,b2,c1,c2,d1,d2;
  quant2(v.x, qs, a1, a2); quant2(v.y, qs, b1, b2);
  quant2(v.z, qs, c1, c2); quant2(v.w, qs, d1, d2);
  ((uchar4*)g_xq1)[i] = make_uchar4((uint8_t)a1,(uint8_t)b1,(uint8_t)c1,(uint8_t)d1);
  ((uchar4*)g_xq2)[i] = make_uchar4((uint8_t)a2,(uint8_t)b2,(uint8_t)c2,(uint8_t)d2);
}
__global__ void k_quant_kt(int n4){
  int i = blockIdx.x * blockDim.x + threadIdx.x;
  if (i >= n4) return;
  const float qs = 127.0f / g_scales[5];
  float4 v = ((const float4*)g_ktf)[i];
  int8_t a1,a2,b1,b2,c1,c2,d1,d2;
  quant2(v.x, qs, a1, a2); quant2(v.y, qs, b1, b2);
  quant2(v.z, qs, c1, c2); quant2(v.w, qs, d1, d2);
  ((uchar4*)g_ktq1)[i] = make_uchar4((uint8_t)a1,(uint8_t)b1,(uint8_t)c1,(uint8_t)d1);
  ((uchar4*)g_ktq2)[i] = make_uchar4((uint8_t)a2,(uint8_t)b2,(uint8_t)c2,(uint8_t)d2);
}

// ===========================================================================
// x transpose: fp32 [B,N,C] -> int8 q1/q2 planes [b*C+c][n]
// Tile 128(n) x 32(c); coalesced 128B row loads, uint4 (16x int8) stores.
// grid (8, 24, 64), block 256
// ===========================================================================
__global__ void k_transpose_x(const float* __restrict__ in){
  __shared__ float t[128][33];
  const int b  = blockIdx.z;
  const int n0 = blockIdx.x * 128, c0 = blockIdx.y * 32;
  const float qs = 127.0f / g_scales[0];
  const int tid = threadIdx.x;
  const int w = tid >> 5, l = tid & 31;
  const float* ip = in + (size_t)b * N_ * C_;
#pragma unroll
  for (int r = 0; r < 16; r++){
    const int nr = w * 16 + r;
    t[nr][l] = ip[(size_t)(n0 + nr) * C_ + c0 + l];
  }
  __syncthreads();
  const int cl = tid >> 3;            // 0..31
  const int ns = (tid & 7) * 16;      // 0..112
  uint8_t q1b[16], q2b[16];
#pragma unroll
  for (int j = 0; j < 16; j++){
    int8_t q1, q2;
    quant2(t[ns + j][cl], qs, q1, q2);
    q1b[j] = (uint8_t)q1;
    q2b[j] = (uint8_t)q2;
  }
  const size_t o = ((size_t)b * C_ + c0 + cl) * N_ + n0 + ns;
  *(uint4*)(g_xq1 + o) = *(const uint4*)q1b;
  *(uint4*)(g_xq2 + o) = *(const uint4*)q2b;
}

// ===========================================================================
// int8 IMMA mainloop, templated on K-chunk KCI.
// 3-stage pipeline, sync every chunk (each barrier publishes cp.async fills).
// Row stride KCI+16 bytes keeps 8-row ldmatrix groups conflict-free.
// accM += a1*b1 ; accC += a1*b2 + a2*b1
// ===========================================================================
template<int KCI>
__device__ __forceinline__ void gemm_main_i8(
    uint32_t sb, int tid,
    const int8_t* __restrict__ A1, const int8_t* __restrict__ A2, int lda,
    const int8_t* __restrict__ B1, const int8_t* __restrict__ B2, int ldb,
    int nch, int (*accM)[4], int (*accC)[4]){
  constexpr int RSBI = KCI + 16;
  constexpr int TILE = 128 * RSBI;
  constexpr int STAGE = 4 * TILE;
  constexpr int SPR = KCI / 16;
  const int t64  = tid & 63;
  const int tile = tid >> 6;                 // 0:A1 1:A2 2:B1 3:B2
  const int8_t* gsrc; int ld;
  if      (tile == 0){ gsrc = A1; ld = lda; }
  else if (tile == 1){ gsrc = A2; ld = lda; }
  else if (tile == 2){ gsrc = B1; ld = ldb; }
  else               { gsrc = B2; ld = ldb; }

  auto issue = [&](int ch, int stage){
    const int k0 = ch * KCI;
    const uint32_t sbase = sb + stage * STAGE + tile * TILE;
#pragma unroll
    for (int j = 0; j < 2*SPR; j++){
      const int seg = t64 + 64 * j;
      const int row = seg / SPR, s = seg % SPR;
      CP_ASYNC16(sbase + row * RSBI + s * 16,
                 (const char*)(gsrc + (size_t)row * ld + k0) + s * 16);
    }
    CP_COMMIT();
  };

  issue(0, 0);
  issue(1, 1);

  const int wid = tid >> 5, lane = tid & 31;
  const int wm = (wid >> 2) * 64, wn = (wid & 3) * 32;
  const int a_row = lane & 15, a_kb = (lane >> 4) * 16;
  const int b_row = (lane & 7) + ((lane >> 4) * 8);
  const int b_kb  = ((lane >> 3) & 1) * 16;

  for (int ch = 0; ch < nch; ch++){
    CP_WAIT1();
    __syncthreads();
    if (ch + 2 < nch) issue(ch + 2, (ch + 2) % 3);
    else CP_COMMIT();

    const uint32_t st = sb + (ch % 3) * STAGE;
    const uint32_t a1T = st,           a2T = st + TILE;
    const uint32_t b1T = st + 2*TILE,  b2T = st + 3*TILE;

#pragma unroll
    for (int kk = 0; kk < KCI/32; kk++){
      const int kb = kk * 32;
      uint32_t a1[4][4], a2[4][4], b1[4][2], b2[4][2];
#pragma unroll
      for (int mi = 0; mi < 4; mi++){
        const uint32_t ro = (uint32_t)(wm + mi*16 + a_row) * RSBI + kb + a_kb;
        ldmx4(a1[mi], a1T + ro);
        ldmx4(a2[mi], a2T + ro);
      }
#pragma unroll
      for (int nh = 0; nh < 2; nh++){
        const uint32_t ro = (uint32_t)(wn + nh*16 + b_row) * RSBI + kb + b_kb;
        uint32_t r[4];
        ldmx4(r, b1T + ro);
        b1[nh*2+0][0]=r[0]; b1[nh*2+0][1]=r[1]; b1[nh*2+1][0]=r[2]; b1[nh*2+1][1]=r[3];
        ldmx4(r, b2T + ro);
        b2[nh*2+0][0]=r[0]; b2[nh*2+0][1]=r[1]; b2[nh*2+1][0]=r[2]; b2[nh*2+1][1]=r[3];
      }
#pragma unroll
      for (int mi = 0; mi < 4; mi++)
#pragma unroll
        for (int ni = 0; ni < 4; ni++){
          imma16832(accM[4*mi+ni], a1[mi], b1[ni]);
          imma16832(accC[4*mi+ni], a1[mi], b2[ni]);
          imma16832(accC[4*mi+ni], a2[mi], b1[ni]);
        }
    }
  }
  CP_WAIT0();
  __syncthreads();
}

#define GSMEM_I128 (3*4*128*(128+16))   // 221184 B (KCI=128)
#define GSMEM_I64  (3*4*128*(64+16))    // 122880 B (KCI=64)

// ===========================================================================
// bf16 HMMA mainloop (kt GEMM), templated on K-chunk KCB (bf16 elements).
// Row stride 2*KCB+16 bytes. 3-stage, sync every chunk (proven protocol).
// ===========================================================================
template<int KCB>
__device__ __forceinline__ void gemm_main(
    uint32_t sb, int tid,
    const __nv_bfloat16* __restrict__ Ah, const __nv_bfloat16* __restrict__ Al, int lda,
    const __nv_bfloat16* __restrict__ Bh, const __nv_bfloat16* __restrict__ Bl, int ldb,
    int nch, float (*acc)[4]){
  constexpr int RSB = 2*KCB + 16;
  constexpr int TILE = 128 * RSB;
  constexpr int STAGE = 4 * TILE;
  constexpr int SPR = 2*KCB / 16;
  const int t64  = tid & 63;
  const int tile = tid >> 6;
  const __nv_bfloat16* gsrc; int ld;
  if      (tile == 0){ gsrc = Ah; ld = lda; }
  else if (tile == 1){ gsrc = Al; ld = lda; }
  else if (tile == 2){ gsrc = Bh; ld = ldb; }
  else               { gsrc = Bl; ld = ldb; }

  auto issue = [&](int ch, int stage){
    const int k0 = ch * KCB;
    const uint32_t sbase = sb + stage * STAGE + tile * TILE;
#pragma unroll
    for (int j = 0; j < 2*SPR; j++){
      const int seg = t64 + 64 * j;
      const int row = seg / SPR, s = seg % SPR;
      CP_ASYNC16(sbase + row * RSB + s * 16,
                 (const char*)(gsrc + (size_t)row * ld + k0) + s * 16);
    }
    CP_COMMIT();
  };

  issue(0, 0);
  issue(1, 1);

  const int wid = tid >> 5, lane = tid & 31;
  const int wm = (wid >> 2) * 64, wn = (wid & 3) * 32;
  const int a_row = lane % 16, a_k8 = (lane >> 4) * 8;
  const int b_row = (lane & 7) + ((lane >> 4) * 8);
  const int b_k8  = ((lane >> 3) & 1) * 8;

  for (int ch = 0; ch < nch; ch++){
    CP_WAIT1();
    __syncthreads();
    if (ch + 2 < nch) issue(ch + 2, (ch + 2) % 3);
    else CP_COMMIT();

    const uint32_t st = sb + (ch % 3) * STAGE;
    const uint32_t aH = st,           aL = st + TILE;
    const uint32_t bH = st + 2*TILE,  bL = st + 3*TILE;

#pragma unroll
    for (int kk = 0; kk < KCB/16; kk++){
      uint32_t ah[4][4], al[4][4], bh[4][2], bl[4][2];
      const int kc = kk * 32 + a_k8 * 2;
#pragma unroll
      for (int mi = 0; mi < 4; mi++){
        const uint32_t ro = (uint32_t)(wm + mi*16 + a_row) * RSB + kc;
        ldmx4(ah[mi], aH + ro);
        ldmx4(al[mi], aL + ro);
      }
#pragma unroll
      for (int nh = 0; nh < 2; nh++){
        const uint32_t ro = (uint32_t)(wn + nh*16 + b_row) * RSB + kk*32 + b_k8*2;
        uint32_t r[4];
        ldmx4(r, bH + ro);
        bh[nh*2+0][0]=r[0]; bh[nh*2+0][1]=r[1]; bh[nh*2+1][0]=r[2]; bh[nh*2+1][1]=r[3];
        ldmx4(r, bL + ro);
        bl[nh*2+0][0]=r[0]; bl[nh*2+0][1]=r[1]; bl[nh*2+1][0]=r[2]; bl[nh*2+1][1]=r[3];
      }
#pragma unroll
      for (int mi = 0; mi < 4; mi++)
#pragma unroll
        for (int ni = 0; ni < 4; ni++){
          mma16816(acc[4*mi+ni], ah[mi], bh[ni]);
          mma16816(acc[4*mi+ni], ah[mi], bl[ni]);
          mma16816(acc[4*mi+ni], al[mi], bh[ni]);
        }
    }
  }
  CP_WAIT0();
  __syncthreads();
}

#define GSMEM_B64 (3*4*128*(2*64+16))   // 221184 B (KCB=64)

// Transposed bf16 hi/lo epilogue via fp32 smem bounce.
#define TS 130
__device__ __forceinline__ void epi_T_bf16(
    float (*acc)[4], char* smem, int tid, float f,
    __nv_bfloat16* dsth, __nv_bfloat16* dstl, int ldd){
  float* T = (float*)smem;
  const int wid = tid >> 5, lane = tid & 31;
  const int wm = (wid >> 2) * 64, wn = (wid & 3) * 32;
  const int tr = lane >> 2, tc = (lane & 3) * 2;
#pragma unroll
  for (int mi = 0; mi < 4; mi++)
#pragma unroll
    for (int ni = 0; ni < 4; ni++){
      float* a = acc[4*mi+ni];
      const int r = wm + mi*16 + tr, c = wn + ni*8 + tc;
      T[r*TS + c]     = a[0]*f; T[r*TS + c + 1]     = a[1]*f;
      T[(r+8)*TS + c] = a[2]*f; T[(r+8)*TS + c + 1] = a[3]*f;
    }
  __syncthreads();
#pragma unroll
  for (int it = 0; it < 4; it++){
    const int j = it*32 + (tid >> 3);
    const int mbase = (tid & 7) * 2;
#pragma unroll
    for (int p = 0; p < 8; p++){
      const int m = mbase + p*16;
      float f0 = T[m*TS + j], f1 = T[(m+1)*TS + j];
      uint32_t h, l; split2(f0, f1, h, l);
      *(uint32_t*)(dsth + (size_t)j*ldd + m) = h;
      *(uint32_t*)(dstl + (size_t)j*ldd + m) = l;
    }
  }
  __syncthreads();
}

// ===========================================================================
// kv GEMM (int8, KCI=128): C = xt @ W^T -> transposed bf16 hi/lo (+ norm)
// ===========================================================================
__global__ void __launch_bounds__(256,1)
k_gemm_kv_i8(const int8_t* __restrict__ W1, const int8_t* __restrict__ W2,
             int wsidx,
             __nv_bfloat16* __restrict__ dsth, __nv_bfloat16* __restrict__ dstl,
             int with_norm){
  extern __shared__ __align__(128) char smem[];
  __shared__ float red[8];
  const uint32_t sb = smem_u32(smem);
  const int tid = threadIdx.x;
  const int n0 = blockIdx.x * 128, m0 = blockIdx.y * 128;
  int accM[16][4] = {}, accC[16][4] = {};
  gemm_main_i8<128>(sb, tid, g_xq1 + (size_t)m0*N_, g_xq2 + (size_t)m0*N_, N_,
                    W1 + (size_t)n0*N_, W2 + (size_t)n0*N_, N_, 8, accM, accC);
  const float f = g_scales[0] * g_scales[wsidx] / 16129.0f;
  float facc[16][4];
#pragma unroll
  for (int q = 0; q < 16; q++)
#pragma unroll
    for (int e = 0; e < 4; e++)
      facc[q][e] = f * ((float)accM[q][e] + (float)accC[q][e] * (1.0f/254.0f));
  if (with_norm){
    float s2 = 0.f;
#pragma unroll
    for (int q = 0; q < 16; q++)
#pragma unroll
      for (int e = 0; e < 4; e++) s2 += facc[q][e]*facc[q][e];
#pragma unroll
    for (int o = 16; o; o >>= 1) s2 += __shfl_down_sync(0xffffffffu, s2, o);
    if ((tid & 31) == 0) red[tid >> 5] = s2;
    __syncthreads();
    if (tid == 0){
      float t = 0.f;
#pragma unroll
      for (int w = 0; w < 8; w++) t += red[w];
      g_part[blockIdx.y * 8 + blockIdx.x] = t;
    }
  }
  const int b = m0 / C_, c0 = m0 % C_;
  const size_t off = ((size_t)b*N_ + n0) * C_ + c0;
  epi_T_bf16(facc, smem, tid, 1.f, dsth + off, dstl + off, C_);
}

__global__ void k_reduce(){
  __shared__ float sh[1024];
  const int t = threadIdx.x;
  sh[t] = g_part[t] + g_part[t+1024] + g_part[t+2048];
  __syncthreads();
  for (int o = 512; o; o >>= 1){
    if (t < o) sh[t] += sh[t+o];
    __syncthreads();
  }
  if (t == 0) g_norm2 = sh[0];
}

// ===========================================================================
// kt GEMM (bf16, KCB=64): kt[n][m] = sum_c kT[n][c]*vT[m][c]; scaled;
// store ktT[m][n] fp32 + amax partials
// ===========================================================================
__global__ void __launch_bounds__(256,1)
k_gemm_kt(const float* __restrict__ scale){
  extern __shared__ __align__(128) char smem[];
  __shared__ float redm[8];
  const uint32_t sb = smem_u32(smem);
  const int tid = threadIdx.x;
  const int bh = blockIdx.x, b = bh >> 3, h = bh & 7;
  const size_t base = ((size_t)b*N_ + h*D_) * C_;
  float acc[16][4] = {};
  gemm_main<64>(sb, tid, g_kTh + base, g_kTl + base, C_,
                g_vTh + base, g_vTl + base, C_, 12, acc);
  const float nrm = sqrtf(g_norm2) + EPSF;
  const float f = scale[h] / (nrm*nrm);
  float mx = 0.f;
#pragma unroll
  for (int q = 0; q < 16; q++)
#pragma unroll
    for (int e = 0; e < 4; e++){
      acc[q][e] *= f;
      mx = fmaxf(mx, fabsf(acc[q][e]));
    }
#pragma unroll
  for (int o = 16; o; o >>= 1) mx = fmaxf(mx, __shfl_down_sync(0xffffffffu, mx, o));
  const int wid = tid >> 5, lane = tid & 31;
  if (lane == 0) redm[wid] = mx;
  float* T = (float*)smem;
  const int wm = (wid >> 2) * 64, wn = (wid & 3) * 32;
  const int tr = lane >> 2, tc = (lane & 3) * 2;
#pragma unroll
  for (int mi = 0; mi < 4; mi++)
#pragma unroll
    for (int ni = 0; ni < 4; ni++){
      float* a = acc[4*mi+ni];
      const int r = wm + mi*16 + tr, c = wn + ni*8 + tc;
      T[r*TS + c]     = a[0]; T[r*TS + c + 1]     = a[1];
      T[(r+8)*TS + c] = a[2]; T[(r+8)*TS + c + 1] = a[3];
    }
  __syncthreads();
  float* dst = g_ktf + (size_t)bh*D_*D_;
#pragma unroll
  for (int it = 0; it < 4; it++){
    const int j = it*32 + (tid >> 3);
    const int mbase = (tid & 7) * 2;
#pragma unroll
    for (int p = 0; p < 8; p++){
      const int m = mbase + p*16;
      *(float2*)(dst + (size_t)j*D_ + m) = make_float2(T[m*TS + j], T[(m+1)*TS + j]);
    }
  }
  if (tid == 0){
    float t = 0.f;
#pragma unroll
    for (int w = 0; w < 8; w++) t = fmaxf(t, redm[w]);
    g_mpart[5120 + bh] = t;
  }
}

// ===========================================================================
// out GEMM (int8, KCI=64, nch=2): out1 = q @ kt -> gelu fp32 + amax partial
// ===========================================================================
__global__ void __launch_bounds__(256,1)
k_gemm_out_i8(){
  extern __shared__ __align__(128) char smem[];
  __shared__ float redm[8];
  const uint32_t sb = smem_u32(smem);
  const int tid = threadIdx.x;
  const int c0 = blockIdx.x * 128;
  const int bh = blockIdx.y, b = bh >> 3, h = bh & 7;
  const size_t Abase = ((size_t)b*C_ + c0) * N_ + (size_t)h*D_;
  int accM[16][4] = {}, accC[16][4] = {};
  gemm_main_i8<64>(sb, tid, g_xq1 + Abase, g_xq2 + Abase, N_,
                   g_ktq1 + (size_t)bh*D_*D_, g_ktq2 + (size_t)bh*D_*D_, D_, 2,
                   accM, accC);
  const float f = g_scales[0] * g_scales[5] / 16129.0f;
  const int wid = tid >> 5, lane = tid & 31;
  const int wm = (wid >> 2) * 64, wn = (wid & 3) * 32;
  const int tr = lane >> 2, tc = (lane & 3) * 2;
  float mx = 0.f;
#pragma unroll
  for (int mi = 0; mi < 4; mi++)
#pragma unroll
    for (int ni = 0; ni < 4; ni++){
      int* aM = accM[4*mi+ni];
      int* aC = accC[4*mi+ni];
      const int col = wn + ni*8 + tc;
      const size_t r0 = Abase + (size_t)(wm + mi*16 + tr) * N_ + col;
      const size_t r1 = r0 + 8*N_;
      float v0 = f*((float)aM[0] + (float)aC[0]*(1.0f/254.0f));
      float v1 = f*((float)aM[1] + (float)aC[1]*(1.0f/254.0f));
      float v2 = f*((float)aM[2] + (float)aC[2]*(1.0f/254.0f));
      float v3 = f*((float)aM[3] + (float)aC[3]*(1.0f/254.0f));
      float g0 = gelu_exact(v0), g1 = gelu_exact(v1);
      float g2 = gelu_exact(v2), g3 = gelu_exact(v3);
      *(float2*)(g_gelu + r0) = make_float2(g0, g1);
      *(float2*)(g_gelu + r1) = make_float2(g2, g3);
      mx = fmaxf(mx, fmaxf(fmaxf(fabsf(g0), fabsf(g1)), fmaxf(fabsf(g2), fabsf(g3))));
    }
#pragma unroll
  for (int o = 16; o; o >>= 1) mx = fmaxf(mx, __shfl_down_sync(0xffffffffu, mx, o));
  if (lane == 0) redm[wid] = mx;
  __syncthreads();
  if (tid == 0){
    float t = 0.f;
#pragma unroll
    for (int w = 0; w < 8; w++) t = fmaxf(t, redm[w]);
    g_mpart[2048 + blockIdx.y*6 + blockIdx.x] = t;
  }
}

// ===========================================================================
// proj GEMM (int8, KCI=128): out2 = gelu @ proj_w^T + pb; -> [B,N,C]
// ===========================================================================
__global__ void __launch_bounds__(256,1)
k_gemm_proj_i8(const int8_t* __restrict__ W1, const int8_t* __restrict__ W2,
               const float* __restrict__ pb, float* __restrict__ out){
  extern __shared__ __align__(128) char smem[];
  const uint32_t sb = smem_u32(smem);
  const int tid = threadIdx.x;
  const int n0 = blockIdx.x * 128, m0 = blockIdx.y * 128;
  int accM[16][4] = {}, accC[16][4] = {};
  gemm_main_i8<128>(sb, tid, g_xq1 + (size_t)m0*N_, g_xq2 + (size_t)m0*N_, N_,
                    W1 + (size_t)n0*N_, W2 + (size_t)n0*N_, N_, 8, accM, accC);
  const float f = g_scales[4] * g_scales[3] / 16129.0f;
  const int wid = tid >> 5, lane = tid & 31;
  const int wm = (wid >> 2) * 64, wn = (wid & 3) * 32;
  const int tr = lane >> 2, tc = (lane & 3) * 2;
  float* T = (float*)smem;
#pragma unroll
  for (int mi = 0; mi < 4; mi++)
#pragma unroll
    for (int ni = 0; ni < 4; ni++){
      int* aM = accM[4*mi+ni];
      int* aC = accC[4*mi+ni];
      const int c = wn + ni*8 + tc;
      const float2 bv = *(const float2*)(pb + n0 + c);
      const int r = wm + mi*16 + tr;
      float v0 = f*((float)aM[0] + (float)aC[0]*(1.0f/254.0f)) + bv.x;
      float v1 = f*((float)aM[1] + (float)aC[1]*(1.0f/254.0f)) + bv.y;
      float v2 = f*((float)aM[2] + (float)aC[2]*(1.0f/254.0f)) + bv.x;
      float v3 = f*((float)aM[3] + (float)aC[3]*(1.0f/254.0f)) + bv.y;
      T[r*TS + c]     = v0; T[r*TS + c + 1]     = v1;
      T[(r+8)*TS + c] = v2; T[(r+8)*TS + c + 1] = v3;
    }
  __syncthreads();
  const int b = m0 / C_, c0 = m0 % C_;
  float* dst = out + ((size_t)b*N_ + n0) * C_ + c0;
#pragma unroll
  for (int it = 0; it < 4; it++){
    const int j = it*32 + (tid >> 3);
    const int mbase = (tid & 7) * 2;
#pragma unroll
    for (int p = 0; p < 8; p++){
      const int m = mbase + p*16;
      *(float2*)(dst + (size_t)j*C_ + m) = make_float2(T[m*TS + j], T[(m+1)*TS + j]);
    }
  }
}

// ---------------------------------------------------------------------------
// Launch: graph-capturable, allocation-free, deterministic.
// ---------------------------------------------------------------------------
extern "C" void kernel_launch(void* const* d_in, const int* in_sizes, int n_in,
                              void* d_out, int out_size){
  const float* x   = (const float*)d_in[0];
  const float* qkw = (const float*)d_in[1];
  const float* vw  = (const float*)d_in[2];
  const float* pw  = (const float*)d_in[3];
  const float* pb  = (const float*)d_in[4];
  const float* sc  = (const float*)d_in[5];
  float* out = (float*)d_out;

  int8_t *p_wq1=nullptr, *p_wq2=nullptr;
  __nv_bfloat16 *p_kTh=nullptr, *p_kTl=nullptr, *p_vTh=nullptr, *p_vTl=nullptr;
  cudaGetSymbolAddress((void**)&p_wq1, g_wq1);
  cudaGetSymbolAddress((void**)&p_wq2, g_wq2);
  cudaGetSymbolAddress((void**)&p_kTh, g_kTh);
  cudaGetSymbolAddress((void**)&p_kTl, g_kTl);
  cudaGetSymbolAddress((void**)&p_vTh, g_vTh);
  cudaGetSymbolAddress((void**)&p_vTl, g_vTl);

  cudaFuncSetAttribute(k_gemm_kv_i8,  cudaFuncAttributeMaxDynamicSharedMemorySize, GSMEM_I128);
  cudaFuncSetAttribute(k_gemm_proj_i8,cudaFuncAttributeMaxDynamicSharedMemorySize, GSMEM_I128);
  cudaFuncSetAttribute(k_gemm_out_i8, cudaFuncAttributeMaxDynamicSharedMemorySize, GSMEM_I64);
  cudaFuncSetAttribute(k_gemm_kt,  cudaFuncAttributeMaxDynamicSharedMemorySize, GSMEM_B64);

  const size_t W2 = (size_t)N_*N_;

  // amax scales (exact, deterministic) — one fused kernel
  k_amax_all<<<dim3(512,4), 256>>>((const float4*)x, (const float4*)qkw,
                                   (const float4*)vw, (const float4*)pw);
  k_amax_fin<<<1, 512>>>();

  // x -> xt int8 q1/q2 (coalesced uint4 stores); weight quantization
  k_transpose_x<<<dim3(8,24,64), 256>>>(x);
  k_quantW<<<1024, 256>>>(qkw, p_wq1,      p_wq2,      1, (int)(W2/4));
  k_quantW<<<1024, 256>>>(vw,  p_wq1+W2,   p_wq2+W2,   2, (int)(W2/4));
  k_quantW<<<1024, 256>>>(pw,  p_wq1+2*W2, p_wq2+2*W2, 3, (int)(W2/4));

  // k -> kT (+ norm partials), v -> vT  (int8 IMMA, KC=128)
  k_gemm_kv_i8<<<dim3(8,384), 256, GSMEM_I128>>>(p_wq1,    p_wq2,    1, p_kTh, p_kTl, 1);
  k_gemm_kv_i8<<<dim3(8,384), 256, GSMEM_I128>>>(p_wq1+W2, p_wq2+W2, 2, p_vTh, p_vTl, 0);
  k_reduce<<<1,1024>>>();

  // kt (bf16, KC=64) -> ktT fp32 + amax; quantize kt; out (int8) -> gelu + amax
  k_gemm_kt<<<512, 256, GSMEM_B64>>>(sc);
  k_scale_kt<<<1, 512>>>();
  k_quant_kt<<<8192, 256>>>((int)(KTN_/4));
  k_gemm_out_i8<<<dim3(6,512), 256, GSMEM_I64>>>();
  k_scale_gelu<<<1, 1024>>>();
  k_quant_gelu<<<49152, 256>>>((int)(ROWS_*N_/4));

  // proj (int8 IMMA, KC=128) + bias, transposed write direct to [B,N,C]
  k_gemm_proj_i8<<<dim3(8,384), 256, GSMEM_I128>>>(p_wq1+2*W2, p_wq2+2*W2, pb, out);
}